// round 1
// baseline (speedup 1.0000x reference)
#include <cuda_runtime.h>
#include <cuda_bf16.h>
#include <math.h>

#define NN 50000
#define EE 800000
#define FIN 256
#define HID 256
#define OUTD 64
#define HEADS 8
#define HP 32

// ---------------- scratch (device globals: allowed, allocation-free) -------
struct GS {
    float h0[NN * 256];
    float h1[NN * 256];
    float skb[NN * 256];
    float agg0[NN * 256];
    float agg1[NN * 256];
    float first[NN * 256];
    float h2[NN * 64];
    float fw[NN * 64];
    float as0[NN * 8], ad0[NN * 8], as1[NN * 8], ad1[NN * 8];
    float as2[NN], ad2[NN];
    float Wcat[256 * 768];
    float Wcat2[256 * 128];
    int deg0[NN], deg1[NN];
    int off0[NN + 1], off1[NN + 1];
    int cur0[NN], cur1[NN];
    int csr0[EE], csr1[EE];
};
__device__ GS gs;

// ---------------- helpers --------------------------------------------------
__device__ __forceinline__ float wredsum(float v) {
#pragma unroll
    for (int o = 16; o; o >>= 1) v += __shfl_xor_sync(0xffffffffu, v, o);
    return v;
}
__device__ __forceinline__ float wredmax(float v) {
#pragma unroll
    for (int o = 16; o; o >>= 1) v = fmaxf(v, __shfl_xor_sync(0xffffffffu, v, o));
    return v;
}
__device__ __forceinline__ float lrelu(float x) { return fmaxf(x, 0.2f * x); }

// ---------------- CSR build ------------------------------------------------
__global__ void zero_int(int* p, int n) {
    int i = blockIdx.x * blockDim.x + threadIdx.x;
    if (i < n) p[i] = 0;
}

__global__ void hist_kernel(const int* __restrict__ dst, int* __restrict__ deg) {
    int i = blockIdx.x * blockDim.x + threadIdx.x;
    if (i < EE) atomicAdd(&deg[dst[i]], 1);
}

__global__ void scan_kernel(const int* __restrict__ deg, int* __restrict__ off) {
    __shared__ int sh[1024];
    const int n = NN;
    int t = threadIdx.x;
    int chunk = (n + 1023) >> 10;
    int s = t * chunk;
    int e = min(s + chunk, n);
    int sum = 0;
    for (int i = s; i < e; i++) sum += deg[i];
    sh[t] = sum;
    __syncthreads();
#pragma unroll
    for (int o = 1; o < 1024; o <<= 1) {
        int val = (t >= o) ? sh[t - o] : 0;
        __syncthreads();
        sh[t] += val;
        __syncthreads();
    }
    int run = sh[t] - sum;  // exclusive prefix
    for (int i = s; i < e; i++) { off[i] = run; run += deg[i]; }
    if (t == 1023) off[n] = sh[1023];
}

__global__ void copy_int(const int* __restrict__ src, int* __restrict__ dst, int n) {
    int i = blockIdx.x * blockDim.x + threadIdx.x;
    if (i < n) dst[i] = src[i];
}

__global__ void scatter_kernel(const int* __restrict__ esrc, const int* __restrict__ edst,
                               int* __restrict__ cur, int* __restrict__ csr) {
    int i = blockIdx.x * blockDim.x + threadIdx.x;
    if (i < EE) {
        int d = edst[i];
        int p = atomicAdd(&cur[d], 1);
        csr[p] = esrc[i];
    }
}

// ---------------- weight packing -------------------------------------------
__global__ void pack_w1(const float* __restrict__ W1, const float* __restrict__ skipW,
                        float* __restrict__ Wcat) {
    int i = blockIdx.x * blockDim.x + threadIdx.x;
    if (i >= 256 * 768) return;
    int r = i / 768, c = i % 768;
    float v;
    if (c < 256) v = W1[r * 256 + c];
    else if (c < 512) v = W1[256 * 256 + r * 256 + (c - 256)];
    else v = skipW[r * 256 + (c - 512)];
    Wcat[i] = v;
}

__global__ void pack_w2(const float* __restrict__ W2, const float* __restrict__ finalW,
                        float* __restrict__ Wcat2) {
    int i = blockIdx.x * blockDim.x + threadIdx.x;
    if (i >= 256 * 128) return;
    int r = i / 128, c = i % 128;
    Wcat2[i] = (c < 64) ? W2[r * 64 + c] : finalW[r * 64 + (c - 64)];
}

// ---------------- fp32 tiled GEMM: C = A[M,256] * B[256,Nn] ----------------
// Output routed to up-to-3 separate buffers by column bucket of width `split`.
#define BM 64
#define BN 64
#define BK 16
__global__ __launch_bounds__(256) void gemm256(const float* __restrict__ A,
                                               const float* __restrict__ B, int M, int Ncols,
                                               float* C0, float* C1, float* C2, int split) {
    __shared__ float As[BK][BM + 1];
    __shared__ float Bs[BK][BN];
    int m0 = blockIdx.y * BM, n0 = blockIdx.x * BN;
    int tid = threadIdx.x;
    int ty = tid >> 4, tx = tid & 15;
    float acc[4][4] = {};
    for (int k0 = 0; k0 < 256; k0 += BK) {
#pragma unroll
        for (int r = 0; r < 4; r++) {
            int idx = tid + r * 256;
            int mm = idx >> 4, kk = idx & 15;
            int gm = m0 + mm;
            As[kk][mm] = (gm < M) ? A[gm * 256 + k0 + kk] : 0.f;
        }
#pragma unroll
        for (int r = 0; r < 4; r++) {
            int idx = tid + r * 256;
            int kk = idx >> 6, nn = idx & 63;
            Bs[kk][nn] = B[(k0 + kk) * Ncols + n0 + nn];
        }
        __syncthreads();
#pragma unroll
        for (int k = 0; k < BK; k++) {
            float a[4], b[4];
#pragma unroll
            for (int i = 0; i < 4; i++) a[i] = As[k][ty * 4 + i];
#pragma unroll
            for (int j = 0; j < 4; j++) b[j] = Bs[k][tx * 4 + j];
#pragma unroll
            for (int i = 0; i < 4; i++)
#pragma unroll
                for (int j = 0; j < 4; j++) acc[i][j] += a[i] * b[j];
        }
        __syncthreads();
    }
    int bucket = n0 / split;
    float* C = (bucket == 0) ? C0 : ((bucket == 1) ? C1 : C2);
    int ncol0 = n0 - bucket * split;
#pragma unroll
    for (int i = 0; i < 4; i++) {
        int gm = m0 + ty * 4 + i;
        if (gm < M) {
#pragma unroll
            for (int j = 0; j < 4; j++)
                C[gm * split + ncol0 + tx * 4 + j] = acc[i][j];
        }
    }
}

// ---------------- per-node attention logits (8 heads) ----------------------
__global__ void logits8(const float* __restrict__ h, const float* __restrict__ a_src,
                        const float* __restrict__ a_dst, float* __restrict__ as,
                        float* __restrict__ ad) {
    int t = blockIdx.x * blockDim.x + threadIdx.x;
    if (t >= NN * 8) return;
    int v = t >> 3, k = t & 7;
    const float* hr = h + v * 256 + k * 32;
    const float* sv = a_src + k * 32;
    const float* dv = a_dst + k * 32;
    float s = 0.f, d = 0.f;
#pragma unroll
    for (int c = 0; c < 32; c++) {
        float hv = hr[c];
        s += hv * sv[c];
        d += hv * dv[c];
    }
    as[t] = s;
    ad[t] = d;
}

__global__ void logits1(const float* __restrict__ h2, const float* __restrict__ a_src,
                        const float* __restrict__ a_dst, float* __restrict__ as,
                        float* __restrict__ ad) {
    int v = blockIdx.x * blockDim.x + threadIdx.x;
    if (v >= NN) return;
    const float* hr = h2 + v * 64;
    float s = 0.f, d = 0.f;
#pragma unroll
    for (int c = 0; c < 64; c++) {
        float hv = hr[c];
        s += hv * a_src[c];
        d += hv * a_dst[c];
    }
    as[v] = s;
    ad[v] = d;
}

// ---------------- GAT softmax + aggregate, 8 heads, warp per dst node ------
__global__ __launch_bounds__(256) void gat_agg8(const float* __restrict__ h,
                                                const float* __restrict__ as,
                                                const float* __restrict__ ad,
                                                const int* __restrict__ off,
                                                const int* __restrict__ csr,
                                                float* __restrict__ out) {
    int warp = (blockIdx.x * blockDim.x + threadIdx.x) >> 5;
    int lane = threadIdx.x & 31;
    if (warp >= NN) return;
    int v = warp;
    int s0 = off[v];
    int d = off[v + 1] - s0;
    float adv[8], asv[8];
#pragma unroll
    for (int k = 0; k < 8; k++) { adv[k] = ad[v * 8 + k]; asv[k] = as[v * 8 + k]; }

    // pass 1: max (self loop included in init)
    float m[8];
#pragma unroll
    for (int k = 0; k < 8; k++) m[k] = lrelu(asv[k] + adv[k]);
    for (int j = lane; j < d; j += 32) {
        int s = csr[s0 + j];
#pragma unroll
        for (int k = 0; k < 8; k++) m[k] = fmaxf(m[k], lrelu(as[s * 8 + k] + adv[k]));
    }
#pragma unroll
    for (int k = 0; k < 8; k++) m[k] = wredmax(m[k]);

    // pass 2: denom
    float den[8];
#pragma unroll
    for (int k = 0; k < 8; k++)
        den[k] = (lane == 0) ? __expf(lrelu(asv[k] + adv[k]) - m[k]) : 0.f;
    for (int j = lane; j < d; j += 32) {
        int s = csr[s0 + j];
#pragma unroll
        for (int k = 0; k < 8; k++)
            den[k] += __expf(lrelu(as[s * 8 + k] + adv[k]) - m[k]);
    }
#pragma unroll
    for (int k = 0; k < 8; k++) {
        den[k] = wredsum(den[k]);
        den[k] = 1.f / (den[k] + 1e-16f);
    }

    // pass 3: aggregate (lane owns channels lane + 32k)
    float acc[8];
#pragma unroll
    for (int k = 0; k < 8; k++) {
        float al = __expf(lrelu(asv[k] + adv[k]) - m[k]) * den[k];
        acc[k] = al * h[v * 256 + k * 32 + lane];
    }
    for (int j = 0; j < d; j++) {
        int s = csr[s0 + j];  // uniform load, broadcast
        float al = 0.f;
        if (lane < 8)
            al = __expf(lrelu(as[s * 8 + lane] + adv[lane]) - m[lane]) * den[lane];
#pragma unroll
        for (int k = 0; k < 8; k++) {
            float a = __shfl_sync(0xffffffffu, al, k);
            acc[k] += a * h[s * 256 + k * 32 + lane];
        }
    }
#pragma unroll
    for (int k = 0; k < 8; k++) out[v * 256 + k * 32 + lane] = acc[k];
}

// ---------------- hop combine + skip + LayerNorm1, warp per node -----------
__global__ __launch_bounds__(256) void combine_ln(const float* __restrict__ agg0,
                                                  const float* __restrict__ agg1,
                                                  const float* __restrict__ skb,
                                                  const float* __restrict__ b1,
                                                  const float* __restrict__ skip_b,
                                                  const float* __restrict__ ha,
                                                  const float* __restrict__ g,
                                                  const float* __restrict__ bt,
                                                  float* __restrict__ first) {
    int warp = (blockIdx.x * blockDim.x + threadIdx.x) >> 5;
    int lane = threadIdx.x & 31;
    if (warp >= NN) return;
    int v = warp;
    float a0h = ha[0], a1h = ha[1];
    float mx = fmaxf(a0h, a1h);
    float e0 = __expf(a0h - mx), e1 = __expf(a1h - mx);
    float inv = 1.f / (e0 + e1);
    float w0 = e0 * inv, w1 = e1 * inv;

    float vals[8];
    float sum = 0.f;
#pragma unroll
    for (int k = 0; k < 8; k++) {
        int c = k * 32 + lane;
        float x0 = agg0[v * 256 + c] + b1[c];
        x0 = (x0 > 0.f) ? x0 : (__expf(x0) - 1.f);
        float x1 = agg1[v * 256 + c] + b1[256 + c];
        x1 = (x1 > 0.f) ? x1 : (__expf(x1) - 1.f);
        float val = w0 * x0 + w1 * x1 + skb[v * 256 + c] + skip_b[c];
        vals[k] = val;
        sum += val;
    }
    sum = wredsum(sum);
    float mu = sum * (1.f / 256.f);
    float vs = 0.f;
#pragma unroll
    for (int k = 0; k < 8; k++) {
        float dd = vals[k] - mu;
        vs += dd * dd;
    }
    vs = wredsum(vs);
    float istd = rsqrtf(vs * (1.f / 256.f) + 1e-5f);
#pragma unroll
    for (int k = 0; k < 8; k++) {
        int c = k * 32 + lane;
        first[v * 256 + c] = (vals[k] - mu) * istd * g[c] + bt[c];
    }
}

// ---------------- conv2 (1 head) aggregate + residual + LayerNorm2 ---------
__global__ __launch_bounds__(256) void conv2_ln(const float* __restrict__ h2,
                                                const float* __restrict__ fw,
                                                const float* __restrict__ as2,
                                                const float* __restrict__ ad2,
                                                const int* __restrict__ off,
                                                const int* __restrict__ csr,
                                                const float* __restrict__ b2,
                                                const float* __restrict__ finalb,
                                                const float* __restrict__ g2,
                                                const float* __restrict__ bt2,
                                                float* __restrict__ out) {
    int warp = (blockIdx.x * blockDim.x + threadIdx.x) >> 5;
    int lane = threadIdx.x & 31;
    if (warp >= NN) return;
    int v = warp;
    int s0 = off[v];
    int d = off[v + 1] - s0;
    float adv = ad2[v], asv = as2[v];
    float eself = lrelu(asv + adv);
    float m = eself;
    for (int j = lane; j < d; j += 32) {
        int s = csr[s0 + j];
        m = fmaxf(m, lrelu(as2[s] + adv));
    }
    m = wredmax(m);
    float den = (lane == 0) ? __expf(eself - m) : 0.f;
    for (int j = lane; j < d; j += 32) {
        int s = csr[s0 + j];
        den += __expf(lrelu(as2[s] + adv) - m);
    }
    den = wredsum(den);
    float inv = 1.f / (den + 1e-16f);

    float al = __expf(eself - m) * inv;
    float acc0 = al * h2[v * 64 + lane];
    float acc1 = al * h2[v * 64 + 32 + lane];
    for (int j = 0; j < d; j++) {
        int s = csr[s0 + j];  // uniform
        float a = __expf(lrelu(as2[s] + adv) - m) * inv;
        acc0 += a * h2[s * 64 + lane];
        acc1 += a * h2[s * 64 + 32 + lane];
    }
    int c0 = lane, c1 = lane + 32;
    acc0 += b2[c0] + fw[v * 64 + c0] + finalb[c0];
    acc1 += b2[c1] + fw[v * 64 + c1] + finalb[c1];
    float sum = wredsum(acc0 + acc1);
    float mu = sum * (1.f / 64.f);
    float d0 = acc0 - mu, d1 = acc1 - mu;
    float vs = wredsum(d0 * d0 + d1 * d1);
    float istd = rsqrtf(vs * (1.f / 64.f) + 1e-5f);
    out[v * 64 + c0] = d0 * istd * g2[c0] + bt2[c0];
    out[v * 64 + c1] = d1 * istd * g2[c1] + bt2[c1];
}

// ---------------- hop-attention weights to output tail ---------------------
__global__ void write_w(const float* __restrict__ ha, float* __restrict__ out) {
    if (threadIdx.x == 0) {
        float a0 = ha[0], a1 = ha[1];
        float mx = fmaxf(a0, a1);
        float e0 = __expf(a0 - mx), e1 = __expf(a1 - mx);
        float inv = 1.f / (e0 + e1);
        out[NN * 64 + 0] = e0 * inv;
        out[NN * 64 + 1] = e1 * inv;
    }
}

// ---------------- launch ----------------------------------------------------
extern "C" void kernel_launch(void* const* d_in, const int* in_sizes, int n_in,
                              void* d_out, int out_size) {
    const float* x = (const float*)d_in[0];
    const int* ei = (const int*)d_in[1];
    const int* ei2 = (const int*)d_in[2];
    const float* W1 = (const float*)d_in[3];
    const float* att_src1 = (const float*)d_in[4];
    const float* att_dst1 = (const float*)d_in[5];
    const float* b1 = (const float*)d_in[6];
    const float* W2 = (const float*)d_in[7];
    const float* att_src2 = (const float*)d_in[8];
    const float* att_dst2 = (const float*)d_in[9];
    const float* b2 = (const float*)d_in[10];
    const float* ha = (const float*)d_in[11];
    const float* skipW = (const float*)d_in[12];
    const float* skipb = (const float*)d_in[13];
    const float* finalW = (const float*)d_in[14];
    const float* finalb = (const float*)d_in[15];
    const float* ln1g = (const float*)d_in[16];
    const float* ln1b = (const float*)d_in[17];
    const float* ln2g = (const float*)d_in[18];
    const float* ln2b = (const float*)d_in[19];
    float* out = (float*)d_out;

    GS* g = nullptr;
    cudaGetSymbolAddress((void**)&g, gs);

    const int TB = 256;
    int eb = (EE + TB - 1) / TB;
    int nb = (NN + TB - 1) / TB;
    int wb = (NN + 7) / 8;  // warp-per-node grids (8 warps / 256-thread block)

    // CSR build for both graphs
    zero_int<<<nb, TB>>>(g->deg0, NN);
    zero_int<<<nb, TB>>>(g->deg1, NN);
    hist_kernel<<<eb, TB>>>(ei + EE, g->deg0);
    hist_kernel<<<eb, TB>>>(ei2 + EE, g->deg1);
    scan_kernel<<<1, 1024>>>(g->deg0, g->off0);
    scan_kernel<<<1, 1024>>>(g->deg1, g->off1);
    copy_int<<<nb, TB>>>(g->off0, g->cur0, NN);
    copy_int<<<nb, TB>>>(g->off1, g->cur1, NN);
    scatter_kernel<<<eb, TB>>>(ei, ei + EE, g->cur0, g->csr0);
    scatter_kernel<<<eb, TB>>>(ei2, ei2 + EE, g->cur1, g->csr1);

    // Pack weights
    pack_w1<<<(256 * 768 + TB - 1) / TB, TB>>>(W1, skipW, g->Wcat);
    pack_w2<<<(256 * 128 + TB - 1) / TB, TB>>>(W2, finalW, g->Wcat2);

    // GEMM1: x @ [W1_0 | W1_1 | skip_W] -> h0, h1, skb
    {
        dim3 grid(768 / BN, (NN + BM - 1) / BM);
        gemm256<<<grid, 256>>>(x, g->Wcat, NN, 768, g->h0, g->h1, g->skb, 256);
    }

    // attention logits per hop
    logits8<<<(NN * 8 + TB - 1) / TB, TB>>>(g->h0, att_src1, att_dst1, g->as0, g->ad0);
    logits8<<<(NN * 8 + TB - 1) / TB, TB>>>(g->h1, att_src1 + 256, att_dst1 + 256, g->as1, g->ad1);

    // GAT aggregation per hop
    gat_agg8<<<wb, TB>>>(g->h0, g->as0, g->ad0, g->off0, g->csr0, g->agg0);
    gat_agg8<<<wb, TB>>>(g->h1, g->as1, g->ad1, g->off1, g->csr1, g->agg1);

    // combine hops + skip + LN1
    combine_ln<<<wb, TB>>>(g->agg0, g->agg1, g->skb, b1, skipb, ha, ln1g, ln1b, g->first);

    // GEMM2: first @ [W2 | final_W] -> h2, fw
    {
        dim3 grid(128 / BN, (NN + BM - 1) / BM);
        gemm256<<<grid, 256>>>(g->first, g->Wcat2, NN, 128, g->h2, g->fw, nullptr, 64);
    }

    // conv2 logits + aggregate + residual + LN2 -> out
    logits1<<<nb, TB>>>(g->h2, att_src2, att_dst2, g->as2, g->ad2);
    conv2_ln<<<wb, TB>>>(g->h2, g->fw, g->as2, g->ad2, g->off0, g->csr0, b2, finalb,
                         ln2g, ln2b, out);

    // hop weights tail
    write_w<<<1, 32>>>(ha, out);
}

// round 3
// speedup vs baseline: 1.3780x; 1.3780x over previous
#include <cuda_runtime.h>
#include <cuda_bf16.h>
#include <math.h>
#include <stdint.h>

#define NN 50000
#define EE 800000

// ================= scratch ==================================================
struct GS {
    float hcat[(size_t)NN * 768];     // [h0 | h1 | skb] per row
    float agg0[(size_t)NN * 256];
    float agg1[(size_t)NN * 256];
    float h2fw[(size_t)NN * 128];     // [h2 | fw] per row
    float as0[NN * 8], ad0[NN * 8], as1[NN * 8], ad1[NN * 8];
    float as2[NN], ad2[NN];
    __nv_bfloat16 xh[(size_t)NN * 256], xl[(size_t)NN * 256];
    __nv_bfloat16 fxh[(size_t)NN * 256], fxl[(size_t)NN * 256];
    __nv_bfloat16 B1h[768 * 256], B1l[768 * 256];
    __nv_bfloat16 B2h[128 * 256], B2l[128 * 256];
    int deg0[NN], deg1[NN];
    int off0[NN + 1], off1[NN + 1];
    int cur0[NN], cur1[NN];
    int csr0[EE], csr1[EE];
};
__device__ GS gs;

// ================= helpers ==================================================
__device__ __forceinline__ float wredsum(float v) {
#pragma unroll
    for (int o = 16; o; o >>= 1) v += __shfl_xor_sync(0xffffffffu, v, o);
    return v;
}
__device__ __forceinline__ float wredmax(float v) {
#pragma unroll
    for (int o = 16; o; o >>= 1) v = fmaxf(v, __shfl_xor_sync(0xffffffffu, v, o));
    return v;
}
__device__ __forceinline__ float lrelu(float x) { return fmaxf(x, 0.2f * x); }
__device__ __forceinline__ uint32_t smem_u32(const void* p) {
    uint32_t a;
    asm("{ .reg .u64 t; cvta.to.shared.u64 t, %1; cvt.u32.u64 %0, t; }" : "=r"(a) : "l"(p));
    return a;
}
__device__ __forceinline__ void cp16(uint32_t dst, const void* src, bool v) {
    int bytes = v ? 16 : 0;
    asm volatile("cp.async.cg.shared.global [%0], [%1], 16, %2;\n"
                 :: "r"(dst), "l"(src), "r"(bytes));
}
__device__ __forceinline__ void ldsm4(uint32_t* r, uint32_t addr) {
    asm volatile("ldmatrix.sync.aligned.m8n8.x4.shared.b16 {%0,%1,%2,%3}, [%4];\n"
                 : "=r"(r[0]), "=r"(r[1]), "=r"(r[2]), "=r"(r[3]) : "r"(addr));
}
__device__ __forceinline__ void mma_bf16(float* d, const uint32_t* a, uint32_t b0, uint32_t b1) {
    asm volatile(
        "mma.sync.aligned.m16n8k16.row.col.f32.bf16.bf16.f32 "
        "{%0,%1,%2,%3}, {%4,%5,%6,%7}, {%8,%9}, {%0,%1,%2,%3};\n"
        : "+f"(d[0]), "+f"(d[1]), "+f"(d[2]), "+f"(d[3])
        : "r"(a[0]), "r"(a[1]), "r"(a[2]), "r"(a[3]), "r"(b0), "r"(b1));
}

// ================= CSR build ================================================
__global__ void zero_int(int* p, int n) {
    int i = blockIdx.x * blockDim.x + threadIdx.x;
    if (i < n) p[i] = 0;
}
__global__ void hist_kernel(const int* __restrict__ dst, int* __restrict__ deg) {
    int i = blockIdx.x * blockDim.x + threadIdx.x;
    if (i < EE) atomicAdd(&deg[dst[i]], 1);
}
__global__ void scan_kernel(const int* __restrict__ deg, int* __restrict__ off) {
    __shared__ int sh[1024];
    const int n = NN;
    int t = threadIdx.x;
    int chunk = (n + 1023) >> 10;
    int s = t * chunk;
    int e = min(s + chunk, n);
    int sum = 0;
    for (int i = s; i < e; i++) sum += deg[i];
    sh[t] = sum;
    __syncthreads();
#pragma unroll
    for (int o = 1; o < 1024; o <<= 1) {
        int val = (t >= o) ? sh[t - o] : 0;
        __syncthreads();
        sh[t] += val;
        __syncthreads();
    }
    int run = sh[t] - sum;
    for (int i = s; i < e; i++) { off[i] = run; run += deg[i]; }
    if (t == 1023) off[n] = sh[1023];
}
__global__ void copy_int(const int* __restrict__ src, int* __restrict__ dst, int n) {
    int i = blockIdx.x * blockDim.x + threadIdx.x;
    if (i < n) dst[i] = src[i];
}
__global__ void scatter_kernel(const int* __restrict__ esrc, const int* __restrict__ edst,
                               int* __restrict__ cur, int* __restrict__ csr) {
    int i = blockIdx.x * blockDim.x + threadIdx.x;
    if (i < EE) {
        int d = edst[i];
        int p = atomicAdd(&cur[d], 1);
        csr[p] = esrc[i];
    }
}

// ================= operand packing ==========================================
__global__ void split_x(const float* __restrict__ x, __nv_bfloat16* __restrict__ xh,
                        __nv_bfloat16* __restrict__ xl, int n) {
    int i = blockIdx.x * blockDim.x + threadIdx.x;
    if (i >= n) return;
    float v = x[i];
    __nv_bfloat16 h = __float2bfloat16(v);
    xh[i] = h;
    xl[i] = __float2bfloat16(v - __bfloat162float(h));
}
// B transposed to [n, k] row-major with bf16 split
__global__ void pack_B1(const float* __restrict__ W1, const float* __restrict__ skipW,
                        __nv_bfloat16* __restrict__ Bh, __nv_bfloat16* __restrict__ Bl) {
    int i = blockIdx.x * blockDim.x + threadIdx.x;
    if (i >= 768 * 256) return;
    int n = i / 256, k = i % 256;
    float v;
    if (n < 256) v = W1[k * 256 + n];
    else if (n < 512) v = W1[65536 + k * 256 + (n - 256)];
    else v = skipW[k * 256 + (n - 512)];
    __nv_bfloat16 h = __float2bfloat16(v);
    Bh[i] = h;
    Bl[i] = __float2bfloat16(v - __bfloat162float(h));
}
__global__ void pack_B2(const float* __restrict__ W2, const float* __restrict__ finalW,
                        __nv_bfloat16* __restrict__ Bh, __nv_bfloat16* __restrict__ Bl) {
    int i = blockIdx.x * blockDim.x + threadIdx.x;
    if (i >= 128 * 256) return;
    int n = i / 256, k = i % 256;
    float v = (n < 64) ? W2[k * 64 + n] : finalW[k * 64 + (n - 64)];
    __nv_bfloat16 h = __float2bfloat16(v);
    Bh[i] = h;
    Bl[i] = __float2bfloat16(v - __bfloat162float(h));
}

// ====== HMMA GEMM: C[M,Ncols] = A[M,256] @ B[Ncols,256]^T (bf16 2-split) ====
// CTA tile 128x128, 8 warps (2m x 4n), BK=32, cp.async double buffer.
// smem stage: Ah(10240) Al(10240) Bh(10240) Bl(10240) = 40960B; rows padded to 80B.
__global__ __launch_bounds__(256, 1) void hmma_gemm(
    const __nv_bfloat16* __restrict__ Ah, const __nv_bfloat16* __restrict__ Al,
    const __nv_bfloat16* __restrict__ Bh, const __nv_bfloat16* __restrict__ Bl,
    float* __restrict__ C, int M, int Ncols) {
    extern __shared__ char sm[];
    const int tid = threadIdx.x, lane = tid & 31, warp = tid >> 5;
    const int wm = warp & 1, wn = warp >> 1;
    const int m0 = blockIdx.y * 128, n0 = blockIdx.x * 128;
    uint32_t sbase = smem_u32(sm);

    float acc[4][4][4];
#pragma unroll
    for (int a = 0; a < 4; a++)
#pragma unroll
        for (int b = 0; b < 4; b++)
#pragma unroll
            for (int q = 0; q < 4; q++) acc[a][b][q] = 0.f;

#define LOAD_STAGE(c, s)                                                          \
    do {                                                                          \
        uint32_t sb_ = sbase + (s) * 40960;                                       \
        _Pragma("unroll") for (int it = 0; it < 2; it++) {                        \
            int idx = tid + it * 256;                                             \
            int row = idx >> 2, kc = idx & 3;                                     \
            uint32_t so = row * 80 + kc * 16;                                     \
            bool va = (m0 + row) < M;                                             \
            long ga = (long)(m0 + row) * 256 + (c) * 32 + kc * 8;                 \
            if (!va) ga = 0;                                                      \
            cp16(sb_ + so, Ah + ga, va);                                          \
            cp16(sb_ + 10240 + so, Al + ga, va);                                  \
            long gb = (long)(n0 + row) * 256 + (c) * 32 + kc * 8;                 \
            cp16(sb_ + 20480 + so, Bh + gb, true);                                \
            cp16(sb_ + 30720 + so, Bl + gb, true);                                \
        }                                                                         \
        asm volatile("cp.async.commit_group;\n" ::: "memory");                    \
    } while (0)

    LOAD_STAGE(0, 0);
    for (int c = 0; c < 8; c++) {
        if (c < 7) {
            LOAD_STAGE(c + 1, (c + 1) & 1);
            asm volatile("cp.async.wait_group 1;\n" ::: "memory");
        } else {
            asm volatile("cp.async.wait_group 0;\n" ::: "memory");
        }
        __syncthreads();
        uint32_t sb = sbase + (c & 1) * 40960;
#pragma unroll
        for (int ks = 0; ks < 2; ks++) {
            uint32_t ah[4][4], al[4][4], bhf[2][4], blf[2][4];
            int acol = ks * 16 + 8 * (lane >> 4);
            int arowl = (lane & 15);
#pragma unroll
            for (int mf = 0; mf < 4; mf++) {
                int arow = wm * 64 + mf * 16 + arowl;
                uint32_t ad = sb + arow * 80 + acol * 2;
                ldsm4(ah[mf], ad);
                ldsm4(al[mf], ad + 10240);
            }
            int bcol = ks * 16 + 8 * ((lane >> 3) & 1);
            int browl = (lane & 7) + 8 * (lane >> 4);
#pragma unroll
            for (int p = 0; p < 2; p++) {
                int brow = wn * 32 + p * 16 + browl;
                uint32_t bd = sb + 20480 + brow * 80 + bcol * 2;
                ldsm4(bhf[p], bd);
                ldsm4(blf[p], bd + 10240);
            }
#pragma unroll
            for (int mf = 0; mf < 4; mf++)
#pragma unroll
                for (int p = 0; p < 2; p++)
#pragma unroll
                    for (int sub = 0; sub < 2; sub++) {
                        int nf = p * 2 + sub;
                        uint32_t h0 = bhf[p][sub * 2], h1 = bhf[p][sub * 2 + 1];
                        uint32_t l0 = blf[p][sub * 2], l1 = blf[p][sub * 2 + 1];
                        mma_bf16(acc[mf][nf], ah[mf], h0, h1);
                        mma_bf16(acc[mf][nf], ah[mf], l0, l1);
                        mma_bf16(acc[mf][nf], al[mf], h0, h1);
                    }
        }
        __syncthreads();
    }
#undef LOAD_STAGE

    int group = lane >> 2, q = lane & 3;
#pragma unroll
    for (int mf = 0; mf < 4; mf++) {
        int r0 = m0 + wm * 64 + mf * 16 + group;
#pragma unroll
        for (int nf = 0; nf < 4; nf++) {
            int col = n0 + wn * 32 + nf * 8 + q * 2;
            if (r0 < M)
                *(float2*)(C + (long)r0 * Ncols + col) =
                    make_float2(acc[mf][nf][0], acc[mf][nf][1]);
            if (r0 + 8 < M)
                *(float2*)(C + (long)(r0 + 8) * Ncols + col) =
                    make_float2(acc[mf][nf][2], acc[mf][nf][3]);
        }
    }
}

// ================= attention logits =========================================
__global__ void logits8(const float* __restrict__ h, int stride, const float* __restrict__ a_src,
                        const float* __restrict__ a_dst, float* __restrict__ as,
                        float* __restrict__ ad) {
    int t = blockIdx.x * blockDim.x + threadIdx.x;
    if (t >= NN * 8) return;
    int v = t >> 3, k = t & 7;
    const float* hr = h + (long)v * stride + k * 32;
    const float* sv = a_src + k * 32;
    const float* dv = a_dst + k * 32;
    float s = 0.f, d = 0.f;
#pragma unroll
    for (int c = 0; c < 32; c++) {
        float hv = hr[c];
        s += hv * sv[c];
        d += hv * dv[c];
    }
    as[t] = s;
    ad[t] = d;
}
__global__ void logits1(const float* __restrict__ h2, const float* __restrict__ a_src,
                        const float* __restrict__ a_dst, float* __restrict__ as,
                        float* __restrict__ ad) {
    int v = blockIdx.x * blockDim.x + threadIdx.x;
    if (v >= NN) return;
    const float* hr = h2 + (long)v * 128;
    float s = 0.f, d = 0.f;
#pragma unroll
    for (int c = 0; c < 64; c++) {
        float hv = hr[c];
        s += hv * a_src[c];
        d += hv * a_dst[c];
    }
    as[v] = s;
    ad[v] = d;
}

// ================= GAT aggregation (8 heads, warp per dst) ==================
__global__ __launch_bounds__(256) void gat_agg8(const float* __restrict__ h, int stride,
                                                const float* __restrict__ as,
                                                const float* __restrict__ ad,
                                                const int* __restrict__ off,
                                                const int* __restrict__ csr,
                                                float* __restrict__ out) {
    int warp = (blockIdx.x * blockDim.x + threadIdx.x) >> 5;
    int lane = threadIdx.x & 31;
    if (warp >= NN) return;
    int v = warp;
    int s0 = off[v];
    int d = off[v + 1] - s0;
    float adv[8], asv[8];
#pragma unroll
    for (int k = 0; k < 8; k++) { adv[k] = ad[v * 8 + k]; asv[k] = as[v * 8 + k]; }

    float m[8];
#pragma unroll
    for (int k = 0; k < 8; k++) m[k] = lrelu(asv[k] + adv[k]);
    for (int j = lane; j < d; j += 32) {
        int s = csr[s0 + j];
#pragma unroll
        for (int k = 0; k < 8; k++) m[k] = fmaxf(m[k], lrelu(as[s * 8 + k] + adv[k]));
    }
#pragma unroll
    for (int k = 0; k < 8; k++) m[k] = wredmax(m[k]);

    float den[8];
#pragma unroll
    for (int k = 0; k < 8; k++)
        den[k] = (lane == 0) ? __expf(lrelu(asv[k] + adv[k]) - m[k]) : 0.f;
    for (int j = lane; j < d; j += 32) {
        int s = csr[s0 + j];
#pragma unroll
        for (int k = 0; k < 8; k++)
            den[k] += __expf(lrelu(as[s * 8 + k] + adv[k]) - m[k]);
    }
#pragma unroll
    for (int k = 0; k < 8; k++) {
        den[k] = wredsum(den[k]);
        den[k] = 1.f / (den[k] + 1e-16f);
    }

    float acc[8];
#pragma unroll
    for (int k = 0; k < 8; k++) {
        float al = __expf(lrelu(asv[k] + adv[k]) - m[k]) * den[k];
        acc[k] = al * h[(long)v * stride + k * 32 + lane];
    }
    for (int j = 0; j < d; j++) {
        int s = csr[s0 + j];
        float al = 0.f;
        if (lane < 8)
            al = __expf(lrelu(as[s * 8 + lane] + adv[lane]) - m[lane]) * den[lane];
#pragma unroll
        for (int k = 0; k < 8; k++) {
            float a = __shfl_sync(0xffffffffu, al, k);
            acc[k] += a * h[(long)s * stride + k * 32 + lane];
        }
    }
#pragma unroll
    for (int k = 0; k < 8; k++) out[(long)v * 256 + k * 32 + lane] = acc[k];
}

// ========== hop combine + skip + LN1 -> bf16 split for GEMM2 ================
__global__ __launch_bounds__(256) void combine_ln(const float* __restrict__ agg0,
                                                  const float* __restrict__ agg1,
                                                  const float* __restrict__ hcat,
                                                  const float* __restrict__ b1,
                                                  const float* __restrict__ skip_b,
                                                  const float* __restrict__ ha,
                                                  const float* __restrict__ g,
                                                  const float* __restrict__ bt,
                                                  __nv_bfloat16* __restrict__ fxh,
                                                  __nv_bfloat16* __restrict__ fxl) {
    int warp = (blockIdx.x * blockDim.x + threadIdx.x) >> 5;
    int lane = threadIdx.x & 31;
    if (warp >= NN) return;
    int v = warp;
    float a0h = ha[0], a1h = ha[1];
    float mx = fmaxf(a0h, a1h);
    float e0 = __expf(a0h - mx), e1 = __expf(a1h - mx);
    float inv = 1.f / (e0 + e1);
    float w0 = e0 * inv, w1 = e1 * inv;

    float vals[8];
    float sum = 0.f;
#pragma unroll
    for (int k = 0; k < 8; k++) {
        int c = k * 32 + lane;
        float x0 = agg0[(long)v * 256 + c] + b1[c];
        x0 = (x0 > 0.f) ? x0 : (__expf(x0) - 1.f);
        float x1 = agg1[(long)v * 256 + c] + b1[256 + c];
        x1 = (x1 > 0.f) ? x1 : (__expf(x1) - 1.f);
        float val = w0 * x0 + w1 * x1 + hcat[(long)v * 768 + 512 + c] + skip_b[c];
        vals[k] = val;
        sum += val;
    }
    sum = wredsum(sum);
    float mu = sum * (1.f / 256.f);
    float vs = 0.f;
#pragma unroll
    for (int k = 0; k < 8; k++) {
        float dd = vals[k] - mu;
        vs += dd * dd;
    }
    vs = wredsum(vs);
    float istd = rsqrtf(vs * (1.f / 256.f) + 1e-5f);
#pragma unroll
    for (int k = 0; k < 8; k++) {
        int c = k * 32 + lane;
        float y = (vals[k] - mu) * istd * g[c] + bt[c];
        __nv_bfloat16 hi = __float2bfloat16(y);
        fxh[(long)v * 256 + c] = hi;
        fxl[(long)v * 256 + c] = __float2bfloat16(y - __bfloat162float(hi));
    }
}

// ========== conv2 aggregate + residual + LN2 ================================
__global__ __launch_bounds__(256) void conv2_ln(const float* __restrict__ h2fw,
                                                const float* __restrict__ as2,
                                                const float* __restrict__ ad2,
                                                const int* __restrict__ off,
                                                const int* __restrict__ csr,
                                                const float* __restrict__ b2,
                                                const float* __restrict__ finalb,
                                                const float* __restrict__ g2,
                                                const float* __restrict__ bt2,
                                                float* __restrict__ out) {
    int warp = (blockIdx.x * blockDim.x + threadIdx.x) >> 5;
    int lane = threadIdx.x & 31;
    if (warp >= NN) return;
    int v = warp;
    int s0 = off[v];
    int d = off[v + 1] - s0;
    float adv = ad2[v], asv = as2[v];
    float eself = lrelu(asv + adv);
    float m = eself;
    for (int j = lane; j < d; j += 32) {
        int s = csr[s0 + j];
        m = fmaxf(m, lrelu(as2[s] + adv));
    }
    m = wredmax(m);
    float den = (lane == 0) ? __expf(eself - m) : 0.f;
    for (int j = lane; j < d; j += 32) {
        int s = csr[s0 + j];
        den += __expf(lrelu(as2[s] + adv) - m);
    }
    den = wredsum(den);
    float inv = 1.f / (den + 1e-16f);

    float al = __expf(eself - m) * inv;
    float acc0 = al * h2fw[(long)v * 128 + lane];
    float acc1 = al * h2fw[(long)v * 128 + 32 + lane];
    for (int j = 0; j < d; j++) {
        int s = csr[s0 + j];
        float a = __expf(lrelu(as2[s] + adv) - m) * inv;
        acc0 += a * h2fw[(long)s * 128 + lane];
        acc1 += a * h2fw[(long)s * 128 + 32 + lane];
    }
    int c0 = lane, c1 = lane + 32;
    acc0 += b2[c0] + h2fw[(long)v * 128 + 64 + c0] + finalb[c0];
    acc1 += b2[c1] + h2fw[(long)v * 128 + 64 + c1] + finalb[c1];
    float sum = wredsum(acc0 + acc1);
    float mu = sum * (1.f / 64.f);
    float d0 = acc0 - mu, d1 = acc1 - mu;
    float vs = wredsum(d0 * d0 + d1 * d1);
    float istd = rsqrtf(vs * (1.f / 64.f) + 1e-5f);
    out[(long)v * 64 + c0] = d0 * istd * g2[c0] + bt2[c0];
    out[(long)v * 64 + c1] = d1 * istd * g2[c1] + bt2[c1];
}

__global__ void write_w(const float* __restrict__ ha, float* __restrict__ out) {
    if (threadIdx.x == 0) {
        float a0 = ha[0], a1 = ha[1];
        float mx = fmaxf(a0, a1);
        float e0 = __expf(a0 - mx), e1 = __expf(a1 - mx);
        float inv = 1.f / (e0 + e1);
        out[NN * 64 + 0] = e0 * inv;
        out[NN * 64 + 1] = e1 * inv;
    }
}

// ================= launch ===================================================
extern "C" void kernel_launch(void* const* d_in, const int* in_sizes, int n_in,
                              void* d_out, int out_size) {
    const float* x = (const float*)d_in[0];
    const int* ei = (const int*)d_in[1];
    const int* ei2 = (const int*)d_in[2];
    const float* W1 = (const float*)d_in[3];
    const float* att_src1 = (const float*)d_in[4];
    const float* att_dst1 = (const float*)d_in[5];
    const float* b1 = (const float*)d_in[6];
    const float* W2 = (const float*)d_in[7];
    const float* att_src2 = (const float*)d_in[8];
    const float* att_dst2 = (const float*)d_in[9];
    const float* b2 = (const float*)d_in[10];
    const float* ha = (const float*)d_in[11];
    const float* skipW = (const float*)d_in[12];
    const float* skipb = (const float*)d_in[13];
    const float* finalW = (const float*)d_in[14];
    const float* finalb = (const float*)d_in[15];
    const float* ln1g = (const float*)d_in[16];
    const float* ln1b = (const float*)d_in[17];
    const float* ln2g = (const float*)d_in[18];
    const float* ln2b = (const float*)d_in[19];
    float* out = (float*)d_out;

    GS* g = nullptr;
    cudaGetSymbolAddress((void**)&g, gs);

    const int GSMEM = 2 * 40960;  // 80 KB double-buffered
    cudaFuncSetAttribute(hmma_gemm, cudaFuncAttributeMaxDynamicSharedMemorySize, GSMEM);

    const int TB = 256;
    int eb = (EE + TB - 1) / TB;
    int nb = (NN + TB - 1) / TB;
    int wb = (NN + 7) / 8;

    // operand prep
    split_x<<<(NN * 256 + TB - 1) / TB, TB>>>(x, g->xh, g->xl, NN * 256);
    pack_B1<<<(768 * 256 + TB - 1) / TB, TB>>>(W1, skipW, g->B1h, g->B1l);
    pack_B2<<<(128 * 256 + TB - 1) / TB, TB>>>(W2, finalW, g->B2h, g->B2l);

    // GEMM1: x @ [W1_0 | W1_1 | skip_W] -> hcat
    {
        dim3 grid(6, (NN + 127) / 128);
        hmma_gemm<<<grid, 256, GSMEM>>>(g->xh, g->xl, g->B1h, g->B1l, g->hcat, NN, 768);
    }

    // CSR build
    zero_int<<<nb, TB>>>(g->deg0, NN);
    zero_int<<<nb, TB>>>(g->deg1, NN);
    hist_kernel<<<eb, TB>>>(ei + EE, g->deg0);
    hist_kernel<<<eb, TB>>>(ei2 + EE, g->deg1);
    scan_kernel<<<1, 1024>>>(g->deg0, g->off0);
    scan_kernel<<<1, 1024>>>(g->deg1, g->off1);
    copy_int<<<nb, TB>>>(g->off0, g->cur0, NN);
    copy_int<<<nb, TB>>>(g->off1, g->cur1, NN);
    scatter_kernel<<<eb, TB>>>(ei, ei + EE, g->cur0, g->csr0);
    scatter_kernel<<<eb, TB>>>(ei2, ei2 + EE, g->cur1, g->csr1);

    // logits per hop
    logits8<<<(NN * 8 + TB - 1) / TB, TB>>>(g->hcat, 768, att_src1, att_dst1, g->as0, g->ad0);
    logits8<<<(NN * 8 + TB - 1) / TB, TB>>>(g->hcat + 256, 768, att_src1 + 256, att_dst1 + 256,
                                            g->as1, g->ad1);

    // GAT aggregation per hop
    gat_agg8<<<wb, TB>>>(g->hcat, 768, g->as0, g->ad0, g->off0, g->csr0, g->agg0);
    gat_agg8<<<wb, TB>>>(g->hcat + 256, 768, g->as1, g->ad1, g->off1, g->csr1, g->agg1);

    // combine + skip + LN1 -> bf16 split
    combine_ln<<<wb, TB>>>(g->agg0, g->agg1, g->hcat, b1, skipb, ha, ln1g, ln1b, g->fxh, g->fxl);

    // GEMM2: first @ [W2 | final_W] -> h2fw
    {
        dim3 grid(1, (NN + 127) / 128);
        hmma_gemm<<<grid, 256, GSMEM>>>(g->fxh, g->fxl, g->B2h, g->B2l, g->h2fw, NN, 128);
    }

    logits1<<<nb, TB>>>(g->h2fw, att_src2, att_dst2, g->as2, g->ad2);
    conv2_ln<<<wb, TB>>>(g->h2fw, g->as2, g->ad2, g->off0, g->csr0, b2, finalb, ln2g, ln2b, out);
    write_w<<<1, 32>>>(ha, out);
}

// round 4
// speedup vs baseline: 1.4810x; 1.0748x over previous
#include <cuda_runtime.h>
#include <cuda_bf16.h>
#include <math.h>
#include <stdint.h>

#define NN 50000
#define EE 800000

// ================= scratch ==================================================
struct GS {
    float h0[(size_t)NN * 256];
    float h1[(size_t)NN * 256];
    float skb[(size_t)NN * 256];
    float agg0[(size_t)NN * 256];
    float agg1[(size_t)NN * 256];
    float h2fw[(size_t)NN * 128];     // [h2 | fw] per row
    float as0[NN * 8], ad0[NN * 8], as1[NN * 8], ad1[NN * 8];
    float as2[NN], ad2[NN];
    __nv_bfloat16 xh[(size_t)NN * 256], xl[(size_t)NN * 256];
    __nv_bfloat16 fxh[(size_t)NN * 256], fxl[(size_t)NN * 256];
    __nv_bfloat16 B1h[768 * 256], B1l[768 * 256];
    __nv_bfloat16 B2h[128 * 256], B2l[128 * 256];
    int deg0[NN], deg1[NN];
    int off0[NN + 1], off1[NN + 1];
    int cur0[NN], cur1[NN];
    int csr0[EE], csr1[EE];
};
__device__ GS gs;

// ================= helpers ==================================================
__device__ __forceinline__ float wredsum(float v) {
#pragma unroll
    for (int o = 16; o; o >>= 1) v += __shfl_xor_sync(0xffffffffu, v, o);
    return v;
}
__device__ __forceinline__ float wredmax(float v) {
#pragma unroll
    for (int o = 16; o; o >>= 1) v = fmaxf(v, __shfl_xor_sync(0xffffffffu, v, o));
    return v;
}
__device__ __forceinline__ float lrelu(float x) { return fmaxf(x, 0.2f * x); }
__device__ __forceinline__ uint32_t smem_u32(const void* p) {
    uint32_t a;
    asm("{ .reg .u64 t; cvta.to.shared.u64 t, %1; cvt.u32.u64 %0, t; }" : "=r"(a) : "l"(p));
    return a;
}
__device__ __forceinline__ void cp16(uint32_t dst, const void* src, bool v) {
    int bytes = v ? 16 : 0;
    asm volatile("cp.async.cg.shared.global [%0], [%1], 16, %2;\n"
                 :: "r"(dst), "l"(src), "r"(bytes));
}
__device__ __forceinline__ void ldsm4(uint32_t* r, uint32_t addr) {
    asm volatile("ldmatrix.sync.aligned.m8n8.x4.shared.b16 {%0,%1,%2,%3}, [%4];\n"
                 : "=r"(r[0]), "=r"(r[1]), "=r"(r[2]), "=r"(r[3]) : "r"(addr));
}
__device__ __forceinline__ void mma_bf16(float* d, const uint32_t* a, uint32_t b0, uint32_t b1) {
    asm volatile(
        "mma.sync.aligned.m16n8k16.row.col.f32.bf16.bf16.f32 "
        "{%0,%1,%2,%3}, {%4,%5,%6,%7}, {%8,%9}, {%0,%1,%2,%3};\n"
        : "+f"(d[0]), "+f"(d[1]), "+f"(d[2]), "+f"(d[3])
        : "r"(a[0]), "r"(a[1]), "r"(a[2]), "r"(a[3]), "r"(b0), "r"(b1));
}

// ================= CSR build ================================================
__global__ void zero_int(int* p, int n) {
    int i = blockIdx.x * blockDim.x + threadIdx.x;
    if (i < n) p[i] = 0;
}
__global__ void hist_kernel(const int* __restrict__ dst, int* __restrict__ deg) {
    int i = blockIdx.x * blockDim.x + threadIdx.x;
    if (i < EE) atomicAdd(&deg[dst[i]], 1);
}
__global__ void scan_kernel(const int* __restrict__ deg, int* __restrict__ off) {
    __shared__ int sh[1024];
    const int n = NN;
    int t = threadIdx.x;
    int chunk = (n + 1023) >> 10;
    int s = t * chunk;
    int e = min(s + chunk, n);
    int sum = 0;
    for (int i = s; i < e; i++) sum += deg[i];
    sh[t] = sum;
    __syncthreads();
#pragma unroll
    for (int o = 1; o < 1024; o <<= 1) {
        int val = (t >= o) ? sh[t - o] : 0;
        __syncthreads();
        sh[t] += val;
        __syncthreads();
    }
    int run = sh[t] - sum;
    for (int i = s; i < e; i++) { off[i] = run; run += deg[i]; }
    if (t == 1023) off[n] = sh[1023];
}
__global__ void copy_int(const int* __restrict__ src, int* __restrict__ dst, int n) {
    int i = blockIdx.x * blockDim.x + threadIdx.x;
    if (i < n) dst[i] = src[i];
}
__global__ void scatter_kernel(const int* __restrict__ esrc, const int* __restrict__ edst,
                               int* __restrict__ cur, int* __restrict__ csr) {
    int i = blockIdx.x * blockDim.x + threadIdx.x;
    if (i < EE) {
        int d = edst[i];
        int p = atomicAdd(&cur[d], 1);
        csr[p] = esrc[i];
    }
}

// ================= operand packing ==========================================
__global__ void split_x(const float* __restrict__ x, __nv_bfloat16* __restrict__ xh,
                        __nv_bfloat16* __restrict__ xl, int n) {
    int i = blockIdx.x * blockDim.x + threadIdx.x;
    if (i >= n) return;
    float v = x[i];
    __nv_bfloat16 h = __float2bfloat16(v);
    xh[i] = h;
    xl[i] = __float2bfloat16(v - __bfloat162float(h));
}
// B transposed to [n, k] row-major with bf16 split
__global__ void pack_B1(const float* __restrict__ W1, const float* __restrict__ skipW,
                        __nv_bfloat16* __restrict__ Bh, __nv_bfloat16* __restrict__ Bl) {
    int i = blockIdx.x * blockDim.x + threadIdx.x;
    if (i >= 768 * 256) return;
    int n = i / 256, k = i % 256;
    float v;
    if (n < 256) v = W1[k * 256 + n];
    else if (n < 512) v = W1[65536 + k * 256 + (n - 256)];
    else v = skipW[k * 256 + (n - 512)];
    __nv_bfloat16 h = __float2bfloat16(v);
    Bh[i] = h;
    Bl[i] = __float2bfloat16(v - __bfloat162float(h));
}
__global__ void pack_B2(const float* __restrict__ W2, const float* __restrict__ finalW,
                        __nv_bfloat16* __restrict__ Bh, __nv_bfloat16* __restrict__ Bl) {
    int i = blockIdx.x * blockDim.x + threadIdx.x;
    if (i >= 128 * 256) return;
    int n = i / 256, k = i % 256;
    float v = (n < 64) ? W2[k * 64 + n] : finalW[k * 64 + (n - 64)];
    __nv_bfloat16 h = __float2bfloat16(v);
    Bh[i] = h;
    Bl[i] = __float2bfloat16(v - __bfloat162float(h));
}

// ====== HMMA GEMM: C[M,*] = A[M,256] @ B[*,256]^T (bf16 2-split) ============
// CTA tile 128x128, 8 warps (2m x 4n), BK=32, cp.async double buffer.
// Output column block n0 routed to C0/C1/C2 by bucket of width `split`.
__global__ __launch_bounds__(256, 2) void hmma_gemm(
    const __nv_bfloat16* __restrict__ Ah, const __nv_bfloat16* __restrict__ Al,
    const __nv_bfloat16* __restrict__ Bh, const __nv_bfloat16* __restrict__ Bl,
    float* __restrict__ C0, float* __restrict__ C1, float* __restrict__ C2,
    int M, int split) {
    extern __shared__ char sm[];
    const int tid = threadIdx.x, lane = tid & 31, warp = tid >> 5;
    const int wm = warp & 1, wn = warp >> 1;
    const int m0 = blockIdx.y * 128, n0 = blockIdx.x * 128;
    uint32_t sbase = smem_u32(sm);

    float acc[4][4][4];
#pragma unroll
    for (int a = 0; a < 4; a++)
#pragma unroll
        for (int b = 0; b < 4; b++)
#pragma unroll
            for (int q = 0; q < 4; q++) acc[a][b][q] = 0.f;

#define LOAD_STAGE(c, s)                                                          \
    do {                                                                          \
        uint32_t sb_ = sbase + (s) * 40960;                                       \
        _Pragma("unroll") for (int it = 0; it < 2; it++) {                        \
            int idx = tid + it * 256;                                             \
            int row = idx >> 2, kc = idx & 3;                                     \
            uint32_t so = row * 80 + kc * 16;                                     \
            bool va = (m0 + row) < M;                                             \
            long ga = (long)(m0 + row) * 256 + (c) * 32 + kc * 8;                 \
            if (!va) ga = 0;                                                      \
            cp16(sb_ + so, Ah + ga, va);                                          \
            cp16(sb_ + 10240 + so, Al + ga, va);                                  \
            long gb = (long)(n0 + row) * 256 + (c) * 32 + kc * 8;                 \
            cp16(sb_ + 20480 + so, Bh + gb, true);                                \
            cp16(sb_ + 30720 + so, Bl + gb, true);                                \
        }                                                                         \
        asm volatile("cp.async.commit_group;\n" ::: "memory");                    \
    } while (0)

    LOAD_STAGE(0, 0);
    for (int c = 0; c < 8; c++) {
        if (c < 7) {
            LOAD_STAGE(c + 1, (c + 1) & 1);
            asm volatile("cp.async.wait_group 1;\n" ::: "memory");
        } else {
            asm volatile("cp.async.wait_group 0;\n" ::: "memory");
        }
        __syncthreads();
        uint32_t sb = sbase + (c & 1) * 40960;
#pragma unroll
        for (int ks = 0; ks < 2; ks++) {
            uint32_t ah[4][4], al[4][4], bhf[2][4], blf[2][4];
            int acol = ks * 16 + 8 * (lane >> 4);
            int arowl = (lane & 15);
#pragma unroll
            for (int mf = 0; mf < 4; mf++) {
                int arow = wm * 64 + mf * 16 + arowl;
                uint32_t ad = sb + arow * 80 + acol * 2;
                ldsm4(ah[mf], ad);
                ldsm4(al[mf], ad + 10240);
            }
            int bcol = ks * 16 + 8 * ((lane >> 3) & 1);
            int browl = (lane & 7) + 8 * (lane >> 4);
#pragma unroll
            for (int p = 0; p < 2; p++) {
                int brow = wn * 32 + p * 16 + browl;
                uint32_t bd = sb + 20480 + brow * 80 + bcol * 2;
                ldsm4(bhf[p], bd);
                ldsm4(blf[p], bd + 10240);
            }
#pragma unroll
            for (int mf = 0; mf < 4; mf++)
#pragma unroll
                for (int p = 0; p < 2; p++)
#pragma unroll
                    for (int sub = 0; sub < 2; sub++) {
                        int nf = p * 2 + sub;
                        uint32_t h0 = bhf[p][sub * 2], h1 = bhf[p][sub * 2 + 1];
                        uint32_t l0 = blf[p][sub * 2], l1 = blf[p][sub * 2 + 1];
                        mma_bf16(acc[mf][nf], ah[mf], h0, h1);
                        mma_bf16(acc[mf][nf], ah[mf], l0, l1);
                        mma_bf16(acc[mf][nf], al[mf], h0, h1);
                    }
        }
        __syncthreads();
    }
#undef LOAD_STAGE

    int bucket = n0 / split;
    float* C = (bucket == 0) ? C0 : ((bucket == 1) ? C1 : C2);
    int cb = n0 - bucket * split;
    int group = lane >> 2, q = lane & 3;
#pragma unroll
    for (int mf = 0; mf < 4; mf++) {
        int r0 = m0 + wm * 64 + mf * 16 + group;
#pragma unroll
        for (int nf = 0; nf < 4; nf++) {
            int col = cb + wn * 32 + nf * 8 + q * 2;
            if (r0 < M)
                *(float2*)(C + (long)r0 * split + col) =
                    make_float2(acc[mf][nf][0], acc[mf][nf][1]);
            if (r0 + 8 < M)
                *(float2*)(C + (long)(r0 + 8) * split + col) =
                    make_float2(acc[mf][nf][2], acc[mf][nf][3]);
        }
    }
}

// ================= attention logits =========================================
__global__ void logits8(const float* __restrict__ h, const float* __restrict__ a_src,
                        const float* __restrict__ a_dst, float* __restrict__ as,
                        float* __restrict__ ad) {
    int t = blockIdx.x * blockDim.x + threadIdx.x;
    if (t >= NN * 8) return;
    int v = t >> 3, k = t & 7;
    const float* hr = h + (long)v * 256 + k * 32;
    const float* sv = a_src + k * 32;
    const float* dv = a_dst + k * 32;
    float s = 0.f, d = 0.f;
#pragma unroll
    for (int c = 0; c < 32; c++) {
        float hv = hr[c];
        s += hv * sv[c];
        d += hv * dv[c];
    }
    as[t] = s;
    ad[t] = d;
}
__global__ void logits1(const float* __restrict__ h2, const float* __restrict__ a_src,
                        const float* __restrict__ a_dst, float* __restrict__ as,
                        float* __restrict__ ad) {
    int v = blockIdx.x * blockDim.x + threadIdx.x;
    if (v >= NN) return;
    const float* hr = h2 + (long)v * 128;
    float s = 0.f, d = 0.f;
#pragma unroll
    for (int c = 0; c < 64; c++) {
        float hv = hr[c];
        s += hv * a_src[c];
        d += hv * a_dst[c];
    }
    as[v] = s;
    ad[v] = d;
}

// ================= GAT aggregation (8 heads, warp per dst) ==================
__global__ __launch_bounds__(256) void gat_agg8(const float* __restrict__ h,
                                                const float* __restrict__ as,
                                                const float* __restrict__ ad,
                                                const int* __restrict__ off,
                                                const int* __restrict__ csr,
                                                float* __restrict__ out) {
    int warp = (blockIdx.x * blockDim.x + threadIdx.x) >> 5;
    int lane = threadIdx.x & 31;
    if (warp >= NN) return;
    int v = warp;
    int s0 = off[v];
    int d = off[v + 1] - s0;
    float adv[8], asv[8];
#pragma unroll
    for (int k = 0; k < 8; k++) { adv[k] = ad[v * 8 + k]; asv[k] = as[v * 8 + k]; }

    float m[8];
#pragma unroll
    for (int k = 0; k < 8; k++) m[k] = lrelu(asv[k] + adv[k]);
    for (int j = lane; j < d; j += 32) {
        int s = csr[s0 + j];
#pragma unroll
        for (int k = 0; k < 8; k++) m[k] = fmaxf(m[k], lrelu(as[s * 8 + k] + adv[k]));
    }
#pragma unroll
    for (int k = 0; k < 8; k++) m[k] = wredmax(m[k]);

    float den[8];
#pragma unroll
    for (int k = 0; k < 8; k++)
        den[k] = (lane == 0) ? __expf(lrelu(asv[k] + adv[k]) - m[k]) : 0.f;
    for (int j = lane; j < d; j += 32) {
        int s = csr[s0 + j];
#pragma unroll
        for (int k = 0; k < 8; k++)
            den[k] += __expf(lrelu(as[s * 8 + k] + adv[k]) - m[k]);
    }
#pragma unroll
    for (int k = 0; k < 8; k++) {
        den[k] = wredsum(den[k]);
        den[k] = 1.f / (den[k] + 1e-16f);
    }

    float acc[8];
#pragma unroll
    for (int k = 0; k < 8; k++) {
        float al = __expf(lrelu(asv[k] + adv[k]) - m[k]) * den[k];
        acc[k] = al * h[(long)v * 256 + k * 32 + lane];
    }
    for (int j = 0; j < d; j++) {
        int s = csr[s0 + j];
        float al = 0.f;
        if (lane < 8)
            al = __expf(lrelu(as[s * 8 + lane] + adv[lane]) - m[lane]) * den[lane];
#pragma unroll
        for (int k = 0; k < 8; k++) {
            float a = __shfl_sync(0xffffffffu, al, k);
            acc[k] += a * h[(long)s * 256 + k * 32 + lane];
        }
    }
#pragma unroll
    for (int k = 0; k < 8; k++) out[(long)v * 256 + k * 32 + lane] = acc[k];
}

// ========== hop combine + skip + LN1 -> bf16 split for GEMM2 ================
__global__ __launch_bounds__(256) void combine_ln(const float* __restrict__ agg0,
                                                  const float* __restrict__ agg1,
                                                  const float* __restrict__ skb,
                                                  const float* __restrict__ b1,
                                                  const float* __restrict__ skip_b,
                                                  const float* __restrict__ ha,
                                                  const float* __restrict__ g,
                                                  const float* __restrict__ bt,
                                                  __nv_bfloat16* __restrict__ fxh,
                                                  __nv_bfloat16* __restrict__ fxl) {
    int warp = (blockIdx.x * blockDim.x + threadIdx.x) >> 5;
    int lane = threadIdx.x & 31;
    if (warp >= NN) return;
    int v = warp;
    float a0h = ha[0], a1h = ha[1];
    float mx = fmaxf(a0h, a1h);
    float e0 = __expf(a0h - mx), e1 = __expf(a1h - mx);
    float inv = 1.f / (e0 + e1);
    float w0 = e0 * inv, w1 = e1 * inv;

    float vals[8];
    float sum = 0.f;
#pragma unroll
    for (int k = 0; k < 8; k++) {
        int c = k * 32 + lane;
        float x0 = agg0[(long)v * 256 + c] + b1[c];
        x0 = (x0 > 0.f) ? x0 : (__expf(x0) - 1.f);
        float x1 = agg1[(long)v * 256 + c] + b1[256 + c];
        x1 = (x1 > 0.f) ? x1 : (__expf(x1) - 1.f);
        float val = w0 * x0 + w1 * x1 + skb[(long)v * 256 + c] + skip_b[c];
        vals[k] = val;
        sum += val;
    }
    sum = wredsum(sum);
    float mu = sum * (1.f / 256.f);
    float vs = 0.f;
#pragma unroll
    for (int k = 0; k < 8; k++) {
        float dd = vals[k] - mu;
        vs += dd * dd;
    }
    vs = wredsum(vs);
    float istd = rsqrtf(vs * (1.f / 256.f) + 1e-5f);
#pragma unroll
    for (int k = 0; k < 8; k++) {
        int c = k * 32 + lane;
        float y = (vals[k] - mu) * istd * g[c] + bt[c];
        __nv_bfloat16 hi = __float2bfloat16(y);
        fxh[(long)v * 256 + c] = hi;
        fxl[(long)v * 256 + c] = __float2bfloat16(y - __bfloat162float(hi));
    }
}

// ========== conv2 aggregate + residual + LN2 ================================
__global__ __launch_bounds__(256) void conv2_ln(const float* __restrict__ h2fw,
                                                const float* __restrict__ as2,
                                                const float* __restrict__ ad2,
                                                const int* __restrict__ off,
                                                const int* __restrict__ csr,
                                                const float* __restrict__ b2,
                                                const float* __restrict__ finalb,
                                                const float* __restrict__ g2,
                                                const float* __restrict__ bt2,
                                                float* __restrict__ out) {
    int warp = (blockIdx.x * blockDim.x + threadIdx.x) >> 5;
    int lane = threadIdx.x & 31;
    if (warp >= NN) return;
    int v = warp;
    int s0 = off[v];
    int d = off[v + 1] - s0;
    float adv = ad2[v], asv = as2[v];
    float eself = lrelu(asv + adv);
    float m = eself;
    for (int j = lane; j < d; j += 32) {
        int s = csr[s0 + j];
        m = fmaxf(m, lrelu(as2[s] + adv));
    }
    m = wredmax(m);
    float den = (lane == 0) ? __expf(eself - m) : 0.f;
    for (int j = lane; j < d; j += 32) {
        int s = csr[s0 + j];
        den += __expf(lrelu(as2[s] + adv) - m);
    }
    den = wredsum(den);
    float inv = 1.f / (den + 1e-16f);

    float al = __expf(eself - m) * inv;
    float acc0 = al * h2fw[(long)v * 128 + lane];
    float acc1 = al * h2fw[(long)v * 128 + 32 + lane];
    for (int j = 0; j < d; j++) {
        int s = csr[s0 + j];
        float a = __expf(lrelu(as2[s] + adv) - m) * inv;
        acc0 += a * h2fw[(long)s * 128 + lane];
        acc1 += a * h2fw[(long)s * 128 + 32 + lane];
    }
    int c0 = lane, c1 = lane + 32;
    acc0 += b2[c0] + h2fw[(long)v * 128 + 64 + c0] + finalb[c0];
    acc1 += b2[c1] + h2fw[(long)v * 128 + 64 + c1] + finalb[c1];
    float sum = wredsum(acc0 + acc1);
    float mu = sum * (1.f / 64.f);
    float d0 = acc0 - mu, d1 = acc1 - mu;
    float vs = wredsum(d0 * d0 + d1 * d1);
    float istd = rsqrtf(vs * (1.f / 64.f) + 1e-5f);
    out[(long)v * 64 + c0] = d0 * istd * g2[c0] + bt2[c0];
    out[(long)v * 64 + c1] = d1 * istd * g2[c1] + bt2[c1];
}

__global__ void write_w(const float* __restrict__ ha, float* __restrict__ out) {
    if (threadIdx.x == 0) {
        float a0 = ha[0], a1 = ha[1];
        float mx = fmaxf(a0, a1);
        float e0 = __expf(a0 - mx), e1 = __expf(a1 - mx);
        float inv = 1.f / (e0 + e1);
        out[NN * 64 + 0] = e0 * inv;
        out[NN * 64 + 1] = e1 * inv;
    }
}

// ================= launch ===================================================
extern "C" void kernel_launch(void* const* d_in, const int* in_sizes, int n_in,
                              void* d_out, int out_size) {
    const float* x = (const float*)d_in[0];
    const int* ei = (const int*)d_in[1];
    const int* ei2 = (const int*)d_in[2];
    const float* W1 = (const float*)d_in[3];
    const float* att_src1 = (const float*)d_in[4];
    const float* att_dst1 = (const float*)d_in[5];
    const float* b1 = (const float*)d_in[6];
    const float* W2 = (const float*)d_in[7];
    const float* att_src2 = (const float*)d_in[8];
    const float* att_dst2 = (const float*)d_in[9];
    const float* b2 = (const float*)d_in[10];
    const float* ha = (const float*)d_in[11];
    const float* skipW = (const float*)d_in[12];
    const float* skipb = (const float*)d_in[13];
    const float* finalW = (const float*)d_in[14];
    const float* finalb = (const float*)d_in[15];
    const float* ln1g = (const float*)d_in[16];
    const float* ln1b = (const float*)d_in[17];
    const float* ln2g = (const float*)d_in[18];
    const float* ln2b = (const float*)d_in[19];
    float* out = (float*)d_out;

    GS* g = nullptr;
    cudaGetSymbolAddress((void**)&g, gs);

    const int GSMEM = 2 * 40960;  // 80 KB double-buffered
    cudaFuncSetAttribute(hmma_gemm, cudaFuncAttributeMaxDynamicSharedMemorySize, GSMEM);

    const int TB = 256;
    int eb = (EE + TB - 1) / TB;
    int nb = (NN + TB - 1) / TB;
    int wb = (NN + 7) / 8;

    // operand prep
    split_x<<<(NN * 256 + TB - 1) / TB, TB>>>(x, g->xh, g->xl, NN * 256);
    pack_B1<<<(768 * 256 + TB - 1) / TB, TB>>>(W1, skipW, g->B1h, g->B1l);
    pack_B2<<<(128 * 256 + TB - 1) / TB, TB>>>(W2, finalW, g->B2h, g->B2l);

    // GEMM1: x @ [W1_0 | W1_1 | skip_W] -> h0, h1, skb (separate buffers)
    {
        dim3 grid(6, (NN + 127) / 128);
        hmma_gemm<<<grid, 256, GSMEM>>>(g->xh, g->xl, g->B1h, g->B1l,
                                        g->h0, g->h1, g->skb, NN, 256);
    }

    // CSR build
    zero_int<<<nb, TB>>>(g->deg0, NN);
    zero_int<<<nb, TB>>>(g->deg1, NN);
    hist_kernel<<<eb, TB>>>(ei + EE, g->deg0);
    hist_kernel<<<eb, TB>>>(ei2 + EE, g->deg1);
    scan_kernel<<<1, 1024>>>(g->deg0, g->off0);
    scan_kernel<<<1, 1024>>>(g->deg1, g->off1);
    copy_int<<<nb, TB>>>(g->off0, g->cur0, NN);
    copy_int<<<nb, TB>>>(g->off1, g->cur1, NN);
    scatter_kernel<<<eb, TB>>>(ei, ei + EE, g->cur0, g->csr0);
    scatter_kernel<<<eb, TB>>>(ei2, ei2 + EE, g->cur1, g->csr1);

    // logits per hop
    logits8<<<(NN * 8 + TB - 1) / TB, TB>>>(g->h0, att_src1, att_dst1, g->as0, g->ad0);
    logits8<<<(NN * 8 + TB - 1) / TB, TB>>>(g->h1, att_src1 + 256, att_dst1 + 256,
                                            g->as1, g->ad1);

    // GAT aggregation per hop (h0 then h1: each 51MB, L2-resident)
    gat_agg8<<<wb, TB>>>(g->h0, g->as0, g->ad0, g->off0, g->csr0, g->agg0);
    gat_agg8<<<wb, TB>>>(g->h1, g->as1, g->ad1, g->off1, g->csr1, g->agg1);

    // combine + skip + LN1 -> bf16 split
    combine_ln<<<wb, TB>>>(g->agg0, g->agg1, g->skb, b1, skipb, ha, ln1g, ln1b, g->fxh, g->fxl);

    // GEMM2: first @ [W2 | final_W] -> h2fw
    {
        dim3 grid(1, (NN + 127) / 128);
        hmma_gemm<<<grid, 256, GSMEM>>>(g->fxh, g->fxl, g->B2h, g->B2l,
                                        g->h2fw, nullptr, nullptr, NN, 128);
    }

    logits1<<<nb, TB>>>(g->h2fw, att_src2, att_dst2, g->as2, g->ad2);
    conv2_ln<<<wb, TB>>>(g->h2fw, g->as2, g->ad2, g->off0, g->csr0, b2, finalb, ln2g, ln2b, out);
    write_w<<<1, 32>>>(ha, out);
}

// round 5
// speedup vs baseline: 1.5751x; 1.0636x over previous
#include <cuda_runtime.h>
#include <cuda_bf16.h>
#include <math.h>
#include <stdint.h>

#define NN 50000
#define EE 800000
#define CAP 96

// ================= scratch ==================================================
struct GS {
    float h0[(size_t)NN * 256];
    float h1[(size_t)NN * 256];
    float skb[(size_t)NN * 256];
    float agg0[(size_t)NN * 256];
    float agg1[(size_t)NN * 256];
    float h2fw[(size_t)NN * 128];     // [h2 | fw] per row
    float as0[NN * 8], ad0[NN * 8], as1[NN * 8], ad1[NN * 8];
    float as2[NN], ad2[NN];
    __nv_bfloat16 xh[(size_t)NN * 256], xl[(size_t)NN * 256];
    __nv_bfloat16 fxh[(size_t)NN * 256], fxl[(size_t)NN * 256];
    __nv_bfloat16 B1h[768 * 256], B1l[768 * 256];
    __nv_bfloat16 B2h[128 * 256], B2l[128 * 256];
    int deg0[NN], deg1[NN];
    int off0[NN + 1], off1[NN + 1];
    int cur0[NN], cur1[NN];
    int csr0[EE], csr1[EE];
};
__device__ GS gs;

// ================= helpers ==================================================
__device__ __forceinline__ float wredsum(float v) {
#pragma unroll
    for (int o = 16; o; o >>= 1) v += __shfl_xor_sync(0xffffffffu, v, o);
    return v;
}
__device__ __forceinline__ float wredmax(float v) {
#pragma unroll
    for (int o = 16; o; o >>= 1) v = fmaxf(v, __shfl_xor_sync(0xffffffffu, v, o));
    return v;
}
__device__ __forceinline__ float lrelu(float x) { return fmaxf(x, 0.2f * x); }
__device__ __forceinline__ uint32_t smem_u32(const void* p) {
    uint32_t a;
    asm("{ .reg .u64 t; cvta.to.shared.u64 t, %1; cvt.u32.u64 %0, t; }" : "=r"(a) : "l"(p));
    return a;
}
__device__ __forceinline__ void cp16(uint32_t dst, const void* src, bool v) {
    int bytes = v ? 16 : 0;
    asm volatile("cp.async.cg.shared.global [%0], [%1], 16, %2;\n"
                 :: "r"(dst), "l"(src), "r"(bytes));
}
__device__ __forceinline__ void ldsm4(uint32_t* r, uint32_t addr) {
    asm volatile("ldmatrix.sync.aligned.m8n8.x4.shared.b16 {%0,%1,%2,%3}, [%4];\n"
                 : "=r"(r[0]), "=r"(r[1]), "=r"(r[2]), "=r"(r[3]) : "r"(addr));
}
__device__ __forceinline__ void mma_bf16(float* d, const uint32_t* a, uint32_t b0, uint32_t b1) {
    asm volatile(
        "mma.sync.aligned.m16n8k16.row.col.f32.bf16.bf16.f32 "
        "{%0,%1,%2,%3}, {%4,%5,%6,%7}, {%8,%9}, {%0,%1,%2,%3};\n"
        : "+f"(d[0]), "+f"(d[1]), "+f"(d[2]), "+f"(d[3])
        : "r"(a[0]), "r"(a[1]), "r"(a[2]), "r"(a[3]), "r"(b0), "r"(b1));
}

// ================= CSR build ================================================
__global__ void zero_int(int* p, int n) {
    int i = blockIdx.x * blockDim.x + threadIdx.x;
    if (i < n) p[i] = 0;
}
__global__ void hist_kernel(const int* __restrict__ dst, int* __restrict__ deg) {
    int i = blockIdx.x * blockDim.x + threadIdx.x;
    if (i < EE) atomicAdd(&deg[dst[i]], 1);
}
__global__ void scan_kernel(const int* __restrict__ deg, int* __restrict__ off) {
    __shared__ int sh[1024];
    const int n = NN;
    int t = threadIdx.x;
    int chunk = (n + 1023) >> 10;
    int s = t * chunk;
    int e = min(s + chunk, n);
    int sum = 0;
    for (int i = s; i < e; i++) sum += deg[i];
    sh[t] = sum;
    __syncthreads();
#pragma unroll
    for (int o = 1; o < 1024; o <<= 1) {
        int val = (t >= o) ? sh[t - o] : 0;
        __syncthreads();
        sh[t] += val;
        __syncthreads();
    }
    int run = sh[t] - sum;
    for (int i = s; i < e; i++) { off[i] = run; run += deg[i]; }
    if (t == 1023) off[n] = sh[1023];
}
__global__ void copy_int(const int* __restrict__ src, int* __restrict__ dst, int n) {
    int i = blockIdx.x * blockDim.x + threadIdx.x;
    if (i < n) dst[i] = src[i];
}
__global__ void scatter_kernel(const int* __restrict__ esrc, const int* __restrict__ edst,
                               int* __restrict__ cur, int* __restrict__ csr) {
    int i = blockIdx.x * blockDim.x + threadIdx.x;
    if (i < EE) {
        int d = edst[i];
        int p = atomicAdd(&cur[d], 1);
        csr[p] = esrc[i];
    }
}

// ================= operand packing ==========================================
__global__ void split_x(const float* __restrict__ x, __nv_bfloat16* __restrict__ xh,
                        __nv_bfloat16* __restrict__ xl, int n) {
    int i = blockIdx.x * blockDim.x + threadIdx.x;
    if (i >= n) return;
    float v = x[i];
    __nv_bfloat16 h = __float2bfloat16(v);
    xh[i] = h;
    xl[i] = __float2bfloat16(v - __bfloat162float(h));
}
__global__ void pack_B1(const float* __restrict__ W1, const float* __restrict__ skipW,
                        __nv_bfloat16* __restrict__ Bh, __nv_bfloat16* __restrict__ Bl) {
    int i = blockIdx.x * blockDim.x + threadIdx.x;
    if (i >= 768 * 256) return;
    int n = i / 256, k = i % 256;
    float v;
    if (n < 256) v = W1[k * 256 + n];
    else if (n < 512) v = W1[65536 + k * 256 + (n - 256)];
    else v = skipW[k * 256 + (n - 512)];
    __nv_bfloat16 h = __float2bfloat16(v);
    Bh[i] = h;
    Bl[i] = __float2bfloat16(v - __bfloat162float(h));
}
__global__ void pack_B2(const float* __restrict__ W2, const float* __restrict__ finalW,
                        __nv_bfloat16* __restrict__ Bh, __nv_bfloat16* __restrict__ Bl) {
    int i = blockIdx.x * blockDim.x + threadIdx.x;
    if (i >= 128 * 256) return;
    int n = i / 256, k = i % 256;
    float v = (n < 64) ? W2[k * 64 + n] : finalW[k * 64 + (n - 64)];
    __nv_bfloat16 h = __float2bfloat16(v);
    Bh[i] = h;
    Bl[i] = __float2bfloat16(v - __bfloat162float(h));
}

// ====== HMMA GEMM: C[M,*] = A[M,256] @ B[*,256]^T (bf16 2-split) ============
__global__ __launch_bounds__(256, 2) void hmma_gemm(
    const __nv_bfloat16* __restrict__ Ah, const __nv_bfloat16* __restrict__ Al,
    const __nv_bfloat16* __restrict__ Bh, const __nv_bfloat16* __restrict__ Bl,
    float* __restrict__ C0, float* __restrict__ C1, float* __restrict__ C2,
    int M, int split) {
    extern __shared__ char sm[];
    const int tid = threadIdx.x, lane = tid & 31, warp = tid >> 5;
    const int wm = warp & 1, wn = warp >> 1;
    const int m0 = blockIdx.y * 128, n0 = blockIdx.x * 128;
    uint32_t sbase = smem_u32(sm);

    float acc[4][4][4];
#pragma unroll
    for (int a = 0; a < 4; a++)
#pragma unroll
        for (int b = 0; b < 4; b++)
#pragma unroll
            for (int q = 0; q < 4; q++) acc[a][b][q] = 0.f;

#define LOAD_STAGE(c, s)                                                          \
    do {                                                                          \
        uint32_t sb_ = sbase + (s) * 40960;                                       \
        _Pragma("unroll") for (int it = 0; it < 2; it++) {                        \
            int idx = tid + it * 256;                                             \
            int row = idx >> 2, kc = idx & 3;                                     \
            uint32_t so = row * 80 + kc * 16;                                     \
            bool va = (m0 + row) < M;                                             \
            long ga = (long)(m0 + row) * 256 + (c) * 32 + kc * 8;                 \
            if (!va) ga = 0;                                                      \
            cp16(sb_ + so, Ah + ga, va);                                          \
            cp16(sb_ + 10240 + so, Al + ga, va);                                  \
            long gb = (long)(n0 + row) * 256 + (c) * 32 + kc * 8;                 \
            cp16(sb_ + 20480 + so, Bh + gb, true);                                \
            cp16(sb_ + 30720 + so, Bl + gb, true);                                \
        }                                                                         \
        asm volatile("cp.async.commit_group;\n" ::: "memory");                    \
    } while (0)

    LOAD_STAGE(0, 0);
    for (int c = 0; c < 8; c++) {
        if (c < 7) {
            LOAD_STAGE(c + 1, (c + 1) & 1);
            asm volatile("cp.async.wait_group 1;\n" ::: "memory");
        } else {
            asm volatile("cp.async.wait_group 0;\n" ::: "memory");
        }
        __syncthreads();
        uint32_t sb = sbase + (c & 1) * 40960;
#pragma unroll
        for (int ks = 0; ks < 2; ks++) {
            uint32_t ah[4][4], al[4][4], bhf[2][4], blf[2][4];
            int acol = ks * 16 + 8 * (lane >> 4);
            int arowl = (lane & 15);
#pragma unroll
            for (int mf = 0; mf < 4; mf++) {
                int arow = wm * 64 + mf * 16 + arowl;
                uint32_t ad = sb + arow * 80 + acol * 2;
                ldsm4(ah[mf], ad);
                ldsm4(al[mf], ad + 10240);
            }
            int bcol = ks * 16 + 8 * ((lane >> 3) & 1);
            int browl = (lane & 7) + 8 * (lane >> 4);
#pragma unroll
            for (int p = 0; p < 2; p++) {
                int brow = wn * 32 + p * 16 + browl;
                uint32_t bd = sb + 20480 + brow * 80 + bcol * 2;
                ldsm4(bhf[p], bd);
                ldsm4(blf[p], bd + 10240);
            }
#pragma unroll
            for (int mf = 0; mf < 4; mf++)
#pragma unroll
                for (int p = 0; p < 2; p++)
#pragma unroll
                    for (int sub = 0; sub < 2; sub++) {
                        int nf = p * 2 + sub;
                        uint32_t h0 = bhf[p][sub * 2], h1 = bhf[p][sub * 2 + 1];
                        uint32_t l0 = blf[p][sub * 2], l1 = blf[p][sub * 2 + 1];
                        mma_bf16(acc[mf][nf], ah[mf], h0, h1);
                        mma_bf16(acc[mf][nf], ah[mf], l0, l1);
                        mma_bf16(acc[mf][nf], al[mf], h0, h1);
                    }
        }
        __syncthreads();
    }
#undef LOAD_STAGE

    int bucket = n0 / split;
    float* C = (bucket == 0) ? C0 : ((bucket == 1) ? C1 : C2);
    int cb = n0 - bucket * split;
    int group = lane >> 2, q = lane & 3;
#pragma unroll
    for (int mf = 0; mf < 4; mf++) {
        int r0 = m0 + wm * 64 + mf * 16 + group;
#pragma unroll
        for (int nf = 0; nf < 4; nf++) {
            int col = cb + wn * 32 + nf * 8 + q * 2;
            if (r0 < M)
                *(float2*)(C + (long)r0 * split + col) =
                    make_float2(acc[mf][nf][0], acc[mf][nf][1]);
            if (r0 + 8 < M)
                *(float2*)(C + (long)(r0 + 8) * split + col) =
                    make_float2(acc[mf][nf][2], acc[mf][nf][3]);
        }
    }
}

// ================= attention logits =========================================
__global__ void logits8(const float* __restrict__ h, const float* __restrict__ a_src,
                        const float* __restrict__ a_dst, float* __restrict__ as,
                        float* __restrict__ ad) {
    int t = blockIdx.x * blockDim.x + threadIdx.x;
    if (t >= NN * 8) return;
    int v = t >> 3, k = t & 7;
    const float* hr = h + (long)v * 256 + k * 32;
    const float* sv = a_src + k * 32;
    const float* dv = a_dst + k * 32;
    float s = 0.f, d = 0.f;
#pragma unroll
    for (int c = 0; c < 32; c++) {
        float hv = hr[c];
        s += hv * sv[c];
        d += hv * dv[c];
    }
    as[t] = s;
    ad[t] = d;
}
__global__ void logits1(const float* __restrict__ h2, const float* __restrict__ a_src,
                        const float* __restrict__ a_dst, float* __restrict__ as,
                        float* __restrict__ ad) {
    int v = blockIdx.x * blockDim.x + threadIdx.x;
    if (v >= NN) return;
    const float* hr = h2 + (long)v * 128;
    float s = 0.f, d = 0.f;
#pragma unroll
    for (int c = 0; c < 64; c++) {
        float hv = hr[c];
        s += hv * a_src[c];
        d += hv * a_dst[c];
    }
    as[v] = s;
    ad[v] = d;
}

// ====== GAT aggregation (8 heads, warp per dst, smem-staged alphas) =========
__global__ __launch_bounds__(256) void gat_agg8(const float* __restrict__ h,
                                                const float* __restrict__ as,
                                                const float* __restrict__ ad,
                                                const int* __restrict__ off,
                                                const int* __restrict__ csr,
                                                float* __restrict__ out) {
    __shared__ float sal[8][CAP * 8];
    int gwarp = (blockIdx.x * blockDim.x + threadIdx.x) >> 5;
    int lane = threadIdx.x & 31;
    if (gwarp >= NN) return;
    int v = gwarp;
    float* sm = sal[threadIdx.x >> 5];
    int s0 = off[v];
    int d = off[v + 1] - s0;
    float adv[8], asv[8];
#pragma unroll
    for (int k = 0; k < 8; k++) { adv[k] = ad[v * 8 + k]; asv[k] = as[v * 8 + k]; }

    float m[8];
#pragma unroll
    for (int k = 0; k < 8; k++) m[k] = lrelu(asv[k] + adv[k]);

    float acc[8];

    if (d <= CAP) {
        // pass A: raw logits -> smem, running max
        for (int j = lane; j < d; j += 32) {
            int s = csr[s0 + j];
            const float4* ap = (const float4*)(as + s * 8);
            float4 a0 = ap[0], a1 = ap[1];
            float ev[8] = {a0.x, a0.y, a0.z, a0.w, a1.x, a1.y, a1.z, a1.w};
#pragma unroll
            for (int k = 0; k < 8; k++) {
                float e = lrelu(ev[k] + adv[k]);
                sm[j * 8 + k] = e;
                m[k] = fmaxf(m[k], e);
            }
        }
#pragma unroll
        for (int k = 0; k < 8; k++) m[k] = wredmax(m[k]);

        // pass B: exp in place + denom
        float den[8];
#pragma unroll
        for (int k = 0; k < 8; k++)
            den[k] = (lane == 0) ? __expf(lrelu(asv[k] + adv[k]) - m[k]) : 0.f;
        for (int j = lane; j < d; j += 32) {
#pragma unroll
            for (int k = 0; k < 8; k++) {
                float e = __expf(sm[j * 8 + k] - m[k]);
                sm[j * 8 + k] = e;
                den[k] += e;
            }
        }
#pragma unroll
        for (int k = 0; k < 8; k++) {
            den[k] = wredsum(den[k]);
            den[k] = 1.f / (den[k] + 1e-16f);
        }
        __syncwarp();

        // pass C: aggregate (no exp; smem broadcast alphas)
#pragma unroll
        for (int k = 0; k < 8; k++) {
            float al = __expf(lrelu(asv[k] + adv[k]) - m[k]) * den[k];
            acc[k] = al * h[(long)v * 256 + k * 32 + lane];
        }
        int j = 0;
        for (; j + 2 <= d; j += 2) {
            int sA = csr[s0 + j], sB = csr[s0 + j + 1];
            const float* hA = h + (long)sA * 256 + lane;
            const float* hB = h + (long)sB * 256 + lane;
#pragma unroll
            for (int k = 0; k < 8; k++) {
                float aA = sm[j * 8 + k] * den[k];
                float aB = sm[(j + 1) * 8 + k] * den[k];
                acc[k] += aA * hA[k * 32];
                acc[k] += aB * hB[k * 32];
            }
        }
        if (j < d) {
            int s = csr[s0 + j];
            const float* hp = h + (long)s * 256 + lane;
#pragma unroll
            for (int k = 0; k < 8; k++) acc[k] += sm[j * 8 + k] * den[k] * hp[k * 32];
        }
    } else {
        // fallback: original 3-pass recompute (d > CAP, ~never)
        for (int j = lane; j < d; j += 32) {
            int s = csr[s0 + j];
#pragma unroll
            for (int k = 0; k < 8; k++) m[k] = fmaxf(m[k], lrelu(as[s * 8 + k] + adv[k]));
        }
#pragma unroll
        for (int k = 0; k < 8; k++) m[k] = wredmax(m[k]);
        float den[8];
#pragma unroll
        for (int k = 0; k < 8; k++)
            den[k] = (lane == 0) ? __expf(lrelu(asv[k] + adv[k]) - m[k]) : 0.f;
        for (int j = lane; j < d; j += 32) {
            int s = csr[s0 + j];
#pragma unroll
            for (int k = 0; k < 8; k++)
                den[k] += __expf(lrelu(as[s * 8 + k] + adv[k]) - m[k]);
        }
#pragma unroll
        for (int k = 0; k < 8; k++) {
            den[k] = wredsum(den[k]);
            den[k] = 1.f / (den[k] + 1e-16f);
        }
#pragma unroll
        for (int k = 0; k < 8; k++) {
            float al = __expf(lrelu(asv[k] + adv[k]) - m[k]) * den[k];
            acc[k] = al * h[(long)v * 256 + k * 32 + lane];
        }
        for (int j = 0; j < d; j++) {
            int s = csr[s0 + j];
            float al = 0.f;
            if (lane < 8)
                al = __expf(lrelu(as[s * 8 + lane] + adv[lane]) - m[lane]) * den[lane];
#pragma unroll
            for (int k = 0; k < 8; k++) {
                float a = __shfl_sync(0xffffffffu, al, k);
                acc[k] += a * h[(long)s * 256 + k * 32 + lane];
            }
        }
    }
#pragma unroll
    for (int k = 0; k < 8; k++) out[(long)v * 256 + k * 32 + lane] = acc[k];
}

// ========== hop combine + skip + LN1 -> bf16 split for GEMM2 ================
__global__ __launch_bounds__(256) void combine_ln(const float* __restrict__ agg0,
                                                  const float* __restrict__ agg1,
                                                  const float* __restrict__ skb,
                                                  const float* __restrict__ b1,
                                                  const float* __restrict__ skip_b,
                                                  const float* __restrict__ ha,
                                                  const float* __restrict__ g,
                                                  const float* __restrict__ bt,
                                                  __nv_bfloat16* __restrict__ fxh,
                                                  __nv_bfloat16* __restrict__ fxl) {
    int warp = (blockIdx.x * blockDim.x + threadIdx.x) >> 5;
    int lane = threadIdx.x & 31;
    if (warp >= NN) return;
    int v = warp;
    float a0h = ha[0], a1h = ha[1];
    float mx = fmaxf(a0h, a1h);
    float e0 = __expf(a0h - mx), e1 = __expf(a1h - mx);
    float inv = 1.f / (e0 + e1);
    float w0 = e0 * inv, w1 = e1 * inv;

    float vals[8];
    float sum = 0.f;
#pragma unroll
    for (int k = 0; k < 8; k++) {
        int c = k * 32 + lane;
        float x0 = agg0[(long)v * 256 + c] + b1[c];
        x0 = (x0 > 0.f) ? x0 : (__expf(x0) - 1.f);
        float x1 = agg1[(long)v * 256 + c] + b1[256 + c];
        x1 = (x1 > 0.f) ? x1 : (__expf(x1) - 1.f);
        float val = w0 * x0 + w1 * x1 + skb[(long)v * 256 + c] + skip_b[c];
        vals[k] = val;
        sum += val;
    }
    sum = wredsum(sum);
    float mu = sum * (1.f / 256.f);
    float vs = 0.f;
#pragma unroll
    for (int k = 0; k < 8; k++) {
        float dd = vals[k] - mu;
        vs += dd * dd;
    }
    vs = wredsum(vs);
    float istd = rsqrtf(vs * (1.f / 256.f) + 1e-5f);
#pragma unroll
    for (int k = 0; k < 8; k++) {
        int c = k * 32 + lane;
        float y = (vals[k] - mu) * istd * g[c] + bt[c];
        __nv_bfloat16 hi = __float2bfloat16(y);
        fxh[(long)v * 256 + c] = hi;
        fxl[(long)v * 256 + c] = __float2bfloat16(y - __bfloat162float(hi));
    }
}

// ========== conv2 aggregate + residual + LN2 (smem-staged alphas) ===========
__global__ __launch_bounds__(256) void conv2_ln(const float* __restrict__ h2fw,
                                                const float* __restrict__ as2,
                                                const float* __restrict__ ad2,
                                                const int* __restrict__ off,
                                                const int* __restrict__ csr,
                                                const float* __restrict__ b2,
                                                const float* __restrict__ finalb,
                                                const float* __restrict__ g2,
                                                const float* __restrict__ bt2,
                                                float* __restrict__ out) {
    __shared__ float sal[8][CAP];
    int gwarp = (blockIdx.x * blockDim.x + threadIdx.x) >> 5;
    int lane = threadIdx.x & 31;
    if (gwarp >= NN) return;
    int v = gwarp;
    float* sm = sal[threadIdx.x >> 5];
    int s0 = off[v];
    int d = off[v + 1] - s0;
    float adv = ad2[v], asv = as2[v];
    float eself = lrelu(asv + adv);
    float m = eself;
    float acc0, acc1;

    if (d <= CAP) {
        for (int j = lane; j < d; j += 32) {
            int s = csr[s0 + j];
            float e = lrelu(as2[s] + adv);
            sm[j] = e;
            m = fmaxf(m, e);
        }
        m = wredmax(m);
        float den = (lane == 0) ? __expf(eself - m) : 0.f;
        for (int j = lane; j < d; j += 32) {
            float e = __expf(sm[j] - m);
            sm[j] = e;
            den += e;
        }
        den = wredsum(den);
        float inv = 1.f / (den + 1e-16f);
        __syncwarp();

        float al = __expf(eself - m) * inv;
        acc0 = al * h2fw[(long)v * 128 + lane];
        acc1 = al * h2fw[(long)v * 128 + 32 + lane];
        int j = 0;
        for (; j + 2 <= d; j += 2) {
            int sA = csr[s0 + j], sB = csr[s0 + j + 1];
            float aA = sm[j] * inv, aB = sm[j + 1] * inv;
            const float* hA = h2fw + (long)sA * 128 + lane;
            const float* hB = h2fw + (long)sB * 128 + lane;
            acc0 += aA * hA[0];
            acc1 += aA * hA[32];
            acc0 += aB * hB[0];
            acc1 += aB * hB[32];
        }
        if (j < d) {
            int s = csr[s0 + j];
            float a = sm[j] * inv;
            acc0 += a * h2fw[(long)s * 128 + lane];
            acc1 += a * h2fw[(long)s * 128 + 32 + lane];
        }
    } else {
        for (int j = lane; j < d; j += 32) {
            int s = csr[s0 + j];
            m = fmaxf(m, lrelu(as2[s] + adv));
        }
        m = wredmax(m);
        float den = (lane == 0) ? __expf(eself - m) : 0.f;
        for (int j = lane; j < d; j += 32) {
            int s = csr[s0 + j];
            den += __expf(lrelu(as2[s] + adv) - m);
        }
        den = wredsum(den);
        float inv = 1.f / (den + 1e-16f);
        float al = __expf(eself - m) * inv;
        acc0 = al * h2fw[(long)v * 128 + lane];
        acc1 = al * h2fw[(long)v * 128 + 32 + lane];
        for (int j = 0; j < d; j++) {
            int s = csr[s0 + j];
            float a = __expf(lrelu(as2[s] + adv) - m) * inv;
            acc0 += a * h2fw[(long)s * 128 + lane];
            acc1 += a * h2fw[(long)s * 128 + 32 + lane];
        }
    }

    int c0 = lane, c1 = lane + 32;
    acc0 += b2[c0] + h2fw[(long)v * 128 + 64 + c0] + finalb[c0];
    acc1 += b2[c1] + h2fw[(long)v * 128 + 64 + c1] + finalb[c1];
    float sum = wredsum(acc0 + acc1);
    float mu = sum * (1.f / 64.f);
    float d0 = acc0 - mu, d1 = acc1 - mu;
    float vs = wredsum(d0 * d0 + d1 * d1);
    float istd = rsqrtf(vs * (1.f / 64.f) + 1e-5f);
    out[(long)v * 64 + c0] = d0 * istd * g2[c0] + bt2[c0];
    out[(long)v * 64 + c1] = d1 * istd * g2[c1] + bt2[c1];
}

__global__ void write_w(const float* __restrict__ ha, float* __restrict__ out) {
    if (threadIdx.x == 0) {
        float a0 = ha[0], a1 = ha[1];
        float mx = fmaxf(a0, a1);
        float e0 = __expf(a0 - mx), e1 = __expf(a1 - mx);
        float inv = 1.f / (e0 + e1);
        out[NN * 64 + 0] = e0 * inv;
        out[NN * 64 + 1] = e1 * inv;
    }
}

// ================= launch ===================================================
extern "C" void kernel_launch(void* const* d_in, const int* in_sizes, int n_in,
                              void* d_out, int out_size) {
    const float* x = (const float*)d_in[0];
    const int* ei = (const int*)d_in[1];
    const int* ei2 = (const int*)d_in[2];
    const float* W1 = (const float*)d_in[3];
    const float* att_src1 = (const float*)d_in[4];
    const float* att_dst1 = (const float*)d_in[5];
    const float* b1 = (const float*)d_in[6];
    const float* W2 = (const float*)d_in[7];
    const float* att_src2 = (const float*)d_in[8];
    const float* att_dst2 = (const float*)d_in[9];
    const float* b2 = (const float*)d_in[10];
    const float* ha = (const float*)d_in[11];
    const float* skipW = (const float*)d_in[12];
    const float* skipb = (const float*)d_in[13];
    const float* finalW = (const float*)d_in[14];
    const float* finalb = (const float*)d_in[15];
    const float* ln1g = (const float*)d_in[16];
    const float* ln1b = (const float*)d_in[17];
    const float* ln2g = (const float*)d_in[18];
    const float* ln2b = (const float*)d_in[19];
    float* out = (float*)d_out;

    GS* g = nullptr;
    cudaGetSymbolAddress((void**)&g, gs);

    const int GSMEM = 2 * 40960;  // 80 KB double-buffered
    cudaFuncSetAttribute(hmma_gemm, cudaFuncAttributeMaxDynamicSharedMemorySize, GSMEM);

    const int TB = 256;
    int eb = (EE + TB - 1) / TB;
    int nb = (NN + TB - 1) / TB;
    int wb = (NN + 7) / 8;

    // operand prep
    split_x<<<(NN * 256 + TB - 1) / TB, TB>>>(x, g->xh, g->xl, NN * 256);
    pack_B1<<<(768 * 256 + TB - 1) / TB, TB>>>(W1, skipW, g->B1h, g->B1l);
    pack_B2<<<(128 * 256 + TB - 1) / TB, TB>>>(W2, finalW, g->B2h, g->B2l);

    // GEMM1: x @ [W1_0 | W1_1 | skip_W] -> h0, h1, skb
    {
        dim3 grid(6, (NN + 127) / 128);
        hmma_gemm<<<grid, 256, GSMEM>>>(g->xh, g->xl, g->B1h, g->B1l,
                                        g->h0, g->h1, g->skb, NN, 256);
    }

    // CSR build
    zero_int<<<nb, TB>>>(g->deg0, NN);
    zero_int<<<nb, TB>>>(g->deg1, NN);
    hist_kernel<<<eb, TB>>>(ei + EE, g->deg0);
    hist_kernel<<<eb, TB>>>(ei2 + EE, g->deg1);
    scan_kernel<<<1, 1024>>>(g->deg0, g->off0);
    scan_kernel<<<1, 1024>>>(g->deg1, g->off1);
    copy_int<<<nb, TB>>>(g->off0, g->cur0, NN);
    copy_int<<<nb, TB>>>(g->off1, g->cur1, NN);
    scatter_kernel<<<eb, TB>>>(ei, ei + EE, g->cur0, g->csr0);
    scatter_kernel<<<eb, TB>>>(ei2, ei2 + EE, g->cur1, g->csr1);

    // logits per hop
    logits8<<<(NN * 8 + TB - 1) / TB, TB>>>(g->h0, att_src1, att_dst1, g->as0, g->ad0);
    logits8<<<(NN * 8 + TB - 1) / TB, TB>>>(g->h1, att_src1 + 256, att_dst1 + 256,
                                            g->as1, g->ad1);

    // GAT aggregation per hop
    gat_agg8<<<wb, TB>>>(g->h0, g->as0, g->ad0, g->off0, g->csr0, g->agg0);
    gat_agg8<<<wb, TB>>>(g->h1, g->as1, g->ad1, g->off1, g->csr1, g->agg1);

    // combine + skip + LN1 -> bf16 split
    combine_ln<<<wb, TB>>>(g->agg0, g->agg1, g->skb, b1, skipb, ha, ln1g, ln1b, g->fxh, g->fxl);

    // GEMM2: first @ [W2 | final_W] -> h2fw
    {
        dim3 grid(1, (NN + 127) / 128);
        hmma_gemm<<<grid, 256, GSMEM>>>(g->fxh, g->fxl, g->B2h, g->B2l,
                                        g->h2fw, nullptr, nullptr, NN, 128);
    }

    logits1<<<nb, TB>>>(g->h2fw, att_src2, att_dst2, g->as2, g->ad2);
    conv2_ln<<<wb, TB>>>(g->h2fw, g->as2, g->ad2, g->off0, g->csr0, b2, finalb, ln2g, ln2b, out);
    write_w<<<1, 32>>>(ha, out);
}

// round 6
// speedup vs baseline: 1.9806x; 1.2574x over previous
#include <cuda_runtime.h>
#include <cuda_bf16.h>
#include <cuda_fp16.h>
#include <math.h>
#include <stdint.h>

#define NN 50000
#define EE 800000
#define CAP 96

// ================= scratch ==================================================
struct GS {
    float skb[(size_t)NN * 256];
    float agg0[(size_t)NN * 256];
    float agg1[(size_t)NN * 256];
    float h2fw[(size_t)NN * 128];     // [h2 | fw] per row (fp32)
    __half h0f[(size_t)NN * 256];
    __half h1f[(size_t)NN * 256];
    __half h2f[(size_t)NN * 64];
    float as0[NN * 8], ad0[NN * 8], as1[NN * 8], ad1[NN * 8];
    float as2[NN], ad2[NN];
    __nv_bfloat16 xh[(size_t)NN * 256], xl[(size_t)NN * 256];
    __nv_bfloat16 fxh[(size_t)NN * 256], fxl[(size_t)NN * 256];
    __nv_bfloat16 B1h[768 * 256], B1l[768 * 256];
    __nv_bfloat16 B2h[128 * 256], B2l[128 * 256];
    int deg0[NN], deg1[NN];
    int off0[NN + 1], off1[NN + 1];
    int cur0[NN], cur1[NN];
    int csr0[EE], csr1[EE];
};
__device__ GS gs;

// ================= helpers ==================================================
__device__ __forceinline__ float wredsum(float v) {
#pragma unroll
    for (int o = 16; o; o >>= 1) v += __shfl_xor_sync(0xffffffffu, v, o);
    return v;
}
__device__ __forceinline__ float wredmax(float v) {
#pragma unroll
    for (int o = 16; o; o >>= 1) v = fmaxf(v, __shfl_xor_sync(0xffffffffu, v, o));
    return v;
}
__device__ __forceinline__ float lrelu(float x) { return fmaxf(x, 0.2f * x); }
__device__ __forceinline__ uint32_t smem_u32(const void* p) {
    uint32_t a;
    asm("{ .reg .u64 t; cvta.to.shared.u64 t, %1; cvt.u32.u64 %0, t; }" : "=r"(a) : "l"(p));
    return a;
}
__device__ __forceinline__ void cp16(uint32_t dst, const void* src, bool v) {
    int bytes = v ? 16 : 0;
    asm volatile("cp.async.cg.shared.global [%0], [%1], 16, %2;\n"
                 :: "r"(dst), "l"(src), "r"(bytes));
}
__device__ __forceinline__ void ldsm4(uint32_t* r, uint32_t addr) {
    asm volatile("ldmatrix.sync.aligned.m8n8.x4.shared.b16 {%0,%1,%2,%3}, [%4];\n"
                 : "=r"(r[0]), "=r"(r[1]), "=r"(r[2]), "=r"(r[3]) : "r"(addr));
}
__device__ __forceinline__ void mma_bf16(float* d, const uint32_t* a, uint32_t b0, uint32_t b1) {
    asm volatile(
        "mma.sync.aligned.m16n8k16.row.col.f32.bf16.bf16.f32 "
        "{%0,%1,%2,%3}, {%4,%5,%6,%7}, {%8,%9}, {%0,%1,%2,%3};\n"
        : "+f"(d[0]), "+f"(d[1]), "+f"(d[2]), "+f"(d[3])
        : "r"(a[0]), "r"(a[1]), "r"(a[2]), "r"(a[3]), "r"(b0), "r"(b1));
}

// ================= CSR build ================================================
__global__ void zero_int(int* p, int n) {
    int i = blockIdx.x * blockDim.x + threadIdx.x;
    if (i < n) p[i] = 0;
}
__global__ void hist_kernel(const int* __restrict__ dst, int* __restrict__ deg) {
    int i = blockIdx.x * blockDim.x + threadIdx.x;
    if (i < EE) atomicAdd(&deg[dst[i]], 1);
}
__global__ void scan_kernel(const int* __restrict__ deg, int* __restrict__ off) {
    __shared__ int sh[1024];
    const int n = NN;
    int t = threadIdx.x;
    int chunk = (n + 1023) >> 10;
    int s = t * chunk;
    int e = min(s + chunk, n);
    int sum = 0;
    for (int i = s; i < e; i++) sum += deg[i];
    sh[t] = sum;
    __syncthreads();
#pragma unroll
    for (int o = 1; o < 1024; o <<= 1) {
        int val = (t >= o) ? sh[t - o] : 0;
        __syncthreads();
        sh[t] += val;
        __syncthreads();
    }
    int run = sh[t] - sum;
    for (int i = s; i < e; i++) { off[i] = run; run += deg[i]; }
    if (t == 1023) off[n] = sh[1023];
}
__global__ void copy_int(const int* __restrict__ src, int* __restrict__ dst, int n) {
    int i = blockIdx.x * blockDim.x + threadIdx.x;
    if (i < n) dst[i] = src[i];
}
__global__ void scatter_kernel(const int* __restrict__ esrc, const int* __restrict__ edst,
                               int* __restrict__ cur, int* __restrict__ csr) {
    int i = blockIdx.x * blockDim.x + threadIdx.x;
    if (i < EE) {
        int d = edst[i];
        int p = atomicAdd(&cur[d], 1);
        csr[p] = esrc[i];
    }
}

// ================= operand packing ==========================================
__global__ void split_x(const float* __restrict__ x, __nv_bfloat16* __restrict__ xh,
                        __nv_bfloat16* __restrict__ xl, int n) {
    int i = blockIdx.x * blockDim.x + threadIdx.x;
    if (i >= n) return;
    float v = x[i];
    __nv_bfloat16 h = __float2bfloat16(v);
    xh[i] = h;
    xl[i] = __float2bfloat16(v - __bfloat162float(h));
}
__global__ void pack_B1(const float* __restrict__ W1, const float* __restrict__ skipW,
                        __nv_bfloat16* __restrict__ Bh, __nv_bfloat16* __restrict__ Bl) {
    int i = blockIdx.x * blockDim.x + threadIdx.x;
    if (i >= 768 * 256) return;
    int n = i / 256, k = i % 256;
    float v;
    if (n < 256) v = W1[k * 256 + n];
    else if (n < 512) v = W1[65536 + k * 256 + (n - 256)];
    else v = skipW[k * 256 + (n - 512)];
    __nv_bfloat16 h = __float2bfloat16(v);
    Bh[i] = h;
    Bl[i] = __float2bfloat16(v - __bfloat162float(h));
}
__global__ void pack_B2(const float* __restrict__ W2, const float* __restrict__ finalW,
                        __nv_bfloat16* __restrict__ Bh, __nv_bfloat16* __restrict__ Bl) {
    int i = blockIdx.x * blockDim.x + threadIdx.x;
    if (i >= 128 * 256) return;
    int n = i / 256, k = i % 256;
    float v = (n < 64) ? W2[k * 64 + n] : finalW[k * 64 + (n - 64)];
    __nv_bfloat16 h = __float2bfloat16(v);
    Bh[i] = h;
    Bl[i] = __float2bfloat16(v - __bfloat162float(h));
}

// ====== HMMA GEMM: C = A[M,256] @ B[*,256]^T; buckets 0/1 -> fp16 ==========
__global__ __launch_bounds__(256, 2) void hmma_gemm(
    const __nv_bfloat16* __restrict__ Ah, const __nv_bfloat16* __restrict__ Al,
    const __nv_bfloat16* __restrict__ Bh, const __nv_bfloat16* __restrict__ Bl,
    __half* __restrict__ H0, __half* __restrict__ H1, float* __restrict__ C2,
    int M, int split) {
    extern __shared__ char sm[];
    const int tid = threadIdx.x, lane = tid & 31, warp = tid >> 5;
    const int wm = warp & 1, wn = warp >> 1;
    const int m0 = blockIdx.y * 128, n0 = blockIdx.x * 128;
    uint32_t sbase = smem_u32(sm);

    float acc[4][4][4];
#pragma unroll
    for (int a = 0; a < 4; a++)
#pragma unroll
        for (int b = 0; b < 4; b++)
#pragma unroll
            for (int q = 0; q < 4; q++) acc[a][b][q] = 0.f;

#define LOAD_STAGE(c, s)                                                          \
    do {                                                                          \
        uint32_t sb_ = sbase + (s) * 40960;                                       \
        _Pragma("unroll") for (int it = 0; it < 2; it++) {                        \
            int idx = tid + it * 256;                                             \
            int row = idx >> 2, kc = idx & 3;                                     \
            uint32_t so = row * 80 + kc * 16;                                     \
            bool va = (m0 + row) < M;                                             \
            long ga = (long)(m0 + row) * 256 + (c) * 32 + kc * 8;                 \
            if (!va) ga = 0;                                                      \
            cp16(sb_ + so, Ah + ga, va);                                          \
            cp16(sb_ + 10240 + so, Al + ga, va);                                  \
            long gb = (long)(n0 + row) * 256 + (c) * 32 + kc * 8;                 \
            cp16(sb_ + 20480 + so, Bh + gb, true);                                \
            cp16(sb_ + 30720 + so, Bl + gb, true);                                \
        }                                                                         \
        asm volatile("cp.async.commit_group;\n" ::: "memory");                    \
    } while (0)

    LOAD_STAGE(0, 0);
    for (int c = 0; c < 8; c++) {
        if (c < 7) {
            LOAD_STAGE(c + 1, (c + 1) & 1);
            asm volatile("cp.async.wait_group 1;\n" ::: "memory");
        } else {
            asm volatile("cp.async.wait_group 0;\n" ::: "memory");
        }
        __syncthreads();
        uint32_t sb = sbase + (c & 1) * 40960;
#pragma unroll
        for (int ks = 0; ks < 2; ks++) {
            uint32_t ah[4][4], al[4][4], bhf[2][4], blf[2][4];
            int acol = ks * 16 + 8 * (lane >> 4);
            int arowl = (lane & 15);
#pragma unroll
            for (int mf = 0; mf < 4; mf++) {
                int arow = wm * 64 + mf * 16 + arowl;
                uint32_t ad = sb + arow * 80 + acol * 2;
                ldsm4(ah[mf], ad);
                ldsm4(al[mf], ad + 10240);
            }
            int bcol = ks * 16 + 8 * ((lane >> 3) & 1);
            int browl = (lane & 7) + 8 * (lane >> 4);
#pragma unroll
            for (int p = 0; p < 2; p++) {
                int brow = wn * 32 + p * 16 + browl;
                uint32_t bd = sb + 20480 + brow * 80 + bcol * 2;
                ldsm4(bhf[p], bd);
                ldsm4(blf[p], bd + 10240);
            }
#pragma unroll
            for (int mf = 0; mf < 4; mf++)
#pragma unroll
                for (int p = 0; p < 2; p++)
#pragma unroll
                    for (int sub = 0; sub < 2; sub++) {
                        int nf = p * 2 + sub;
                        uint32_t h0 = bhf[p][sub * 2], h1 = bhf[p][sub * 2 + 1];
                        uint32_t l0 = blf[p][sub * 2], l1 = blf[p][sub * 2 + 1];
                        mma_bf16(acc[mf][nf], ah[mf], h0, h1);
                        mma_bf16(acc[mf][nf], ah[mf], l0, l1);
                        mma_bf16(acc[mf][nf], al[mf], h0, h1);
                    }
        }
        __syncthreads();
    }
#undef LOAD_STAGE

    int bucket = n0 / split;
    int cb = n0 - bucket * split;
    int group = lane >> 2, q = lane & 3;
    bool half_path = (H0 != nullptr) && (bucket < 2);
    __half* H = (bucket == 0) ? H0 : H1;
#pragma unroll
    for (int mf = 0; mf < 4; mf++) {
        int r0 = m0 + wm * 64 + mf * 16 + group;
#pragma unroll
        for (int nf = 0; nf < 4; nf++) {
            int col = cb + wn * 32 + nf * 8 + q * 2;
            if (half_path) {
                if (r0 < M)
                    ((__half2*)H)[(long)r0 * (split / 2) + col / 2] =
                        __floats2half2_rn(acc[mf][nf][0], acc[mf][nf][1]);
                if (r0 + 8 < M)
                    ((__half2*)H)[(long)(r0 + 8) * (split / 2) + col / 2] =
                        __floats2half2_rn(acc[mf][nf][2], acc[mf][nf][3]);
            } else {
                if (r0 < M)
                    *(float2*)(C2 + (long)r0 * split + col) =
                        make_float2(acc[mf][nf][0], acc[mf][nf][1]);
                if (r0 + 8 < M)
                    *(float2*)(C2 + (long)(r0 + 8) * split + col) =
                        make_float2(acc[mf][nf][2], acc[mf][nf][3]);
            }
        }
    }
}

// ================= attention logits (fp16 features) =========================
__global__ void logits8(const __half2* __restrict__ h, const float* __restrict__ a_src,
                        const float* __restrict__ a_dst, float* __restrict__ as,
                        float* __restrict__ ad) {
    int t = blockIdx.x * blockDim.x + threadIdx.x;
    if (t >= NN * 8) return;
    int v = t >> 3, k = t & 7;
    const __half2* hr = h + (long)v * 128 + k * 16;
    const float* sv = a_src + k * 32;
    const float* dv = a_dst + k * 32;
    float s = 0.f, d = 0.f;
#pragma unroll
    for (int c = 0; c < 16; c++) {
        float2 hv = __half22float2(hr[c]);
        s += hv.x * sv[2 * c] + hv.y * sv[2 * c + 1];
        d += hv.x * dv[2 * c] + hv.y * dv[2 * c + 1];
    }
    as[t] = s;
    ad[t] = d;
}
__global__ void logits1(const __half2* __restrict__ h2, const float* __restrict__ a_src,
                        const float* __restrict__ a_dst, float* __restrict__ as,
                        float* __restrict__ ad) {
    int v = blockIdx.x * blockDim.x + threadIdx.x;
    if (v >= NN) return;
    const __half2* hr = h2 + (long)v * 32;
    float s = 0.f, d = 0.f;
#pragma unroll
    for (int c = 0; c < 32; c++) {
        float2 hv = __half22float2(hr[c]);
        s += hv.x * a_src[2 * c] + hv.y * a_src[2 * c + 1];
        d += hv.x * a_dst[2 * c] + hv.y * a_dst[2 * c + 1];
    }
    as[v] = s;
    ad[v] = d;
}

// ====== GAT aggregation: 8 heads, warp/dst, fp16 features, smem alphas ======
__global__ __launch_bounds__(256) void gat_agg8(const __half2* __restrict__ h,
                                                const float* __restrict__ as,
                                                const float* __restrict__ ad,
                                                const int* __restrict__ off,
                                                const int* __restrict__ csr,
                                                float* __restrict__ out) {
    __shared__ float sal[8][8 * CAP];
    int gwarp = (blockIdx.x * blockDim.x + threadIdx.x) >> 5;
    int lane = threadIdx.x & 31;
    if (gwarp >= NN) return;
    int v = gwarp;
    float* sm = sal[threadIdx.x >> 5];
    int s0 = off[v];
    int d = off[v + 1] - s0;
    int hi = lane >> 4;  // which of the pair of heads this lane's channels use
    float adv[8], asv[8];
#pragma unroll
    for (int k = 0; k < 8; k++) { adv[k] = ad[v * 8 + k]; asv[k] = as[v * 8 + k]; }

    float m[8];
#pragma unroll
    for (int k = 0; k < 8; k++) m[k] = lrelu(asv[k] + adv[k]);

    float2 acc[4];

    if (d <= CAP) {
        // pass A: raw logits -> smem [head][j], running max
        for (int j = lane; j < d; j += 32) {
            int s = csr[s0 + j];
            float4 a0 = *(const float4*)(as + s * 8);
            float4 a1 = *(const float4*)(as + s * 8 + 4);
            float ev[8] = {a0.x, a0.y, a0.z, a0.w, a1.x, a1.y, a1.z, a1.w};
#pragma unroll
            for (int k = 0; k < 8; k++) {
                float e = lrelu(ev[k] + adv[k]);
                sm[k * CAP + j] = e;
                m[k] = fmaxf(m[k], e);
            }
        }
#pragma unroll
        for (int k = 0; k < 8; k++) m[k] = wredmax(m[k]);

        // pass B: exp in place + denom
        float den[8];
#pragma unroll
        for (int k = 0; k < 8; k++)
            den[k] = (lane == 0) ? __expf(lrelu(asv[k] + adv[k]) - m[k]) : 0.f;
        for (int j = lane; j < d; j += 32) {
#pragma unroll
            for (int k = 0; k < 8; k++) {
                float e = __expf(sm[k * CAP + j] - m[k]);
                sm[k * CAP + j] = e;
                den[k] += e;
            }
        }
#pragma unroll
        for (int k = 0; k < 8; k++) {
            den[k] = wredsum(den[k]);
            den[k] = 1.f / (den[k] + 1e-16f);
        }
        __syncwarp();

        // per-lane head selection (registers, compile-time indices)
        float msel[4], dsel[4], esel[4];
#pragma unroll
        for (int k = 0; k < 4; k++) {
            msel[k] = hi ? m[2 * k + 1] : m[2 * k];
            dsel[k] = hi ? den[2 * k + 1] : den[2 * k];
            float sl = hi ? (asv[2 * k + 1] + adv[2 * k + 1]) : (asv[2 * k] + adv[2 * k]);
            esel[k] = __expf(lrelu(sl) - msel[k]) * dsel[k];
        }

        // pass C: aggregate (fp16 gathers, 4 LDG per edge, unroll 4)
        const __half2* hv = h + (long)v * 128 + lane;
#pragma unroll
        for (int k = 0; k < 4; k++) {
            float2 x = __half22float2(hv[k * 32]);
            acc[k] = make_float2(esel[k] * x.x, esel[k] * x.y);
        }
        int j = 0;
        for (; j + 4 <= d; j += 4) {
            int sA = csr[s0 + j], sB = csr[s0 + j + 1];
            int sC = csr[s0 + j + 2], sD = csr[s0 + j + 3];
            const __half2* pA = h + (long)sA * 128 + lane;
            const __half2* pB = h + (long)sB * 128 + lane;
            const __half2* pC = h + (long)sC * 128 + lane;
            const __half2* pD = h + (long)sD * 128 + lane;
#pragma unroll
            for (int k = 0; k < 4; k++) {
                int hk = 2 * k + hi;
                float aA = sm[hk * CAP + j] * dsel[k];
                float aB = sm[hk * CAP + j + 1] * dsel[k];
                float aC = sm[hk * CAP + j + 2] * dsel[k];
                float aD = sm[hk * CAP + j + 3] * dsel[k];
                float2 xA = __half22float2(pA[k * 32]);
                float2 xB = __half22float2(pB[k * 32]);
                float2 xC = __half22float2(pC[k * 32]);
                float2 xD = __half22float2(pD[k * 32]);
                acc[k].x += aA * xA.x + aB * xB.x + aC * xC.x + aD * xD.x;
                acc[k].y += aA * xA.y + aB * xB.y + aC * xC.y + aD * xD.y;
            }
        }
        for (; j < d; j++) {
            int s = csr[s0 + j];
            const __half2* p = h + (long)s * 128 + lane;
#pragma unroll
            for (int k = 0; k < 4; k++) {
                int hk = 2 * k + hi;
                float a = sm[hk * CAP + j] * dsel[k];
                float2 x = __half22float2(p[k * 32]);
                acc[k].x += a * x.x;
                acc[k].y += a * x.y;
            }
        }
    } else {
        // fallback (d > CAP, ~never)
        for (int j = lane; j < d; j += 32) {
            int s = csr[s0 + j];
#pragma unroll
            for (int k = 0; k < 8; k++) m[k] = fmaxf(m[k], lrelu(as[s * 8 + k] + adv[k]));
        }
#pragma unroll
        for (int k = 0; k < 8; k++) m[k] = wredmax(m[k]);
        float den[8];
#pragma unroll
        for (int k = 0; k < 8; k++)
            den[k] = (lane == 0) ? __expf(lrelu(asv[k] + adv[k]) - m[k]) : 0.f;
        for (int j = lane; j < d; j += 32) {
            int s = csr[s0 + j];
#pragma unroll
            for (int k = 0; k < 8; k++)
                den[k] += __expf(lrelu(as[s * 8 + k] + adv[k]) - m[k]);
        }
#pragma unroll
        for (int k = 0; k < 8; k++) {
            den[k] = wredsum(den[k]);
            den[k] = 1.f / (den[k] + 1e-16f);
        }
        float msel[4], dsel[4], esel[4];
#pragma unroll
        for (int k = 0; k < 4; k++) {
            msel[k] = hi ? m[2 * k + 1] : m[2 * k];
            dsel[k] = hi ? den[2 * k + 1] : den[2 * k];
            float sl = hi ? (asv[2 * k + 1] + adv[2 * k + 1]) : (asv[2 * k] + adv[2 * k]);
            esel[k] = __expf(lrelu(sl) - msel[k]) * dsel[k];
        }
        const __half2* hv = h + (long)v * 128 + lane;
#pragma unroll
        for (int k = 0; k < 4; k++) {
            float2 x = __half22float2(hv[k * 32]);
            acc[k] = make_float2(esel[k] * x.x, esel[k] * x.y);
        }
        for (int j = 0; j < d; j++) {
            int s = csr[s0 + j];
            float al = 0.f;
            if (lane < 8)
                al = __expf(lrelu(as[s * 8 + lane] + adv[lane]) - m[lane]) * den[lane];
            const __half2* p = h + (long)s * 128 + lane;
#pragma unroll
            for (int k = 0; k < 4; k++) {
                int hk = 2 * k + hi;
                float a = __shfl_sync(0xffffffffu, al, hk);
                float2 x = __half22float2(p[k * 32]);
                acc[k].x += a * x.x;
                acc[k].y += a * x.y;
            }
        }
    }
    float2* op = (float2*)out + (long)v * 128 + lane;
#pragma unroll
    for (int k = 0; k < 4; k++) op[k * 32] = acc[k];
}

// ========== hop combine + skip + LN1 -> bf16 split for GEMM2 ================
__global__ __launch_bounds__(256) void combine_ln(const float* __restrict__ agg0,
                                                  const float* __restrict__ agg1,
                                                  const float* __restrict__ skb,
                                                  const float* __restrict__ b1,
                                                  const float* __restrict__ skip_b,
                                                  const float* __restrict__ ha,
                                                  const float* __restrict__ g,
                                                  const float* __restrict__ bt,
                                                  __nv_bfloat16* __restrict__ fxh,
                                                  __nv_bfloat16* __restrict__ fxl) {
    int warp = (blockIdx.x * blockDim.x + threadIdx.x) >> 5;
    int lane = threadIdx.x & 31;
    if (warp >= NN) return;
    int v = warp;
    float a0h = ha[0], a1h = ha[1];
    float mx = fmaxf(a0h, a1h);
    float e0 = __expf(a0h - mx), e1 = __expf(a1h - mx);
    float inv = 1.f / (e0 + e1);
    float w0 = e0 * inv, w1 = e1 * inv;

    float vals[8];
    float sum = 0.f;
#pragma unroll
    for (int k = 0; k < 8; k++) {
        int c = k * 32 + lane;
        float x0 = agg0[(long)v * 256 + c] + b1[c];
        x0 = (x0 > 0.f) ? x0 : (__expf(x0) - 1.f);
        float x1 = agg1[(long)v * 256 + c] + b1[256 + c];
        x1 = (x1 > 0.f) ? x1 : (__expf(x1) - 1.f);
        float val = w0 * x0 + w1 * x1 + skb[(long)v * 256 + c] + skip_b[c];
        vals[k] = val;
        sum += val;
    }
    sum = wredsum(sum);
    float mu = sum * (1.f / 256.f);
    float vs = 0.f;
#pragma unroll
    for (int k = 0; k < 8; k++) {
        float dd = vals[k] - mu;
        vs += dd * dd;
    }
    vs = wredsum(vs);
    float istd = rsqrtf(vs * (1.f / 256.f) + 1e-5f);
#pragma unroll
    for (int k = 0; k < 8; k++) {
        int c = k * 32 + lane;
        float y = (vals[k] - mu) * istd * g[c] + bt[c];
        __nv_bfloat16 hi = __float2bfloat16(y);
        fxh[(long)v * 256 + c] = hi;
        fxl[(long)v * 256 + c] = __float2bfloat16(y - __bfloat162float(hi));
    }
}

// ========== fp16 copy of h2 part of h2fw ====================================
__global__ void conv_h2(const float* __restrict__ h2fw, __half2* __restrict__ h2f) {
    int i = blockIdx.x * blockDim.x + threadIdx.x;
    if (i >= NN * 32) return;
    int v = i >> 5, c = i & 31;
    float2 w = ((const float2*)(h2fw + (long)v * 128))[c];
    h2f[i] = __floats2half2_rn(w.x, w.y);
}

// ========== conv2 aggregate + residual + LN2 (fp16 gathers) =================
__global__ __launch_bounds__(256) void conv2_ln(const __half2* __restrict__ h2,
                                                const float* __restrict__ h2fw,
                                                const float* __restrict__ as2,
                                                const float* __restrict__ ad2,
                                                const int* __restrict__ off,
                                                const int* __restrict__ csr,
                                                const float* __restrict__ b2,
                                                const float* __restrict__ finalb,
                                                const float* __restrict__ g2,
                                                const float* __restrict__ bt2,
                                                float* __restrict__ out) {
    __shared__ float sal[8][CAP];
    int gwarp = (blockIdx.x * blockDim.x + threadIdx.x) >> 5;
    int lane = threadIdx.x & 31;
    if (gwarp >= NN) return;
    int v = gwarp;
    float* sm = sal[threadIdx.x >> 5];
    int s0 = off[v];
    int d = off[v + 1] - s0;
    float adv = ad2[v], asv = as2[v];
    float eself = lrelu(asv + adv);
    float m = eself;
    float2 acc;

    if (d <= CAP) {
        for (int j = lane; j < d; j += 32) {
            int s = csr[s0 + j];
            float e = lrelu(as2[s] + adv);
            sm[j] = e;
            m = fmaxf(m, e);
        }
        m = wredmax(m);
        float den = (lane == 0) ? __expf(eself - m) : 0.f;
        for (int j = lane; j < d; j += 32) {
            float e = __expf(sm[j] - m);
            sm[j] = e;
            den += e;
        }
        den = wredsum(den);
        float inv = 1.f / (den + 1e-16f);
        __syncwarp();

        float al = __expf(eself - m) * inv;
        float2 xs = __half22float2(h2[(long)v * 32 + lane]);
        acc = make_float2(al * xs.x, al * xs.y);
        int j = 0;
        for (; j + 4 <= d; j += 4) {
            int sA = csr[s0 + j], sB = csr[s0 + j + 1];
            int sC = csr[s0 + j + 2], sD = csr[s0 + j + 3];
            float aA = sm[j] * inv, aB = sm[j + 1] * inv;
            float aC = sm[j + 2] * inv, aD = sm[j + 3] * inv;
            float2 xA = __half22float2(h2[(long)sA * 32 + lane]);
            float2 xB = __half22float2(h2[(long)sB * 32 + lane]);
            float2 xC = __half22float2(h2[(long)sC * 32 + lane]);
            float2 xD = __half22float2(h2[(long)sD * 32 + lane]);
            acc.x += aA * xA.x + aB * xB.x + aC * xC.x + aD * xD.x;
            acc.y += aA * xA.y + aB * xB.y + aC * xC.y + aD * xD.y;
        }
        for (; j < d; j++) {
            int s = csr[s0 + j];
            float a = sm[j] * inv;
            float2 x = __half22float2(h2[(long)s * 32 + lane]);
            acc.x += a * x.x;
            acc.y += a * x.y;
        }
    } else {
        for (int j = lane; j < d; j += 32) {
            int s = csr[s0 + j];
            m = fmaxf(m, lrelu(as2[s] + adv));
        }
        m = wredmax(m);
        float den = (lane == 0) ? __expf(eself - m) : 0.f;
        for (int j = lane; j < d; j += 32) {
            int s = csr[s0 + j];
            den += __expf(lrelu(as2[s] + adv) - m);
        }
        den = wredsum(den);
        float inv = 1.f / (den + 1e-16f);
        float al = __expf(eself - m) * inv;
        float2 xs = __half22float2(h2[(long)v * 32 + lane]);
        acc = make_float2(al * xs.x, al * xs.y);
        for (int j = 0; j < d; j++) {
            int s = csr[s0 + j];
            float a = __expf(lrelu(as2[s] + adv) - m) * inv;
            float2 x = __half22float2(h2[(long)s * 32 + lane]);
            acc.x += a * x.x;
            acc.y += a * x.y;
        }
    }

    int c0 = 2 * lane, c1 = 2 * lane + 1;
    float2 fw = *(const float2*)(h2fw + (long)v * 128 + 64 + c0);
    acc.x += b2[c0] + fw.x + finalb[c0];
    acc.y += b2[c1] + fw.y + finalb[c1];
    float sum = wredsum(acc.x + acc.y);
    float mu = sum * (1.f / 64.f);
    float d0 = acc.x - mu, d1 = acc.y - mu;
    float vs = wredsum(d0 * d0 + d1 * d1);
    float istd = rsqrtf(vs * (1.f / 64.f) + 1e-5f);
    float2 r;
    r.x = d0 * istd * g2[c0] + bt2[c0];
    r.y = d1 * istd * g2[c1] + bt2[c1];
    ((float2*)out)[(long)v * 32 + lane] = r;
}

__global__ void write_w(const float* __restrict__ ha, float* __restrict__ out) {
    if (threadIdx.x == 0) {
        float a0 = ha[0], a1 = ha[1];
        float mx = fmaxf(a0, a1);
        float e0 = __expf(a0 - mx), e1 = __expf(a1 - mx);
        float inv = 1.f / (e0 + e1);
        out[NN * 64 + 0] = e0 * inv;
        out[NN * 64 + 1] = e1 * inv;
    }
}

// ================= launch ===================================================
extern "C" void kernel_launch(void* const* d_in, const int* in_sizes, int n_in,
                              void* d_out, int out_size) {
    const float* x = (const float*)d_in[0];
    const int* ei = (const int*)d_in[1];
    const int* ei2 = (const int*)d_in[2];
    const float* W1 = (const float*)d_in[3];
    const float* att_src1 = (const float*)d_in[4];
    const float* att_dst1 = (const float*)d_in[5];
    const float* b1 = (const float*)d_in[6];
    const float* W2 = (const float*)d_in[7];
    const float* att_src2 = (const float*)d_in[8];
    const float* att_dst2 = (const float*)d_in[9];
    const float* b2 = (const float*)d_in[10];
    const float* ha = (const float*)d_in[11];
    const float* skipW = (const float*)d_in[12];
    const float* skipb = (const float*)d_in[13];
    const float* finalW = (const float*)d_in[14];
    const float* finalb = (const float*)d_in[15];
    const float* ln1g = (const float*)d_in[16];
    const float* ln1b = (const float*)d_in[17];
    const float* ln2g = (const float*)d_in[18];
    const float* ln2b = (const float*)d_in[19];
    float* out = (float*)d_out;

    GS* g = nullptr;
    cudaGetSymbolAddress((void**)&g, gs);

    const int GSMEM = 2 * 40960;
    cudaFuncSetAttribute(hmma_gemm, cudaFuncAttributeMaxDynamicSharedMemorySize, GSMEM);

    const int TB = 256;
    int eb = (EE + TB - 1) / TB;
    int nb = (NN + TB - 1) / TB;
    int wb = (NN + 7) / 8;

    // operand prep
    split_x<<<(NN * 256 + TB - 1) / TB, TB>>>(x, g->xh, g->xl, NN * 256);
    pack_B1<<<(768 * 256 + TB - 1) / TB, TB>>>(W1, skipW, g->B1h, g->B1l);
    pack_B2<<<(128 * 256 + TB - 1) / TB, TB>>>(W2, finalW, g->B2h, g->B2l);

    // GEMM1: x @ [W1_0 | W1_1 | skip_W] -> h0f(fp16), h1f(fp16), skb(fp32)
    {
        dim3 grid(6, (NN + 127) / 128);
        hmma_gemm<<<grid, 256, GSMEM>>>(g->xh, g->xl, g->B1h, g->B1l,
                                        g->h0f, g->h1f, g->skb, NN, 256);
    }

    // CSR build
    zero_int<<<nb, TB>>>(g->deg0, NN);
    zero_int<<<nb, TB>>>(g->deg1, NN);
    hist_kernel<<<eb, TB>>>(ei + EE, g->deg0);
    hist_kernel<<<eb, TB>>>(ei2 + EE, g->deg1);
    scan_kernel<<<1, 1024>>>(g->deg0, g->off0);
    scan_kernel<<<1, 1024>>>(g->deg1, g->off1);
    copy_int<<<nb, TB>>>(g->off0, g->cur0, NN);
    copy_int<<<nb, TB>>>(g->off1, g->cur1, NN);
    scatter_kernel<<<eb, TB>>>(ei, ei + EE, g->cur0, g->csr0);
    scatter_kernel<<<eb, TB>>>(ei2, ei2 + EE, g->cur1, g->csr1);

    // logits per hop (fp16 features)
    logits8<<<(NN * 8 + TB - 1) / TB, TB>>>((const __half2*)g->h0f, att_src1, att_dst1,
                                            g->as0, g->ad0);
    logits8<<<(NN * 8 + TB - 1) / TB, TB>>>((const __half2*)g->h1f, att_src1 + 256,
                                            att_dst1 + 256, g->as1, g->ad1);

    // GAT aggregation per hop
    gat_agg8<<<wb, TB>>>((const __half2*)g->h0f, g->as0, g->ad0, g->off0, g->csr0, g->agg0);
    gat_agg8<<<wb, TB>>>((const __half2*)g->h1f, g->as1, g->ad1, g->off1, g->csr1, g->agg1);

    // combine + skip + LN1 -> bf16 split
    combine_ln<<<wb, TB>>>(g->agg0, g->agg1, g->skb, b1, skipb, ha, ln1g, ln1b, g->fxh, g->fxl);

    // GEMM2: first @ [W2 | final_W] -> h2fw (fp32)
    {
        dim3 grid(1, (NN + 127) / 128);
        hmma_gemm<<<grid, 256, GSMEM>>>(g->fxh, g->fxl, g->B2h, g->B2l,
                                        nullptr, nullptr, g->h2fw, NN, 128);
    }

    // fp16 copy of h2 + logits + conv2 + LN2
    conv_h2<<<(NN * 32 + TB - 1) / TB, TB>>>(g->h2fw, (__half2*)g->h2f);
    logits1<<<nb, TB>>>((const __half2*)g->h2f, att_src2, att_dst2, g->as2, g->ad2);
    conv2_ln<<<wb, TB>>>((const __half2*)g->h2f, g->h2fw, g->as2, g->ad2, g->off0, g->csr0,
                         b2, finalb, ln2g, ln2b, out);
    write_w<<<1, 32>>>(ha, out);
}

// round 7
// speedup vs baseline: 1.9977x; 1.0086x over previous
#include <cuda_runtime.h>
#include <cuda_bf16.h>
#include <cuda_fp16.h>
#include <math.h>
#include <stdint.h>

#define NN 50000
#define EE 800000
#define CAP 96

// ================= scratch ==================================================
struct GS {
    float skb[(size_t)NN * 256];
    float agg0[(size_t)NN * 256];
    float agg1[(size_t)NN * 256];
    float h2fw[(size_t)NN * 128];
    __half h0f[(size_t)NN * 256];
    __half h1f[(size_t)NN * 256];
    __half h2f[(size_t)NN * 64];
    float as0[NN * 8], ad0[NN * 8], as1[NN * 8], ad1[NN * 8];
    float as2[NN], ad2[NN];
    __half xf[(size_t)NN * 256];
    __nv_bfloat16 xh[(size_t)NN * 256], xl[(size_t)NN * 256];
    __nv_bfloat16 fxh[(size_t)NN * 256], fxl[(size_t)NN * 256];
    __half B1f[512 * 256];
    __nv_bfloat16 Bsh[256 * 256], Bsl[256 * 256];
    __nv_bfloat16 B2h[128 * 256], B2l[128 * 256];
    int deg0[NN], deg1[NN];
    int off0[NN + 1], off1[NN + 1];
    int cur0[NN], cur1[NN];
    int csr0[EE], csr1[EE];
};
__device__ GS gs;

// ================= helpers ==================================================
__device__ __forceinline__ float wredsum(float v) {
#pragma unroll
    for (int o = 16; o; o >>= 1) v += __shfl_xor_sync(0xffffffffu, v, o);
    return v;
}
__device__ __forceinline__ float wredmax(float v) {
#pragma unroll
    for (int o = 16; o; o >>= 1) v = fmaxf(v, __shfl_xor_sync(0xffffffffu, v, o));
    return v;
}
__device__ __forceinline__ float lrelu(float x) { return fmaxf(x, 0.2f * x); }
__device__ __forceinline__ uint32_t smem_u32(const void* p) {
    uint32_t a;
    asm("{ .reg .u64 t; cvta.to.shared.u64 t, %1; cvt.u32.u64 %0, t; }" : "=r"(a) : "l"(p));
    return a;
}
__device__ __forceinline__ void cp16(uint32_t dst, const void* src, bool v) {
    int bytes = v ? 16 : 0;
    asm volatile("cp.async.cg.shared.global [%0], [%1], 16, %2;\n"
                 :: "r"(dst), "l"(src), "r"(bytes));
}
__device__ __forceinline__ void ldsm4(uint32_t* r, uint32_t addr) {
    asm volatile("ldmatrix.sync.aligned.m8n8.x4.shared.b16 {%0,%1,%2,%3}, [%4];\n"
                 : "=r"(r[0]), "=r"(r[1]), "=r"(r[2]), "=r"(r[3]) : "r"(addr));
}
__device__ __forceinline__ void mma_bf16(float* d, const uint32_t* a, uint32_t b0, uint32_t b1) {
    asm volatile(
        "mma.sync.aligned.m16n8k16.row.col.f32.bf16.bf16.f32 "
        "{%0,%1,%2,%3}, {%4,%5,%6,%7}, {%8,%9}, {%0,%1,%2,%3};\n"
        : "+f"(d[0]), "+f"(d[1]), "+f"(d[2]), "+f"(d[3])
        : "r"(a[0]), "r"(a[1]), "r"(a[2]), "r"(a[3]), "r"(b0), "r"(b1));
}
__device__ __forceinline__ void mma_f16(float* d, const uint32_t* a, uint32_t b0, uint32_t b1) {
    asm volatile(
        "mma.sync.aligned.m16n8k16.row.col.f32.f16.f16.f32 "
        "{%0,%1,%2,%3}, {%4,%5,%6,%7}, {%8,%9}, {%0,%1,%2,%3};\n"
        : "+f"(d[0]), "+f"(d[1]), "+f"(d[2]), "+f"(d[3])
        : "r"(a[0]), "r"(a[1]), "r"(a[2]), "r"(a[3]), "r"(b0), "r"(b1));
}

// ================= CSR build ================================================
__global__ void zero_int(int* p, int n) {
    int i = blockIdx.x * blockDim.x + threadIdx.x;
    if (i < n) p[i] = 0;
}
__global__ void hist_kernel(const int* __restrict__ dst, int* __restrict__ deg) {
    int i = blockIdx.x * blockDim.x + threadIdx.x;
    if (i < EE) atomicAdd(&deg[dst[i]], 1);
}
__global__ void scan_kernel(const int* __restrict__ deg, int* __restrict__ off,
                            int* __restrict__ cur) {
    __shared__ int sh[1024];
    const int n = NN;
    int t = threadIdx.x;
    int chunk = (n + 1023) >> 10;
    int s = t * chunk;
    int e = min(s + chunk, n);
    int sum = 0;
    for (int i = s; i < e; i++) sum += deg[i];
    sh[t] = sum;
    __syncthreads();
#pragma unroll
    for (int o = 1; o < 1024; o <<= 1) {
        int val = (t >= o) ? sh[t - o] : 0;
        __syncthreads();
        sh[t] += val;
        __syncthreads();
    }
    int run = sh[t] - sum;
    for (int i = s; i < e; i++) {
        off[i] = run;
        cur[i] = run;
        run += deg[i];
    }
    if (t == 1023) off[n] = sh[1023];
}
__global__ void scatter_kernel(const int* __restrict__ esrc, const int* __restrict__ edst,
                               int* __restrict__ cur, int* __restrict__ csr) {
    int i = blockIdx.x * blockDim.x + threadIdx.x;
    if (i < EE) {
        int d = edst[i];
        int p = atomicAdd(&cur[d], 1);
        csr[p] = esrc[i];
    }
}

// ================= operand packing ==========================================
__global__ void split_x(const float* __restrict__ x, __nv_bfloat16* __restrict__ xh,
                        __nv_bfloat16* __restrict__ xl, __half* __restrict__ xf, int n) {
    int i = blockIdx.x * blockDim.x + threadIdx.x;
    if (i >= n) return;
    float v = x[i];
    __nv_bfloat16 h = __float2bfloat16(v);
    xh[i] = h;
    xl[i] = __float2bfloat16(v - __bfloat162float(h));
    xf[i] = __float2half_rn(v);
}
__global__ void pack_B1f(const float* __restrict__ W1, __half* __restrict__ Bf) {
    int i = blockIdx.x * blockDim.x + threadIdx.x;
    if (i >= 512 * 256) return;
    int n = i / 256, k = i % 256;
    float v = (n < 256) ? W1[k * 256 + n] : W1[65536 + k * 256 + (n - 256)];
    Bf[i] = __float2half_rn(v);
}
__global__ void pack_skip(const float* __restrict__ skipW, __nv_bfloat16* __restrict__ Bh,
                          __nv_bfloat16* __restrict__ Bl) {
    int i = blockIdx.x * blockDim.x + threadIdx.x;
    if (i >= 256 * 256) return;
    int n = i / 256, k = i % 256;
    float v = skipW[k * 256 + n];
    __nv_bfloat16 h = __float2bfloat16(v);
    Bh[i] = h;
    Bl[i] = __float2bfloat16(v - __bfloat162float(h));
}
__global__ void pack_B2(const float* __restrict__ W2, const float* __restrict__ finalW,
                        __nv_bfloat16* __restrict__ Bh, __nv_bfloat16* __restrict__ Bl) {
    int i = blockIdx.x * blockDim.x + threadIdx.x;
    if (i >= 128 * 256) return;
    int n = i / 256, k = i % 256;
    float v = (n < 64) ? W2[k * 64 + n] : finalW[k * 64 + (n - 64)];
    __nv_bfloat16 h = __float2bfloat16(v);
    Bh[i] = h;
    Bl[i] = __float2bfloat16(v - __bfloat162float(h));
}

// ====== fp16 single-pass HMMA GEMM: H = A[M,256] @ B[512,256]^T -> fp16 =====
// CTA tile 128x128, 8 warps, BK=32, 3-stage cp.async. Buckets (256 cols) -> H0/H1.
__global__ __launch_bounds__(256, 2) void hmma_gemm_f16(
    const __half* __restrict__ A, const __half* __restrict__ B,
    __half* __restrict__ H0, __half* __restrict__ H1, int M) {
    extern __shared__ char sm[];
    const int tid = threadIdx.x, lane = tid & 31, warp = tid >> 5;
    const int wm = warp & 1, wn = warp >> 1;
    const int m0 = blockIdx.y * 128, n0 = blockIdx.x * 128;
    uint32_t sbase = smem_u32(sm);

    float acc[4][4][4];
#pragma unroll
    for (int a = 0; a < 4; a++)
#pragma unroll
        for (int b = 0; b < 4; b++)
#pragma unroll
            for (int q = 0; q < 4; q++) acc[a][b][q] = 0.f;

#define LOADF(c, s)                                                               \
    do {                                                                          \
        uint32_t sb_ = sbase + (s) * 20480;                                       \
        _Pragma("unroll") for (int it = 0; it < 2; it++) {                        \
            int idx = tid + it * 256;                                             \
            int row = idx >> 2, kc = idx & 3;                                     \
            uint32_t so = row * 80 + kc * 16;                                     \
            bool va = (m0 + row) < M;                                             \
            long ga = (long)(m0 + row) * 256 + (c) * 32 + kc * 8;                 \
            if (!va) ga = 0;                                                      \
            cp16(sb_ + so, A + ga, va);                                           \
            long gb = (long)(n0 + row) * 256 + (c) * 32 + kc * 8;                 \
            cp16(sb_ + 10240 + so, B + gb, true);                                 \
        }                                                                         \
        asm volatile("cp.async.commit_group;\n" ::: "memory");                    \
    } while (0)

    LOADF(0, 0);
    LOADF(1, 1);
    for (int c = 0; c < 8; c++) {
        if (c + 2 < 8) LOADF(c + 2, (c + 2) % 3);
        if (c < 6) asm volatile("cp.async.wait_group 2;\n" ::: "memory");
        else if (c == 6) asm volatile("cp.async.wait_group 1;\n" ::: "memory");
        else asm volatile("cp.async.wait_group 0;\n" ::: "memory");
        __syncthreads();
        uint32_t sb = sbase + (c % 3) * 20480;
#pragma unroll
        for (int ks = 0; ks < 2; ks++) {
            uint32_t ah[4][4], bh[2][4];
            int acol = ks * 16 + 8 * (lane >> 4);
            int arowl = (lane & 15);
#pragma unroll
            for (int mf = 0; mf < 4; mf++) {
                int arow = wm * 64 + mf * 16 + arowl;
                ldsm4(ah[mf], sb + arow * 80 + acol * 2);
            }
            int bcol = ks * 16 + 8 * ((lane >> 3) & 1);
            int browl = (lane & 7) + 8 * (lane >> 4);
#pragma unroll
            for (int p = 0; p < 2; p++) {
                int brow = wn * 32 + p * 16 + browl;
                ldsm4(bh[p], sb + 10240 + brow * 80 + bcol * 2);
            }
#pragma unroll
            for (int mf = 0; mf < 4; mf++)
#pragma unroll
                for (int p = 0; p < 2; p++)
#pragma unroll
                    for (int sub = 0; sub < 2; sub++) {
                        int nf = p * 2 + sub;
                        mma_f16(acc[mf][nf], ah[mf], bh[p][sub * 2], bh[p][sub * 2 + 1]);
                    }
        }
        __syncthreads();
    }
#undef LOADF

    int bucket = n0 >> 8;
    int cb = n0 & 255;
    __half2* H = (__half2*)((bucket == 0) ? H0 : H1);
    int group = lane >> 2, q = lane & 3;
#pragma unroll
    for (int mf = 0; mf < 4; mf++) {
        int r0 = m0 + wm * 64 + mf * 16 + group;
#pragma unroll
        for (int nf = 0; nf < 4; nf++) {
            int col = cb + wn * 32 + nf * 8 + q * 2;
            if (r0 < M)
                H[(long)r0 * 128 + col / 2] = __floats2half2_rn(acc[mf][nf][0], acc[mf][nf][1]);
            if (r0 + 8 < M)
                H[(long)(r0 + 8) * 128 + col / 2] =
                    __floats2half2_rn(acc[mf][nf][2], acc[mf][nf][3]);
        }
    }
}

// ====== bf16-split HMMA GEMM (3 MMA): C[M,split*nb] fp32 ====================
__global__ __launch_bounds__(256, 2) void hmma_gemm(
    const __nv_bfloat16* __restrict__ Ah, const __nv_bfloat16* __restrict__ Al,
    const __nv_bfloat16* __restrict__ Bh, const __nv_bfloat16* __restrict__ Bl,
    float* __restrict__ C, int M, int split) {
    extern __shared__ char sm[];
    const int tid = threadIdx.x, lane = tid & 31, warp = tid >> 5;
    const int wm = warp & 1, wn = warp >> 1;
    const int m0 = blockIdx.y * 128, n0 = blockIdx.x * 128;
    uint32_t sbase = smem_u32(sm);

    float acc[4][4][4];
#pragma unroll
    for (int a = 0; a < 4; a++)
#pragma unroll
        for (int b = 0; b < 4; b++)
#pragma unroll
            for (int q = 0; q < 4; q++) acc[a][b][q] = 0.f;

#define LOAD_STAGE(c, s)                                                          \
    do {                                                                          \
        uint32_t sb_ = sbase + (s) * 40960;                                       \
        _Pragma("unroll") for (int it = 0; it < 2; it++) {                        \
            int idx = tid + it * 256;                                             \
            int row = idx >> 2, kc = idx & 3;                                     \
            uint32_t so = row * 80 + kc * 16;                                     \
            bool va = (m0 + row) < M;                                             \
            long ga = (long)(m0 + row) * 256 + (c) * 32 + kc * 8;                 \
            if (!va) ga = 0;                                                      \
            cp16(sb_ + so, Ah + ga, va);                                          \
            cp16(sb_ + 10240 + so, Al + ga, va);                                  \
            long gb = (long)(n0 + row) * 256 + (c) * 32 + kc * 8;                 \
            cp16(sb_ + 20480 + so, Bh + gb, true);                                \
            cp16(sb_ + 30720 + so, Bl + gb, true);                                \
        }                                                                         \
        asm volatile("cp.async.commit_group;\n" ::: "memory");                    \
    } while (0)

    LOAD_STAGE(0, 0);
    for (int c = 0; c < 8; c++) {
        if (c < 7) {
            LOAD_STAGE(c + 1, (c + 1) & 1);
            asm volatile("cp.async.wait_group 1;\n" ::: "memory");
        } else {
            asm volatile("cp.async.wait_group 0;\n" ::: "memory");
        }
        __syncthreads();
        uint32_t sb = sbase + (c & 1) * 40960;
#pragma unroll
        for (int ks = 0; ks < 2; ks++) {
            uint32_t ah[4][4], al[4][4], bhf[2][4], blf[2][4];
            int acol = ks * 16 + 8 * (lane >> 4);
            int arowl = (lane & 15);
#pragma unroll
            for (int mf = 0; mf < 4; mf++) {
                int arow = wm * 64 + mf * 16 + arowl;
                uint32_t ad = sb + arow * 80 + acol * 2;
                ldsm4(ah[mf], ad);
                ldsm4(al[mf], ad + 10240);
            }
            int bcol = ks * 16 + 8 * ((lane >> 3) & 1);
            int browl = (lane & 7) + 8 * (lane >> 4);
#pragma unroll
            for (int p = 0; p < 2; p++) {
                int brow = wn * 32 + p * 16 + browl;
                uint32_t bd = sb + 20480 + brow * 80 + bcol * 2;
                ldsm4(bhf[p], bd);
                ldsm4(blf[p], bd + 10240);
            }
#pragma unroll
            for (int mf = 0; mf < 4; mf++)
#pragma unroll
                for (int p = 0; p < 2; p++)
#pragma unroll
                    for (int sub = 0; sub < 2; sub++) {
                        int nf = p * 2 + sub;
                        uint32_t h0 = bhf[p][sub * 2], h1 = bhf[p][sub * 2 + 1];
                        uint32_t l0 = blf[p][sub * 2], l1 = blf[p][sub * 2 + 1];
                        mma_bf16(acc[mf][nf], ah[mf], h0, h1);
                        mma_bf16(acc[mf][nf], ah[mf], l0, l1);
                        mma_bf16(acc[mf][nf], al[mf], h0, h1);
                    }
        }
        __syncthreads();
    }
#undef LOAD_STAGE

    int cb = n0 % split;
    int group = lane >> 2, q = lane & 3;
#pragma unroll
    for (int mf = 0; mf < 4; mf++) {
        int r0 = m0 + wm * 64 + mf * 16 + group;
#pragma unroll
        for (int nf = 0; nf < 4; nf++) {
            int col = cb + wn * 32 + nf * 8 + q * 2;
            if (r0 < M)
                *(float2*)(C + (long)r0 * split + col) =
                    make_float2(acc[mf][nf][0], acc[mf][nf][1]);
            if (r0 + 8 < M)
                *(float2*)(C + (long)(r0 + 8) * split + col) =
                    make_float2(acc[mf][nf][2], acc[mf][nf][3]);
        }
    }
}

// ================= attention logits (fp16 features) =========================
__global__ void logits8(const __half2* __restrict__ h, const float* __restrict__ a_src,
                        const float* __restrict__ a_dst, float* __restrict__ as,
                        float* __restrict__ ad) {
    int t = blockIdx.x * blockDim.x + threadIdx.x;
    if (t >= NN * 8) return;
    int v = t >> 3, k = t & 7;
    const __half2* hr = h + (long)v * 128 + k * 16;
    const float* sv = a_src + k * 32;
    const float* dv = a_dst + k * 32;
    float s = 0.f, d = 0.f;
#pragma unroll
    for (int c = 0; c < 16; c++) {
        float2 hv = __half22float2(hr[c]);
        s += hv.x * sv[2 * c] + hv.y * sv[2 * c + 1];
        d += hv.x * dv[2 * c] + hv.y * dv[2 * c + 1];
    }
    as[t] = s;
    ad[t] = d;
}
__global__ void logits1(const __half2* __restrict__ h2, const float* __restrict__ a_src,
                        const float* __restrict__ a_dst, float* __restrict__ as,
                        float* __restrict__ ad) {
    int v = blockIdx.x * blockDim.x + threadIdx.x;
    if (v >= NN) return;
    const __half2* hr = h2 + (long)v * 32;
    float s = 0.f, d = 0.f;
#pragma unroll
    for (int c = 0; c < 32; c++) {
        float2 hv = __half22float2(hr[c]);
        s += hv.x * a_src[2 * c] + hv.y * a_src[2 * c + 1];
        d += hv.x * a_dst[2 * c] + hv.y * a_dst[2 * c + 1];
    }
    as[v] = s;
    ad[v] = d;
}

// ====== GAT aggregation: 8 heads, warp/dst, fp16 features, smem alphas ======
__global__ __launch_bounds__(256) void gat_agg8(const __half2* __restrict__ h,
                                                const float* __restrict__ as,
                                                const float* __restrict__ ad,
                                                const int* __restrict__ off,
                                                const int* __restrict__ csr,
                                                float* __restrict__ out) {
    __shared__ float sal[8][8 * CAP];
    int gwarp = (blockIdx.x * blockDim.x + threadIdx.x) >> 5;
    int lane = threadIdx.x & 31;
    if (gwarp >= NN) return;
    int v = gwarp;
    float* sm = sal[threadIdx.x >> 5];
    int s0 = off[v];
    int d = off[v + 1] - s0;
    int hi = lane >> 4;
    float adv[8], asv[8];
#pragma unroll
    for (int k = 0; k < 8; k++) { adv[k] = ad[v * 8 + k]; asv[k] = as[v * 8 + k]; }

    float m[8];
#pragma unroll
    for (int k = 0; k < 8; k++) m[k] = lrelu(asv[k] + adv[k]);

    float2 acc[4];

    if (d <= CAP) {
        for (int j = lane; j < d; j += 32) {
            int s = csr[s0 + j];
            float4 a0 = *(const float4*)(as + s * 8);
            float4 a1 = *(const float4*)(as + s * 8 + 4);
            float ev[8] = {a0.x, a0.y, a0.z, a0.w, a1.x, a1.y, a1.z, a1.w};
#pragma unroll
            for (int k = 0; k < 8; k++) {
                float e = lrelu(ev[k] + adv[k]);
                sm[k * CAP + j] = e;
                m[k] = fmaxf(m[k], e);
            }
        }
#pragma unroll
        for (int k = 0; k < 8; k++) m[k] = wredmax(m[k]);

        float den[8];
#pragma unroll
        for (int k = 0; k < 8; k++)
            den[k] = (lane == 0) ? __expf(lrelu(asv[k] + adv[k]) - m[k]) : 0.f;
        for (int j = lane; j < d; j += 32) {
#pragma unroll
            for (int k = 0; k < 8; k++) {
                float e = __expf(sm[k * CAP + j] - m[k]);
                sm[k * CAP + j] = e;
                den[k] += e;
            }
        }
#pragma unroll
        for (int k = 0; k < 8; k++) {
            den[k] = wredsum(den[k]);
            den[k] = 1.f / (den[k] + 1e-16f);
        }
        __syncwarp();

        float msel[4], dsel[4], esel[4];
#pragma unroll
        for (int k = 0; k < 4; k++) {
            msel[k] = hi ? m[2 * k + 1] : m[2 * k];
            dsel[k] = hi ? den[2 * k + 1] : den[2 * k];
            float sl = hi ? (asv[2 * k + 1] + adv[2 * k + 1]) : (asv[2 * k] + adv[2 * k]);
            esel[k] = __expf(lrelu(sl) - msel[k]) * dsel[k];
        }

        const __half2* hv = h + (long)v * 128 + lane;
#pragma unroll
        for (int k = 0; k < 4; k++) {
            float2 x = __half22float2(hv[k * 32]);
            acc[k] = make_float2(esel[k] * x.x, esel[k] * x.y);
        }
        int j = 0;
        for (; j + 4 <= d; j += 4) {
            int sA = csr[s0 + j], sB = csr[s0 + j + 1];
            int sC = csr[s0 + j + 2], sD = csr[s0 + j + 3];
            const __half2* pA = h + (long)sA * 128 + lane;
            const __half2* pB = h + (long)sB * 128 + lane;
            const __half2* pC = h + (long)sC * 128 + lane;
            const __half2* pD = h + (long)sD * 128 + lane;
#pragma unroll
            for (int k = 0; k < 4; k++) {
                int hk = 2 * k + hi;
                float aA = sm[hk * CAP + j] * dsel[k];
                float aB = sm[hk * CAP + j + 1] * dsel[k];
                float aC = sm[hk * CAP + j + 2] * dsel[k];
                float aD = sm[hk * CAP + j + 3] * dsel[k];
                float2 xA = __half22float2(pA[k * 32]);
                float2 xB = __half22float2(pB[k * 32]);
                float2 xC = __half22float2(pC[k * 32]);
                float2 xD = __half22float2(pD[k * 32]);
                acc[k].x += aA * xA.x + aB * xB.x + aC * xC.x + aD * xD.x;
                acc[k].y += aA * xA.y + aB * xB.y + aC * xC.y + aD * xD.y;
            }
        }
        for (; j < d; j++) {
            int s = csr[s0 + j];
            const __half2* p = h + (long)s * 128 + lane;
#pragma unroll
            for (int k = 0; k < 4; k++) {
                int hk = 2 * k + hi;
                float a = sm[hk * CAP + j] * dsel[k];
                float2 x = __half22float2(p[k * 32]);
                acc[k].x += a * x.x;
                acc[k].y += a * x.y;
            }
        }
    } else {
        for (int j = lane; j < d; j += 32) {
            int s = csr[s0 + j];
#pragma unroll
            for (int k = 0; k < 8; k++) m[k] = fmaxf(m[k], lrelu(as[s * 8 + k] + adv[k]));
        }
#pragma unroll
        for (int k = 0; k < 8; k++) m[k] = wredmax(m[k]);
        float den[8];
#pragma unroll
        for (int k = 0; k < 8; k++)
            den[k] = (lane == 0) ? __expf(lrelu(asv[k] + adv[k]) - m[k]) : 0.f;
        for (int j = lane; j < d; j += 32) {
            int s = csr[s0 + j];
#pragma unroll
            for (int k = 0; k < 8; k++)
                den[k] += __expf(lrelu(as[s * 8 + k] + adv[k]) - m[k]);
        }
#pragma unroll
        for (int k = 0; k < 8; k++) {
            den[k] = wredsum(den[k]);
            den[k] = 1.f / (den[k] + 1e-16f);
        }
        float msel[4], dsel[4], esel[4];
#pragma unroll
        for (int k = 0; k < 4; k++) {
            msel[k] = hi ? m[2 * k + 1] : m[2 * k];
            dsel[k] = hi ? den[2 * k + 1] : den[2 * k];
            float sl = hi ? (asv[2 * k + 1] + adv[2 * k + 1]) : (asv[2 * k] + adv[2 * k]);
            esel[k] = __expf(lrelu(sl) - msel[k]) * dsel[k];
        }
        const __half2* hv = h + (long)v * 128 + lane;
#pragma unroll
        for (int k = 0; k < 4; k++) {
            float2 x = __half22float2(hv[k * 32]);
            acc[k] = make_float2(esel[k] * x.x, esel[k] * x.y);
        }
        for (int j = 0; j < d; j++) {
            int s = csr[s0 + j];
            float al = 0.f;
            if (lane < 8)
                al = __expf(lrelu(as[s * 8 + lane] + adv[lane]) - m[lane]) * den[lane];
            const __half2* p = h + (long)s * 128 + lane;
#pragma unroll
            for (int k = 0; k < 4; k++) {
                int hk = 2 * k + hi;
                float a = __shfl_sync(0xffffffffu, al, hk);
                float2 x = __half22float2(p[k * 32]);
                acc[k].x += a * x.x;
                acc[k].y += a * x.y;
            }
        }
    }
    float2* op = (float2*)out + (long)v * 128 + lane;
#pragma unroll
    for (int k = 0; k < 4; k++) op[k * 32] = acc[k];
}

// ========== hop combine + skip + LN1 -> bf16 split for GEMM2 ================
__global__ __launch_bounds__(256) void combine_ln(const float* __restrict__ agg0,
                                                  const float* __restrict__ agg1,
                                                  const float* __restrict__ skb,
                                                  const float* __restrict__ b1,
                                                  const float* __restrict__ skip_b,
                                                  const float* __restrict__ ha,
                                                  const float* __restrict__ g,
                                                  const float* __restrict__ bt,
                                                  __nv_bfloat16* __restrict__ fxh,
                                                  __nv_bfloat16* __restrict__ fxl) {
    int warp = (blockIdx.x * blockDim.x + threadIdx.x) >> 5;
    int lane = threadIdx.x & 31;
    if (warp >= NN) return;
    int v = warp;
    float a0h = ha[0], a1h = ha[1];
    float mx = fmaxf(a0h, a1h);
    float e0 = __expf(a0h - mx), e1 = __expf(a1h - mx);
    float inv = 1.f / (e0 + e1);
    float w0 = e0 * inv, w1 = e1 * inv;

    float vals[8];
    float sum = 0.f;
#pragma unroll
    for (int k = 0; k < 8; k++) {
        int c = k * 32 + lane;
        float x0 = agg0[(long)v * 256 + c] + b1[c];
        x0 = (x0 > 0.f) ? x0 : (__expf(x0) - 1.f);
        float x1 = agg1[(long)v * 256 + c] + b1[256 + c];
        x1 = (x1 > 0.f) ? x1 : (__expf(x1) - 1.f);
        float val = w0 * x0 + w1 * x1 + skb[(long)v * 256 + c] + skip_b[c];
        vals[k] = val;
        sum += val;
    }
    sum = wredsum(sum);
    float mu = sum * (1.f / 256.f);
    float vs = 0.f;
#pragma unroll
    for (int k = 0; k < 8; k++) {
        float dd = vals[k] - mu;
        vs += dd * dd;
    }
    vs = wredsum(vs);
    float istd = rsqrtf(vs * (1.f / 256.f) + 1e-5f);
#pragma unroll
    for (int k = 0; k < 8; k++) {
        int c = k * 32 + lane;
        float y = (vals[k] - mu) * istd * g[c] + bt[c];
        __nv_bfloat16 hi = __float2bfloat16(y);
        fxh[(long)v * 256 + c] = hi;
        fxl[(long)v * 256 + c] = __float2bfloat16(y - __bfloat162float(hi));
    }
}

// ========== fp16 copy of h2 part of h2fw ====================================
__global__ void conv_h2(const float* __restrict__ h2fw, __half2* __restrict__ h2f) {
    int i = blockIdx.x * blockDim.x + threadIdx.x;
    if (i >= NN * 32) return;
    int v = i >> 5, c = i & 31;
    float2 w = ((const float2*)(h2fw + (long)v * 128))[c];
    h2f[i] = __floats2half2_rn(w.x, w.y);
}

// ========== conv2 aggregate + residual + LN2 (fp16 gathers) =================
__global__ __launch_bounds__(256) void conv2_ln(const __half2* __restrict__ h2,
                                                const float* __restrict__ h2fw,
                                                const float* __restrict__ as2,
                                                const float* __restrict__ ad2,
                                                const int* __restrict__ off,
                                                const int* __restrict__ csr,
                                                const float* __restrict__ b2,
                                                const float* __restrict__ finalb,
                                                const float* __restrict__ g2,
                                                const float* __restrict__ bt2,
                                                float* __restrict__ out) {
    __shared__ float sal[8][CAP];
    int gwarp = (blockIdx.x * blockDim.x + threadIdx.x) >> 5;
    int lane = threadIdx.x & 31;
    if (gwarp >= NN) return;
    int v = gwarp;
    float* sm = sal[threadIdx.x >> 5];
    int s0 = off[v];
    int d = off[v + 1] - s0;
    float adv = ad2[v], asv = as2[v];
    float eself = lrelu(asv + adv);
    float m = eself;
    float2 acc;

    if (d <= CAP) {
        for (int j = lane; j < d; j += 32) {
            int s = csr[s0 + j];
            float e = lrelu(as2[s] + adv);
            sm[j] = e;
            m = fmaxf(m, e);
        }
        m = wredmax(m);
        float den = (lane == 0) ? __expf(eself - m) : 0.f;
        for (int j = lane; j < d; j += 32) {
            float e = __expf(sm[j] - m);
            sm[j] = e;
            den += e;
        }
        den = wredsum(den);
        float inv = 1.f / (den + 1e-16f);
        __syncwarp();

        float al = __expf(eself - m) * inv;
        float2 xs = __half22float2(h2[(long)v * 32 + lane]);
        acc = make_float2(al * xs.x, al * xs.y);
        int j = 0;
        for (; j + 4 <= d; j += 4) {
            int sA = csr[s0 + j], sB = csr[s0 + j + 1];
            int sC = csr[s0 + j + 2], sD = csr[s0 + j + 3];
            float aA = sm[j] * inv, aB = sm[j + 1] * inv;
            float aC = sm[j + 2] * inv, aD = sm[j + 3] * inv;
            float2 xA = __half22float2(h2[(long)sA * 32 + lane]);
            float2 xB = __half22float2(h2[(long)sB * 32 + lane]);
            float2 xC = __half22float2(h2[(long)sC * 32 + lane]);
            float2 xD = __half22float2(h2[(long)sD * 32 + lane]);
            acc.x += aA * xA.x + aB * xB.x + aC * xC.x + aD * xD.x;
            acc.y += aA * xA.y + aB * xB.y + aC * xC.y + aD * xD.y;
        }
        for (; j < d; j++) {
            int s = csr[s0 + j];
            float a = sm[j] * inv;
            float2 x = __half22float2(h2[(long)s * 32 + lane]);
            acc.x += a * x.x;
            acc.y += a * x.y;
        }
    } else {
        for (int j = lane; j < d; j += 32) {
            int s = csr[s0 + j];
            m = fmaxf(m, lrelu(as2[s] + adv));
        }
        m = wredmax(m);
        float den = (lane == 0) ? __expf(eself - m) : 0.f;
        for (int j = lane; j < d; j += 32) {
            int s = csr[s0 + j];
            den += __expf(lrelu(as2[s] + adv) - m);
        }
        den = wredsum(den);
        float inv = 1.f / (den + 1e-16f);
        float al = __expf(eself - m) * inv;
        float2 xs = __half22float2(h2[(long)v * 32 + lane]);
        acc = make_float2(al * xs.x, al * xs.y);
        for (int j = 0; j < d; j++) {
            int s = csr[s0 + j];
            float a = __expf(lrelu(as2[s] + adv) - m) * inv;
            float2 x = __half22float2(h2[(long)s * 32 + lane]);
            acc.x += a * x.x;
            acc.y += a * x.y;
        }
    }

    int c0 = 2 * lane, c1 = 2 * lane + 1;
    float2 fw = *(const float2*)(h2fw + (long)v * 128 + 64 + c0);
    acc.x += b2[c0] + fw.x + finalb[c0];
    acc.y += b2[c1] + fw.y + finalb[c1];
    float sum = wredsum(acc.x + acc.y);
    float mu = sum * (1.f / 64.f);
    float d0 = acc.x - mu, d1 = acc.y - mu;
    float vs = wredsum(d0 * d0 + d1 * d1);
    float istd = rsqrtf(vs * (1.f / 64.f) + 1e-5f);
    float2 r;
    r.x = d0 * istd * g2[c0] + bt2[c0];
    r.y = d1 * istd * g2[c1] + bt2[c1];
    ((float2*)out)[(long)v * 32 + lane] = r;
}

__global__ void write_w(const float* __restrict__ ha, float* __restrict__ out) {
    if (threadIdx.x == 0) {
        float a0 = ha[0], a1 = ha[1];
        float mx = fmaxf(a0, a1);
        float e0 = __expf(a0 - mx), e1 = __expf(a1 - mx);
        float inv = 1.f / (e0 + e1);
        out[NN * 64 + 0] = e0 * inv;
        out[NN * 64 + 1] = e1 * inv;
    }
}

// ================= launch ===================================================
extern "C" void kernel_launch(void* const* d_in, const int* in_sizes, int n_in,
                              void* d_out, int out_size) {
    const float* x = (const float*)d_in[0];
    const int* ei = (const int*)d_in[1];
    const int* ei2 = (const int*)d_in[2];
    const float* W1 = (const float*)d_in[3];
    const float* att_src1 = (const float*)d_in[4];
    const float* att_dst1 = (const float*)d_in[5];
    const float* b1 = (const float*)d_in[6];
    const float* W2 = (const float*)d_in[7];
    const float* att_src2 = (const float*)d_in[8];
    const float* att_dst2 = (const float*)d_in[9];
    const float* b2 = (const float*)d_in[10];
    const float* ha = (const float*)d_in[11];
    const float* skipW = (const float*)d_in[12];
    const float* skipb = (const float*)d_in[13];
    const float* finalW = (const float*)d_in[14];
    const float* finalb = (const float*)d_in[15];
    const float* ln1g = (const float*)d_in[16];
    const float* ln1b = (const float*)d_in[17];
    const float* ln2g = (const float*)d_in[18];
    const float* ln2b = (const float*)d_in[19];
    float* out = (float*)d_out;

    GS* g = nullptr;
    cudaGetSymbolAddress((void**)&g, gs);

    const int GSMEM = 2 * 40960;      // split kernel: 2-stage
    const int GSMEMF = 3 * 20480;     // f16 kernel: 3-stage
    cudaFuncSetAttribute(hmma_gemm, cudaFuncAttributeMaxDynamicSharedMemorySize, GSMEM);
    cudaFuncSetAttribute(hmma_gemm_f16, cudaFuncAttributeMaxDynamicSharedMemorySize, GSMEMF);

    const int TB = 256;
    int eb = (EE + TB - 1) / TB;
    int nb = (NN + TB - 1) / TB;
    int wb = (NN + 7) / 8;

    // operand prep
    split_x<<<(NN * 256 + TB - 1) / TB, TB>>>(x, g->xh, g->xl, g->xf, NN * 256);
    pack_B1f<<<(512 * 256 + TB - 1) / TB, TB>>>(W1, g->B1f);
    pack_skip<<<(256 * 256 + TB - 1) / TB, TB>>>(skipW, g->Bsh, g->Bsl);
    pack_B2<<<(128 * 256 + TB - 1) / TB, TB>>>(W2, finalW, g->B2h, g->B2l);

    // GEMM1a (fp16 single pass): x @ [W1_0 | W1_1] -> h0f, h1f
    {
        dim3 grid(4, (NN + 127) / 128);
        hmma_gemm_f16<<<grid, 256, GSMEMF>>>(g->xf, g->B1f, g->h0f, g->h1f, NN);
    }
    // GEMM1b (bf16 split): x @ skip_W -> skb (fp32)
    {
        dim3 grid(2, (NN + 127) / 128);
        hmma_gemm<<<grid, 256, GSMEM>>>(g->xh, g->xl, g->Bsh, g->Bsl, g->skb, NN, 256);
    }

    // CSR build
    zero_int<<<(2 * NN + TB - 1) / TB, TB>>>(g->deg0, 2 * NN);
    hist_kernel<<<eb, TB>>>(ei + EE, g->deg0);
    hist_kernel<<<eb, TB>>>(ei2 + EE, g->deg1);
    scan_kernel<<<1, 1024>>>(g->deg0, g->off0, g->cur0);
    scan_kernel<<<1, 1024>>>(g->deg1, g->off1, g->cur1);
    scatter_kernel<<<eb, TB>>>(ei, ei + EE, g->cur0, g->csr0);
    scatter_kernel<<<eb, TB>>>(ei2, ei2 + EE, g->cur1, g->csr1);

    // logits per hop
    logits8<<<(NN * 8 + TB - 1) / TB, TB>>>((const __half2*)g->h0f, att_src1, att_dst1,
                                            g->as0, g->ad0);
    logits8<<<(NN * 8 + TB - 1) / TB, TB>>>((const __half2*)g->h1f, att_src1 + 256,
                                            att_dst1 + 256, g->as1, g->ad1);

    // GAT aggregation per hop
    gat_agg8<<<wb, TB>>>((const __half2*)g->h0f, g->as0, g->ad0, g->off0, g->csr0, g->agg0);
    gat_agg8<<<wb, TB>>>((const __half2*)g->h1f, g->as1, g->ad1, g->off1, g->csr1, g->agg1);

    // combine + skip + LN1 -> bf16 split
    combine_ln<<<wb, TB>>>(g->agg0, g->agg1, g->skb, b1, skipb, ha, ln1g, ln1b, g->fxh, g->fxl);

    // GEMM2 (bf16 split): first @ [W2 | final_W] -> h2fw (fp32)
    {
        dim3 grid(1, (NN + 127) / 128);
        hmma_gemm<<<grid, 256, GSMEM>>>(g->fxh, g->fxl, g->B2h, g->B2l, g->h2fw, NN, 128);
    }

    conv_h2<<<(NN * 32 + TB - 1) / TB, TB>>>(g->h2fw, (__half2*)g->h2f);
    logits1<<<nb, TB>>>((const __half2*)g->h2f, att_src2, att_dst2, g->as2, g->ad2);
    conv2_ln<<<wb, TB>>>((const __half2*)g->h2f, g->h2fw, g->as2, g->ad2, g->off0, g->csr0,
                         b2, finalb, ln2g, ln2b, out);
    write_w<<<1, 32>>>(ha, out);
}

// round 8
// speedup vs baseline: 2.5215x; 1.2622x over previous
#include <cuda_runtime.h>
#include <cuda_bf16.h>
#include <cuda_fp16.h>
#include <math.h>
#include <stdint.h>

#define NN 50000
#define EE 800000
#define CAP 64

// ================= scratch ==================================================
struct GS {
    float skb[(size_t)NN * 256];
    float agg0[(size_t)NN * 256];
    float agg1[(size_t)NN * 256];
    float h2fw[(size_t)NN * 128];
    __half h0f[(size_t)NN * 256];
    __half h1f[(size_t)NN * 256];
    __half h2f[(size_t)NN * 64];
    float as0[NN * 8], ad0[NN * 8], as1[NN * 8], ad1[NN * 8];
    float as2[NN], ad2[NN];
    __half xf[(size_t)NN * 256];
    __nv_bfloat16 fxh[(size_t)NN * 256], fxl[(size_t)NN * 256];
    __half B1f[768 * 256];
    __nv_bfloat16 B2h[128 * 256], B2l[128 * 256];
    int deg0[NN], deg1[NN];
    int off0[NN + 1], off1[NN + 1];
    int cur0[NN], cur1[NN];
    int csr0[EE], csr1[EE];
};
__device__ GS gs;

// ================= helpers ==================================================
__device__ __forceinline__ float wredsum(float v) {
#pragma unroll
    for (int o = 16; o; o >>= 1) v += __shfl_xor_sync(0xffffffffu, v, o);
    return v;
}
__device__ __forceinline__ float wredmax(float v) {
#pragma unroll
    for (int o = 16; o; o >>= 1) v = fmaxf(v, __shfl_xor_sync(0xffffffffu, v, o));
    return v;
}
__device__ __forceinline__ float lrelu(float x) { return fmaxf(x, 0.2f * x); }
__device__ __forceinline__ uint32_t smem_u32(const void* p) {
    uint32_t a;
    asm("{ .reg .u64 t; cvta.to.shared.u64 t, %1; cvt.u32.u64 %0, t; }" : "=r"(a) : "l"(p));
    return a;
}
__device__ __forceinline__ void cp16(uint32_t dst, const void* src, bool v) {
    int bytes = v ? 16 : 0;
    asm volatile("cp.async.cg.shared.global [%0], [%1], 16, %2;\n"
                 :: "r"(dst), "l"(src), "r"(bytes));
}
__device__ __forceinline__ void ldsm4(uint32_t* r, uint32_t addr) {
    asm volatile("ldmatrix.sync.aligned.m8n8.x4.shared.b16 {%0,%1,%2,%3}, [%4];\n"
                 : "=r"(r[0]), "=r"(r[1]), "=r"(r[2]), "=r"(r[3]) : "r"(addr));
}
__device__ __forceinline__ void mma_bf16(float* d, const uint32_t* a, uint32_t b0, uint32_t b1) {
    asm volatile(
        "mma.sync.aligned.m16n8k16.row.col.f32.bf16.bf16.f32 "
        "{%0,%1,%2,%3}, {%4,%5,%6,%7}, {%8,%9}, {%0,%1,%2,%3};\n"
        : "+f"(d[0]), "+f"(d[1]), "+f"(d[2]), "+f"(d[3])
        : "r"(a[0]), "r"(a[1]), "r"(a[2]), "r"(a[3]), "r"(b0), "r"(b1));
}
__device__ __forceinline__ void mma_f16(float* d, const uint32_t* a, uint32_t b0, uint32_t b1) {
    asm volatile(
        "mma.sync.aligned.m16n8k16.row.col.f32.f16.f16.f32 "
        "{%0,%1,%2,%3}, {%4,%5,%6,%7}, {%8,%9}, {%0,%1,%2,%3};\n"
        : "+f"(d[0]), "+f"(d[1]), "+f"(d[2]), "+f"(d[3])
        : "r"(a[0]), "r"(a[1]), "r"(a[2]), "r"(a[3]), "r"(b0), "r"(b1));
}
// acc[0..3] (float2 each, 8 channels) += a * (8 halves in r)
__device__ __forceinline__ void fma8(float2* acc, uint4 r, float a) {
    float2 x0 = __half22float2(*(__half2*)&r.x);
    float2 x1 = __half22float2(*(__half2*)&r.y);
    float2 x2 = __half22float2(*(__half2*)&r.z);
    float2 x3 = __half22float2(*(__half2*)&r.w);
    acc[0].x += a * x0.x; acc[0].y += a * x0.y;
    acc[1].x += a * x1.x; acc[1].y += a * x1.y;
    acc[2].x += a * x2.x; acc[2].y += a * x2.y;
    acc[3].x += a * x3.x; acc[3].y += a * x3.y;
}

// ================= CSR build (merged launches) ==============================
__global__ void zero_int(int* p, int n) {
    int i = blockIdx.x * blockDim.x + threadIdx.x;
    if (i < n) p[i] = 0;
}
__global__ void hist2(const int* __restrict__ d0, const int* __restrict__ d1,
                      int* __restrict__ deg0, int* __restrict__ deg1) {
    int i = blockIdx.x * blockDim.x + threadIdx.x;
    if (i < EE) atomicAdd(&deg0[d0[i]], 1);
    else if (i < 2 * EE) atomicAdd(&deg1[d1[i - EE]], 1);
}
__global__ void scan2(const int* __restrict__ deg0, int* __restrict__ off0, int* __restrict__ cur0,
                      const int* __restrict__ deg1, int* __restrict__ off1, int* __restrict__ cur1) {
    __shared__ int sh[1024];
    const int* deg = blockIdx.x ? deg1 : deg0;
    int* off = blockIdx.x ? off1 : off0;
    int* cur = blockIdx.x ? cur1 : cur0;
    const int n = NN;
    int t = threadIdx.x;
    int chunk = (n + 1023) >> 10;
    int s = t * chunk;
    int e = min(s + chunk, n);
    int sum = 0;
    for (int i = s; i < e; i++) sum += deg[i];
    sh[t] = sum;
    __syncthreads();
#pragma unroll
    for (int o = 1; o < 1024; o <<= 1) {
        int val = (t >= o) ? sh[t - o] : 0;
        __syncthreads();
        sh[t] += val;
        __syncthreads();
    }
    int run = sh[t] - sum;
    for (int i = s; i < e; i++) {
        off[i] = run;
        cur[i] = run;
        run += deg[i];
    }
    if (t == 1023) off[n] = sh[1023];
}
__global__ void scatter2(const int* __restrict__ e0, const int* __restrict__ e1,
                         int* __restrict__ cur0, int* __restrict__ cur1,
                         int* __restrict__ csr0, int* __restrict__ csr1) {
    int i = blockIdx.x * blockDim.x + threadIdx.x;
    if (i < EE) {
        int d = e0[EE + i];
        int p = atomicAdd(&cur0[d], 1);
        csr0[p] = e0[i];
    } else if (i < 2 * EE) {
        int j = i - EE;
        int d = e1[EE + j];
        int p = atomicAdd(&cur1[d], 1);
        csr1[p] = e1[j];
    }
}

// ================= operand packing ==========================================
__global__ void split_x(const float* __restrict__ x, __half* __restrict__ xf, int n) {
    int i = blockIdx.x * blockDim.x + threadIdx.x;
    if (i < n) xf[i] = __float2half_rn(x[i]);
}
__global__ void pack_B1f(const float* __restrict__ W1, const float* __restrict__ skipW,
                         __half* __restrict__ Bf) {
    int i = blockIdx.x * blockDim.x + threadIdx.x;
    if (i >= 768 * 256) return;
    int n = i / 256, k = i % 256;
    float v;
    if (n < 256) v = W1[k * 256 + n];
    else if (n < 512) v = W1[65536 + k * 256 + (n - 256)];
    else v = skipW[k * 256 + (n - 512)];
    Bf[i] = __float2half_rn(v);
}
__global__ void pack_B2(const float* __restrict__ W2, const float* __restrict__ finalW,
                        __nv_bfloat16* __restrict__ Bh, __nv_bfloat16* __restrict__ Bl) {
    int i = blockIdx.x * blockDim.x + threadIdx.x;
    if (i >= 128 * 256) return;
    int n = i / 256, k = i % 256;
    float v = (n < 64) ? W2[k * 64 + n] : finalW[k * 64 + (n - 64)];
    __nv_bfloat16 h = __float2bfloat16(v);
    Bh[i] = h;
    Bl[i] = __float2bfloat16(v - __bfloat162float(h));
}

// ====== fp16 single-pass HMMA GEMM: A[M,256] @ B[768,256]^T =================
// Buckets: 0 -> H0 (fp16), 1 -> H1 (fp16), 2 -> C2 (fp32 skb).
__global__ __launch_bounds__(256, 2) void hmma_gemm_f16(
    const __half* __restrict__ A, const __half* __restrict__ B,
    __half* __restrict__ H0, __half* __restrict__ H1, float* __restrict__ C2, int M) {
    extern __shared__ char sm[];
    const int tid = threadIdx.x, lane = tid & 31, warp = tid >> 5;
    const int wm = warp & 1, wn = warp >> 1;
    const int m0 = blockIdx.y * 128, n0 = blockIdx.x * 128;
    uint32_t sbase = smem_u32(sm);

    float acc[4][4][4];
#pragma unroll
    for (int a = 0; a < 4; a++)
#pragma unroll
        for (int b = 0; b < 4; b++)
#pragma unroll
            for (int q = 0; q < 4; q++) acc[a][b][q] = 0.f;

#define LOADF(c, s)                                                               \
    do {                                                                          \
        uint32_t sb_ = sbase + (s) * 20480;                                       \
        _Pragma("unroll") for (int it = 0; it < 2; it++) {                        \
            int idx = tid + it * 256;                                             \
            int row = idx >> 2, kc = idx & 3;                                     \
            uint32_t so = row * 80 + kc * 16;                                     \
            bool va = (m0 + row) < M;                                             \
            long ga = (long)(m0 + row) * 256 + (c) * 32 + kc * 8;                 \
            if (!va) ga = 0;                                                      \
            cp16(sb_ + so, A + ga, va);                                           \
            long gb = (long)(n0 + row) * 256 + (c) * 32 + kc * 8;                 \
            cp16(sb_ + 10240 + so, B + gb, true);                                 \
        }                                                                         \
        asm volatile("cp.async.commit_group;\n" ::: "memory");                    \
    } while (0)

    LOADF(0, 0);
    LOADF(1, 1);
    for (int c = 0; c < 8; c++) {
        if (c + 2 < 8) LOADF(c + 2, (c + 2) % 3);
        if (c < 6) asm volatile("cp.async.wait_group 2;\n" ::: "memory");
        else if (c == 6) asm volatile("cp.async.wait_group 1;\n" ::: "memory");
        else asm volatile("cp.async.wait_group 0;\n" ::: "memory");
        __syncthreads();
        uint32_t sb = sbase + (c % 3) * 20480;
#pragma unroll
        for (int ks = 0; ks < 2; ks++) {
            uint32_t ah[4][4], bh[2][4];
            int acol = ks * 16 + 8 * (lane >> 4);
            int arowl = (lane & 15);
#pragma unroll
            for (int mf = 0; mf < 4; mf++) {
                int arow = wm * 64 + mf * 16 + arowl;
                ldsm4(ah[mf], sb + arow * 80 + acol * 2);
            }
            int bcol = ks * 16 + 8 * ((lane >> 3) & 1);
            int browl = (lane & 7) + 8 * (lane >> 4);
#pragma unroll
            for (int p = 0; p < 2; p++) {
                int brow = wn * 32 + p * 16 + browl;
                ldsm4(bh[p], sb + 10240 + brow * 80 + bcol * 2);
            }
#pragma unroll
            for (int mf = 0; mf < 4; mf++)
#pragma unroll
                for (int p = 0; p < 2; p++)
#pragma unroll
                    for (int sub = 0; sub < 2; sub++) {
                        int nf = p * 2 + sub;
                        mma_f16(acc[mf][nf], ah[mf], bh[p][sub * 2], bh[p][sub * 2 + 1]);
                    }
        }
        __syncthreads();
    }
#undef LOADF

    int bucket = n0 >> 8;
    int cb = n0 & 255;
    int group = lane >> 2, q = lane & 3;
    if (bucket < 2) {
        __half2* H = (__half2*)((bucket == 0) ? H0 : H1);
#pragma unroll
        for (int mf = 0; mf < 4; mf++) {
            int r0 = m0 + wm * 64 + mf * 16 + group;
#pragma unroll
            for (int nf = 0; nf < 4; nf++) {
                int col = cb + wn * 32 + nf * 8 + q * 2;
                if (r0 < M)
                    H[(long)r0 * 128 + col / 2] =
                        __floats2half2_rn(acc[mf][nf][0], acc[mf][nf][1]);
                if (r0 + 8 < M)
                    H[(long)(r0 + 8) * 128 + col / 2] =
                        __floats2half2_rn(acc[mf][nf][2], acc[mf][nf][3]);
            }
        }
    } else {
#pragma unroll
        for (int mf = 0; mf < 4; mf++) {
            int r0 = m0 + wm * 64 + mf * 16 + group;
#pragma unroll
            for (int nf = 0; nf < 4; nf++) {
                int col = cb + wn * 32 + nf * 8 + q * 2;
                if (r0 < M)
                    *(float2*)(C2 + (long)r0 * 256 + col) =
                        make_float2(acc[mf][nf][0], acc[mf][nf][1]);
                if (r0 + 8 < M)
                    *(float2*)(C2 + (long)(r0 + 8) * 256 + col) =
                        make_float2(acc[mf][nf][2], acc[mf][nf][3]);
            }
        }
    }
}

// ====== bf16-split HMMA GEMM (3 MMA): C[M,split] fp32 =======================
__global__ __launch_bounds__(256, 2) void hmma_gemm(
    const __nv_bfloat16* __restrict__ Ah, const __nv_bfloat16* __restrict__ Al,
    const __nv_bfloat16* __restrict__ Bh, const __nv_bfloat16* __restrict__ Bl,
    float* __restrict__ C, int M, int split) {
    extern __shared__ char sm[];
    const int tid = threadIdx.x, lane = tid & 31, warp = tid >> 5;
    const int wm = warp & 1, wn = warp >> 1;
    const int m0 = blockIdx.y * 128, n0 = blockIdx.x * 128;
    uint32_t sbase = smem_u32(sm);

    float acc[4][4][4];
#pragma unroll
    for (int a = 0; a < 4; a++)
#pragma unroll
        for (int b = 0; b < 4; b++)
#pragma unroll
            for (int q = 0; q < 4; q++) acc[a][b][q] = 0.f;

#define LOAD_STAGE(c, s)                                                          \
    do {                                                                          \
        uint32_t sb_ = sbase + (s) * 40960;                                       \
        _Pragma("unroll") for (int it = 0; it < 2; it++) {                        \
            int idx = tid + it * 256;                                             \
            int row = idx >> 2, kc = idx & 3;                                     \
            uint32_t so = row * 80 + kc * 16;                                     \
            bool va = (m0 + row) < M;                                             \
            long ga = (long)(m0 + row) * 256 + (c) * 32 + kc * 8;                 \
            if (!va) ga = 0;                                                      \
            cp16(sb_ + so, Ah + ga, va);                                          \
            cp16(sb_ + 10240 + so, Al + ga, va);                                  \
            long gb = (long)(n0 + row) * 256 + (c) * 32 + kc * 8;                 \
            cp16(sb_ + 20480 + so, Bh + gb, true);                                \
            cp16(sb_ + 30720 + so, Bl + gb, true);                                \
        }                                                                         \
        asm volatile("cp.async.commit_group;\n" ::: "memory");                    \
    } while (0)

    LOAD_STAGE(0, 0);
    for (int c = 0; c < 8; c++) {
        if (c < 7) {
            LOAD_STAGE(c + 1, (c + 1) & 1);
            asm volatile("cp.async.wait_group 1;\n" ::: "memory");
        } else {
            asm volatile("cp.async.wait_group 0;\n" ::: "memory");
        }
        __syncthreads();
        uint32_t sb = sbase + (c & 1) * 40960;
#pragma unroll
        for (int ks = 0; ks < 2; ks++) {
            uint32_t ah[4][4], al[4][4], bhf[2][4], blf[2][4];
            int acol = ks * 16 + 8 * (lane >> 4);
            int arowl = (lane & 15);
#pragma unroll
            for (int mf = 0; mf < 4; mf++) {
                int arow = wm * 64 + mf * 16 + arowl;
                uint32_t ad = sb + arow * 80 + acol * 2;
                ldsm4(ah[mf], ad);
                ldsm4(al[mf], ad + 10240);
            }
            int bcol = ks * 16 + 8 * ((lane >> 3) & 1);
            int browl = (lane & 7) + 8 * (lane >> 4);
#pragma unroll
            for (int p = 0; p < 2; p++) {
                int brow = wn * 32 + p * 16 + browl;
                uint32_t bd = sb + 20480 + brow * 80 + bcol * 2;
                ldsm4(bhf[p], bd);
                ldsm4(blf[p], bd + 10240);
            }
#pragma unroll
            for (int mf = 0; mf < 4; mf++)
#pragma unroll
                for (int p = 0; p < 2; p++)
#pragma unroll
                    for (int sub = 0; sub < 2; sub++) {
                        int nf = p * 2 + sub;
                        uint32_t h0 = bhf[p][sub * 2], h1 = bhf[p][sub * 2 + 1];
                        uint32_t l0 = blf[p][sub * 2], l1 = blf[p][sub * 2 + 1];
                        mma_bf16(acc[mf][nf], ah[mf], h0, h1);
                        mma_bf16(acc[mf][nf], ah[mf], l0, l1);
                        mma_bf16(acc[mf][nf], al[mf], h0, h1);
                    }
        }
        __syncthreads();
    }
#undef LOAD_STAGE

    int cb = n0 % split;
    int group = lane >> 2, q = lane & 3;
#pragma unroll
    for (int mf = 0; mf < 4; mf++) {
        int r0 = m0 + wm * 64 + mf * 16 + group;
#pragma unroll
        for (int nf = 0; nf < 4; nf++) {
            int col = cb + wn * 32 + nf * 8 + q * 2;
            if (r0 < M)
                *(float2*)(C + (long)r0 * split + col) =
                    make_float2(acc[mf][nf][0], acc[mf][nf][1]);
            if (r0 + 8 < M)
                *(float2*)(C + (long)(r0 + 8) * split + col) =
                    make_float2(acc[mf][nf][2], acc[mf][nf][3]);
        }
    }
}

// ================= attention logits (fp16 features) =========================
__global__ void logits8(const __half2* __restrict__ h, const float* __restrict__ a_src,
                        const float* __restrict__ a_dst, float* __restrict__ as,
                        float* __restrict__ ad) {
    int t = blockIdx.x * blockDim.x + threadIdx.x;
    if (t >= NN * 8) return;
    int v = t >> 3, k = t & 7;
    const __half2* hr = h + (long)v * 128 + k * 16;
    const float* sv = a_src + k * 32;
    const float* dv = a_dst + k * 32;
    float s = 0.f, d = 0.f;
#pragma unroll
    for (int c = 0; c < 16; c++) {
        float2 hv = __half22float2(hr[c]);
        s += hv.x * sv[2 * c] + hv.y * sv[2 * c + 1];
        d += hv.x * dv[2 * c] + hv.y * dv[2 * c + 1];
    }
    as[t] = s;
    ad[t] = d;
}
__global__ void logits1(const __half2* __restrict__ h2, const float* __restrict__ a_src,
                        const float* __restrict__ a_dst, float* __restrict__ as,
                        float* __restrict__ ad) {
    int v = blockIdx.x * blockDim.x + threadIdx.x;
    if (v >= NN) return;
    const __half2* hr = h2 + (long)v * 32;
    float s = 0.f, d = 0.f;
#pragma unroll
    for (int c = 0; c < 32; c++) {
        float2 hv = __half22float2(hr[c]);
        s += hv.x * a_src[2 * c] + hv.y * a_src[2 * c + 1];
        d += hv.x * a_dst[2 * c] + hv.y * a_dst[2 * c + 1];
    }
    as[v] = s;
    ad[v] = d;
}

// ====== GAT aggregation: warp/dst, lane = 8 contiguous channels =============
__global__ __launch_bounds__(256) void gat_agg8(const __half* __restrict__ h,
                                                const float* __restrict__ as,
                                                const float* __restrict__ ad,
                                                const int* __restrict__ off,
                                                const int* __restrict__ csr,
                                                float* __restrict__ out) {
    __shared__ float sal[8][CAP * 9];
    int gwarp = (blockIdx.x * blockDim.x + threadIdx.x) >> 5;
    int lane = threadIdx.x & 31;
    if (gwarp >= NN) return;
    int v = gwarp;
    float* sm = sal[threadIdx.x >> 5];
    int s0 = off[v], d = off[v + 1] - s0;
    int head = lane >> 2;  // this lane's 8 channels all live in this head

    float adv[8], asv[8];
    {
        float4 a0 = *(const float4*)(ad + v * 8);
        float4 a1 = *(const float4*)(ad + v * 8 + 4);
        adv[0] = a0.x; adv[1] = a0.y; adv[2] = a0.z; adv[3] = a0.w;
        adv[4] = a1.x; adv[5] = a1.y; adv[6] = a1.z; adv[7] = a1.w;
        float4 b0 = *(const float4*)(as + v * 8);
        float4 b1 = *(const float4*)(as + v * 8 + 4);
        asv[0] = b0.x; asv[1] = b0.y; asv[2] = b0.z; asv[3] = b0.w;
        asv[4] = b1.x; asv[5] = b1.y; asv[6] = b1.z; asv[7] = b1.w;
    }
    float m[8], den[8];
#pragma unroll
    for (int k = 0; k < 8; k++) m[k] = lrelu(asv[k] + adv[k]);

    bool fits = (d <= CAP);
    if (fits) {
        // pass A: raw logits -> smem (stride 9: conflict-free), running max
        for (int j = lane; j < d; j += 32) {
            int s = csr[s0 + j];
            float4 a0 = *(const float4*)(as + s * 8);
            float4 a1 = *(const float4*)(as + s * 8 + 4);
            float ev[8] = {a0.x, a0.y, a0.z, a0.w, a1.x, a1.y, a1.z, a1.w};
#pragma unroll
            for (int k = 0; k < 8; k++) {
                float e = lrelu(ev[k] + adv[k]);
                sm[j * 9 + k] = e;
                m[k] = fmaxf(m[k], e);
            }
        }
#pragma unroll
        for (int k = 0; k < 8; k++) m[k] = wredmax(m[k]);
        // pass B: exp in place + denom
#pragma unroll
        for (int k = 0; k < 8; k++)
            den[k] = (lane == 0) ? __expf(lrelu(asv[k] + adv[k]) - m[k]) : 0.f;
        for (int j = lane; j < d; j += 32) {
#pragma unroll
            for (int k = 0; k < 8; k++) {
                float e = __expf(sm[j * 9 + k] - m[k]);
                sm[j * 9 + k] = e;
                den[k] += e;
            }
        }
#pragma unroll
        for (int k = 0; k < 8; k++) {
            den[k] = wredsum(den[k]);
            den[k] = 1.f / (den[k] + 1e-16f);
        }
        __syncwarp();
    } else {
        for (int j = lane; j < d; j += 32) {
            int s = csr[s0 + j];
#pragma unroll
            for (int k = 0; k < 8; k++) m[k] = fmaxf(m[k], lrelu(as[s * 8 + k] + adv[k]));
        }
#pragma unroll
        for (int k = 0; k < 8; k++) m[k] = wredmax(m[k]);
#pragma unroll
        for (int k = 0; k < 8; k++)
            den[k] = (lane == 0) ? __expf(lrelu(asv[k] + adv[k]) - m[k]) : 0.f;
        for (int j = lane; j < d; j += 32) {
            int s = csr[s0 + j];
#pragma unroll
            for (int k = 0; k < 8; k++)
                den[k] += __expf(lrelu(as[s * 8 + k] + adv[k]) - m[k]);
        }
#pragma unroll
        for (int k = 0; k < 8; k++) {
            den[k] = wredsum(den[k]);
            den[k] = 1.f / (den[k] + 1e-16f);
        }
    }

    // per-lane head constants via SEL chain (no dynamic register indexing)
    float msel = m[0], dsel = den[0], advsel = adv[0], slsel = asv[0] + adv[0];
#pragma unroll
    for (int k = 1; k < 8; k++)
        if (head == k) { msel = m[k]; dsel = den[k]; advsel = adv[k]; slsel = asv[k] + adv[k]; }
    float esel = __expf(lrelu(slsel) - msel) * dsel;

    float2 acc[4];
    {
        uint4 r = *((const uint4*)(h + (long)v * 256) + lane);
        acc[0] = acc[1] = acc[2] = acc[3] = make_float2(0.f, 0.f);
        fma8(acc, r, esel);
    }
    if (fits) {
        int j = 0;
        for (; j + 4 <= d; j += 4) {
            int sA = csr[s0 + j], sB = csr[s0 + j + 1];
            int sC = csr[s0 + j + 2], sD = csr[s0 + j + 3];
            uint4 rA = *((const uint4*)(h + (long)sA * 256) + lane);
            uint4 rB = *((const uint4*)(h + (long)sB * 256) + lane);
            uint4 rC = *((const uint4*)(h + (long)sC * 256) + lane);
            uint4 rD = *((const uint4*)(h + (long)sD * 256) + lane);
            float aA = sm[j * 9 + head] * dsel;
            float aB = sm[(j + 1) * 9 + head] * dsel;
            float aC = sm[(j + 2) * 9 + head] * dsel;
            float aD = sm[(j + 3) * 9 + head] * dsel;
            fma8(acc, rA, aA);
            fma8(acc, rB, aB);
            fma8(acc, rC, aC);
            fma8(acc, rD, aD);
        }
        for (; j < d; j++) {
            int s = csr[s0 + j];
            uint4 r = *((const uint4*)(h + (long)s * 256) + lane);
            fma8(acc, r, sm[j * 9 + head] * dsel);
        }
    } else {
        for (int j = 0; j < d; j++) {
            int s = csr[s0 + j];
            uint4 r = *((const uint4*)(h + (long)s * 256) + lane);
            float a = __expf(lrelu(as[s * 8 + head] + advsel) - msel) * dsel;
            fma8(acc, r, a);
        }
    }
    float4* op = (float4*)(out + (long)v * 256 + lane * 8);
    op[0] = make_float4(acc[0].x, acc[0].y, acc[1].x, acc[1].y);
    op[1] = make_float4(acc[2].x, acc[2].y, acc[3].x, acc[3].y);
}

// ========== hop combine + skip + LN1 -> bf16 split for GEMM2 ================
__global__ __launch_bounds__(256) void combine_ln(const float* __restrict__ agg0,
                                                  const float* __restrict__ agg1,
                                                  const float* __restrict__ skb,
                                                  const float* __restrict__ b1,
                                                  const float* __restrict__ skip_b,
                                                  const float* __restrict__ ha,
                                                  const float* __restrict__ g,
                                                  const float* __restrict__ bt,
                                                  __nv_bfloat16* __restrict__ fxh,
                                                  __nv_bfloat16* __restrict__ fxl) {
    int warp = (blockIdx.x * blockDim.x + threadIdx.x) >> 5;
    int lane = threadIdx.x & 31;
    if (warp >= NN) return;
    int v = warp;
    float a0h = ha[0], a1h = ha[1];
    float mx = fmaxf(a0h, a1h);
    float e0 = __expf(a0h - mx), e1 = __expf(a1h - mx);
    float inv = 1.f / (e0 + e1);
    float w0 = e0 * inv, w1 = e1 * inv;

    float vals[8];
    float sum = 0.f;
#pragma unroll
    for (int k = 0; k < 8; k++) {
        int c = k * 32 + lane;
        float x0 = agg0[(long)v * 256 + c] + b1[c];
        x0 = (x0 > 0.f) ? x0 : (__expf(x0) - 1.f);
        float x1 = agg1[(long)v * 256 + c] + b1[256 + c];
        x1 = (x1 > 0.f) ? x1 : (__expf(x1) - 1.f);
        float val = w0 * x0 + w1 * x1 + skb[(long)v * 256 + c] + skip_b[c];
        vals[k] = val;
        sum += val;
    }
    sum = wredsum(sum);
    float mu = sum * (1.f / 256.f);
    float vs = 0.f;
#pragma unroll
    for (int k = 0; k < 8; k++) {
        float dd = vals[k] - mu;
        vs += dd * dd;
    }
    vs = wredsum(vs);
    float istd = rsqrtf(vs * (1.f / 256.f) + 1e-5f);
#pragma unroll
    for (int k = 0; k < 8; k++) {
        int c = k * 32 + lane;
        float y = (vals[k] - mu) * istd * g[c] + bt[c];
        __nv_bfloat16 hi = __float2bfloat16(y);
        fxh[(long)v * 256 + c] = hi;
        fxl[(long)v * 256 + c] = __float2bfloat16(y - __bfloat162float(hi));
    }
}

// ========== fp16 copy of h2 part of h2fw ====================================
__global__ void conv_h2(const float* __restrict__ h2fw, __half2* __restrict__ h2f) {
    int i = blockIdx.x * blockDim.x + threadIdx.x;
    if (i >= NN * 32) return;
    int v = i >> 5, c = i & 31;
    float2 w = ((const float2*)(h2fw + (long)v * 128))[c];
    h2f[i] = __floats2half2_rn(w.x, w.y);
}

// ========== conv2 aggregate + residual + LN2 (4-edge groups) ================
__global__ __launch_bounds__(256) void conv2_ln(const __half* __restrict__ h2,
                                                const float* __restrict__ h2fw,
                                                const float* __restrict__ as2,
                                                const float* __restrict__ ad2,
                                                const int* __restrict__ off,
                                                const int* __restrict__ csr,
                                                const float* __restrict__ b2,
                                                const float* __restrict__ finalb,
                                                const float* __restrict__ g2,
                                                const float* __restrict__ bt2,
                                                float* __restrict__ out) {
    __shared__ float sal[8][CAP];
    int gwarp = (blockIdx.x * blockDim.x + threadIdx.x) >> 5;
    int lane = threadIdx.x & 31;
    if (gwarp >= NN) return;
    int v = gwarp;
    float* sm = sal[threadIdx.x >> 5];
    int s0 = off[v], d = off[v + 1] - s0;
    int grp = lane >> 3, ch8 = lane & 7;  // grp: edge group, ch8: 8-channel chunk
    float adv = ad2[v], asv = as2[v];
    float eself = lrelu(asv + adv);
    float m = eself;
    float inv;
    bool fits = (d <= CAP);

    if (fits) {
        for (int j = lane; j < d; j += 32) {
            int s = csr[s0 + j];
            float e = lrelu(as2[s] + adv);
            sm[j] = e;
            m = fmaxf(m, e);
        }
        m = wredmax(m);
        float den = (lane == 0) ? __expf(eself - m) : 0.f;
        for (int j = lane; j < d; j += 32) {
            float e = __expf(sm[j] - m);
            sm[j] = e;
            den += e;
        }
        den = wredsum(den);
        inv = 1.f / (den + 1e-16f);
        __syncwarp();
    } else {
        for (int j = lane; j < d; j += 32) {
            int s = csr[s0 + j];
            m = fmaxf(m, lrelu(as2[s] + adv));
        }
        m = wredmax(m);
        float den = (lane == 0) ? __expf(eself - m) : 0.f;
        for (int j = lane; j < d; j += 32) {
            int s = csr[s0 + j];
            den += __expf(lrelu(as2[s] + adv) - m);
        }
        den = wredsum(den);
        inv = 1.f / (den + 1e-16f);
    }

    float2 acc[4];
    acc[0] = acc[1] = acc[2] = acc[3] = make_float2(0.f, 0.f);
    if (grp == 0) {
        uint4 r = ((const uint4*)(h2 + (long)v * 64))[ch8];
        fma8(acc, r, __expf(eself - m) * inv);
    }
    if (fits) {
        for (int j = grp; j < d; j += 4) {
            int s = csr[s0 + j];
            uint4 r = ((const uint4*)(h2 + (long)s * 64))[ch8];
            fma8(acc, r, sm[j] * inv);
        }
    } else {
        for (int j = grp; j < d; j += 4) {
            int s = csr[s0 + j];
            uint4 r = ((const uint4*)(h2 + (long)s * 64))[ch8];
            float a = __expf(lrelu(as2[s] + adv) - m) * inv;
            fma8(acc, r, a);
        }
    }
    // cross-group reduction (4 partials -> total, replicated to all groups)
#pragma unroll
    for (int i = 0; i < 4; i++) {
        acc[i].x += __shfl_xor_sync(0xffffffffu, acc[i].x, 8);
        acc[i].x += __shfl_xor_sync(0xffffffffu, acc[i].x, 16);
        acc[i].y += __shfl_xor_sync(0xffffffffu, acc[i].y, 8);
        acc[i].y += __shfl_xor_sync(0xffffffffu, acc[i].y, 16);
    }
    // residual + LN over 64 channels (each lane holds 8; replicated x4 across groups)
    float vals[8];
    float lsum = 0.f;
#pragma unroll
    for (int i = 0; i < 4; i++) {
        int c = ch8 * 8 + 2 * i;
        float r0 = acc[i].x + b2[c] + h2fw[(long)v * 128 + 64 + c] + finalb[c];
        float r1 = acc[i].y + b2[c + 1] + h2fw[(long)v * 128 + 64 + c + 1] + finalb[c + 1];
        vals[2 * i] = r0;
        vals[2 * i + 1] = r1;
        lsum += r0 + r1;
    }
    float sum = wredsum(lsum) * 0.25f;  // exact: 4 identical replicas
    float mu = sum * (1.f / 64.f);
    float lvs = 0.f;
#pragma unroll
    for (int i = 0; i < 8; i++) {
        float dd = vals[i] - mu;
        lvs += dd * dd;
    }
    float vs = wredsum(lvs) * 0.25f;
    float istd = rsqrtf(vs * (1.f / 64.f) + 1e-5f);
    if (grp == 0) {
        float o[8];
#pragma unroll
        for (int i = 0; i < 8; i++) {
            int c = ch8 * 8 + i;
            o[i] = (vals[i] - mu) * istd * g2[c] + bt2[c];
        }
        float4* op = (float4*)(out + (long)v * 64 + ch8 * 8);
        op[0] = make_float4(o[0], o[1], o[2], o[3]);
        op[1] = make_float4(o[4], o[5], o[6], o[7]);
    }
}

__global__ void write_w(const float* __restrict__ ha, float* __restrict__ out) {
    if (threadIdx.x == 0) {
        float a0 = ha[0], a1 = ha[1];
        float mx = fmaxf(a0, a1);
        float e0 = __expf(a0 - mx), e1 = __expf(a1 - mx);
        float inv = 1.f / (e0 + e1);
        out[NN * 64 + 0] = e0 * inv;
        out[NN * 64 + 1] = e1 * inv;
    }
}

// ================= launch ===================================================
extern "C" void kernel_launch(void* const* d_in, const int* in_sizes, int n_in,
                              void* d_out, int out_size) {
    const float* x = (const float*)d_in[0];
    const int* ei = (const int*)d_in[1];
    const int* ei2 = (const int*)d_in[2];
    const float* W1 = (const float*)d_in[3];
    const float* att_src1 = (const float*)d_in[4];
    const float* att_dst1 = (const float*)d_in[5];
    const float* b1 = (const float*)d_in[6];
    const float* W2 = (const float*)d_in[7];
    const float* att_src2 = (const float*)d_in[8];
    const float* att_dst2 = (const float*)d_in[9];
    const float* b2 = (const float*)d_in[10];
    const float* ha = (const float*)d_in[11];
    const float* skipW = (const float*)d_in[12];
    const float* skipb = (const float*)d_in[13];
    const float* finalW = (const float*)d_in[14];
    const float* finalb = (const float*)d_in[15];
    const float* ln1g = (const float*)d_in[16];
    const float* ln1b = (const float*)d_in[17];
    const float* ln2g = (const float*)d_in[18];
    const float* ln2b = (const float*)d_in[19];
    float* out = (float*)d_out;

    GS* g = nullptr;
    cudaGetSymbolAddress((void**)&g, gs);

    const int GSMEM = 2 * 40960;
    const int GSMEMF = 3 * 20480;
    cudaFuncSetAttribute(hmma_gemm, cudaFuncAttributeMaxDynamicSharedMemorySize, GSMEM);
    cudaFuncSetAttribute(hmma_gemm_f16, cudaFuncAttributeMaxDynamicSharedMemorySize, GSMEMF);

    const int TB = 256;
    int nb = (NN + TB - 1) / TB;
    int wb = (NN + 7) / 8;
    int eb2 = (2 * EE + TB - 1) / TB;

    // operand prep
    split_x<<<(NN * 256 + TB - 1) / TB, TB>>>(x, g->xf, NN * 256);
    pack_B1f<<<(768 * 256 + TB - 1) / TB, TB>>>(W1, skipW, g->B1f);
    pack_B2<<<(128 * 256 + TB - 1) / TB, TB>>>(W2, finalW, g->B2h, g->B2l);

    // GEMM1 (fp16): x @ [W1_0 | W1_1 | skip_W] -> h0f, h1f (fp16), skb (fp32)
    {
        dim3 grid(6, (NN + 127) / 128);
        hmma_gemm_f16<<<grid, 256, GSMEMF>>>(g->xf, g->B1f, g->h0f, g->h1f, g->skb, NN);
    }

    // CSR build (merged)
    zero_int<<<(2 * NN + TB - 1) / TB, TB>>>(g->deg0, 2 * NN);
    hist2<<<eb2, TB>>>(ei + EE, ei2 + EE, g->deg0, g->deg1);
    scan2<<<2, 1024>>>(g->deg0, g->off0, g->cur0, g->deg1, g->off1, g->cur1);
    scatter2<<<eb2, TB>>>(ei, ei2, g->cur0, g->cur1, g->csr0, g->csr1);

    // logits per hop
    logits8<<<(NN * 8 + TB - 1) / TB, TB>>>((const __half2*)g->h0f, att_src1, att_dst1,
                                            g->as0, g->ad0);
    logits8<<<(NN * 8 + TB - 1) / TB, TB>>>((const __half2*)g->h1f, att_src1 + 256,
                                            att_dst1 + 256, g->as1, g->ad1);

    // GAT aggregation per hop (vectorized gathers)
    gat_agg8<<<wb, TB>>>(g->h0f, g->as0, g->ad0, g->off0, g->csr0, g->agg0);
    gat_agg8<<<wb, TB>>>(g->h1f, g->as1, g->ad1, g->off1, g->csr1, g->agg1);

    // combine + skip + LN1 -> bf16 split
    combine_ln<<<wb, TB>>>(g->agg0, g->agg1, g->skb, b1, skipb, ha, ln1g, ln1b, g->fxh, g->fxl);

    // GEMM2 (bf16 split): first @ [W2 | final_W] -> h2fw (fp32)
    {
        dim3 grid(1, (NN + 127) / 128);
        hmma_gemm<<<grid, 256, GSMEM>>>(g->fxh, g->fxl, g->B2h, g->B2l, g->h2fw, NN, 128);
    }

    conv_h2<<<(NN * 32 + TB - 1) / TB, TB>>>(g->h2fw, (__half2*)g->h2f);
    logits1<<<nb, TB>>>((const __half2*)g->h2f, att_src2, att_dst2, g->as2, g->ad2);
    conv2_ln<<<wb, TB>>>(g->h2f, g->h2fw, g->as2, g->ad2, g->off0, g->csr0,
                         b2, finalb, ln2g, ln2b, out);
    write_w<<<1, 32>>>(ha, out);
}

// round 9
// speedup vs baseline: 2.8964x; 1.1487x over previous
#include <cuda_runtime.h>
#include <cuda_bf16.h>
#include <cuda_fp16.h>
#include <math.h>
#include <stdint.h>

#define NN 50000
#define EE 800000
#define CAP 64

// ================= scratch ==================================================
struct GS {
    float skb[(size_t)NN * 256];
    float agg0[(size_t)NN * 256];
    float agg1[(size_t)NN * 256];
    float h2fw[(size_t)NN * 128];
    __half h0f[(size_t)NN * 256];
    __half h1f[(size_t)NN * 256];
    __half h2f[(size_t)NN * 64];
    float as0[NN * 8], ad0[NN * 8], as1[NN * 8], ad1[NN * 8];
    float as2[NN], ad2[NN];
    __half xf[(size_t)NN * 256];
    __nv_bfloat16 fxh[(size_t)NN * 256], fxl[(size_t)NN * 256];
    __half B1f[768 * 256];
    __nv_bfloat16 B2h[128 * 256], B2l[128 * 256];
    int deg0[NN], deg1[NN];
    int off0[NN + 1], off1[NN + 1];
    int cur0[NN], cur1[NN];
    int csr0[EE], csr1[EE];
};
__device__ GS gs;

// ================= helpers ==================================================
__device__ __forceinline__ float wredsum(float v) {
#pragma unroll
    for (int o = 16; o; o >>= 1) v += __shfl_xor_sync(0xffffffffu, v, o);
    return v;
}
__device__ __forceinline__ float wredmax(float v) {
#pragma unroll
    for (int o = 16; o; o >>= 1) v = fmaxf(v, __shfl_xor_sync(0xffffffffu, v, o));
    return v;
}
__device__ __forceinline__ float lrelu(float x) { return fmaxf(x, 0.2f * x); }
__device__ __forceinline__ uint32_t smem_u32(const void* p) {
    uint32_t a;
    asm("{ .reg .u64 t; cvta.to.shared.u64 t, %1; cvt.u32.u64 %0, t; }" : "=r"(a) : "l"(p));
    return a;
}
__device__ __forceinline__ void cp16(uint32_t dst, const void* src, bool v) {
    int bytes = v ? 16 : 0;
    asm volatile("cp.async.cg.shared.global [%0], [%1], 16, %2;\n"
                 :: "r"(dst), "l"(src), "r"(bytes));
}
__device__ __forceinline__ void ldsm4(uint32_t* r, uint32_t addr) {
    asm volatile("ldmatrix.sync.aligned.m8n8.x4.shared.b16 {%0,%1,%2,%3}, [%4];\n"
                 : "=r"(r[0]), "=r"(r[1]), "=r"(r[2]), "=r"(r[3]) : "r"(addr));
}
__device__ __forceinline__ void mma_bf16(float* d, const uint32_t* a, uint32_t b0, uint32_t b1) {
    asm volatile(
        "mma.sync.aligned.m16n8k16.row.col.f32.bf16.bf16.f32 "
        "{%0,%1,%2,%3}, {%4,%5,%6,%7}, {%8,%9}, {%0,%1,%2,%3};\n"
        : "+f"(d[0]), "+f"(d[1]), "+f"(d[2]), "+f"(d[3])
        : "r"(a[0]), "r"(a[1]), "r"(a[2]), "r"(a[3]), "r"(b0), "r"(b1));
}
__device__ __forceinline__ void mma_f16(float* d, const uint32_t* a, uint32_t b0, uint32_t b1) {
    asm volatile(
        "mma.sync.aligned.m16n8k16.row.col.f32.f16.f16.f32 "
        "{%0,%1,%2,%3}, {%4,%5,%6,%7}, {%8,%9}, {%0,%1,%2,%3};\n"
        : "+f"(d[0]), "+f"(d[1]), "+f"(d[2]), "+f"(d[3])
        : "r"(a[0]), "r"(a[1]), "r"(a[2]), "r"(a[3]), "r"(b0), "r"(b1));
}
__device__ __forceinline__ void fma8(float2* acc, uint4 r, float a) {
    float2 x0 = __half22float2(*(__half2*)&r.x);
    float2 x1 = __half22float2(*(__half2*)&r.y);
    float2 x2 = __half22float2(*(__half2*)&r.z);
    float2 x3 = __half22float2(*(__half2*)&r.w);
    acc[0].x += a * x0.x; acc[0].y += a * x0.y;
    acc[1].x += a * x1.x; acc[1].y += a * x1.y;
    acc[2].x += a * x2.x; acc[2].y += a * x2.y;
    acc[3].x += a * x3.x; acc[3].y += a * x3.y;
}

// ================= CSR build (merged launches) ==============================
__global__ void zero_int(int* p, int n) {
    int i = blockIdx.x * blockDim.x + threadIdx.x;
    if (i < n) p[i] = 0;
}
__global__ void hist2(const int* __restrict__ d0, const int* __restrict__ d1,
                      int* __restrict__ deg0, int* __restrict__ deg1) {
    int i = blockIdx.x * blockDim.x + threadIdx.x;
    if (i < EE) atomicAdd(&deg0[d0[i]], 1);
    else if (i < 2 * EE) atomicAdd(&deg1[d1[i - EE]], 1);
}
__global__ void scan2(const int* __restrict__ deg0, int* __restrict__ off0, int* __restrict__ cur0,
                      const int* __restrict__ deg1, int* __restrict__ off1, int* __restrict__ cur1) {
    __shared__ int sh[1024];
    const int* deg = blockIdx.x ? deg1 : deg0;
    int* off = blockIdx.x ? off1 : off0;
    int* cur = blockIdx.x ? cur1 : cur0;
    const int n = NN;
    int t = threadIdx.x;
    int chunk = (n + 1023) >> 10;
    int s = t * chunk;
    int e = min(s + chunk, n);
    int sum = 0;
    for (int i = s; i < e; i++) sum += deg[i];
    sh[t] = sum;
    __syncthreads();
#pragma unroll
    for (int o = 1; o < 1024; o <<= 1) {
        int val = (t >= o) ? sh[t - o] : 0;
        __syncthreads();
        sh[t] += val;
        __syncthreads();
    }
    int run = sh[t] - sum;
    for (int i = s; i < e; i++) {
        off[i] = run;
        cur[i] = run;
        run += deg[i];
    }
    if (t == 1023) off[n] = sh[1023];
}
__global__ void scatter2(const int* __restrict__ e0, const int* __restrict__ e1,
                         int* __restrict__ cur0, int* __restrict__ cur1,
                         int* __restrict__ csr0, int* __restrict__ csr1) {
    int i = blockIdx.x * blockDim.x + threadIdx.x;
    if (i < EE) {
        int d = e0[EE + i];
        int p = atomicAdd(&cur0[d], 1);
        csr0[p] = e0[i];
    } else if (i < 2 * EE) {
        int j = i - EE;
        int d = e1[EE + j];
        int p = atomicAdd(&cur1[d], 1);
        csr1[p] = e1[j];
    }
}

// ================= operand packing ==========================================
__global__ void split_x(const float* __restrict__ x, __half* __restrict__ xf, int n) {
    int i = blockIdx.x * blockDim.x + threadIdx.x;
    if (i < n) xf[i] = __float2half_rn(x[i]);
}
__global__ void pack_B1f(const float* __restrict__ W1, const float* __restrict__ skipW,
                         __half* __restrict__ Bf) {
    int i = blockIdx.x * blockDim.x + threadIdx.x;
    if (i >= 768 * 256) return;
    int n = i / 256, k = i % 256;
    float v;
    if (n < 256) v = W1[k * 256 + n];
    else if (n < 512) v = W1[65536 + k * 256 + (n - 256)];
    else v = skipW[k * 256 + (n - 512)];
    Bf[i] = __float2half_rn(v);
}
__global__ void pack_B2(const float* __restrict__ W2, const float* __restrict__ finalW,
                        __nv_bfloat16* __restrict__ Bh, __nv_bfloat16* __restrict__ Bl) {
    int i = blockIdx.x * blockDim.x + threadIdx.x;
    if (i >= 128 * 256) return;
    int n = i / 256, k = i % 256;
    float v = (n < 64) ? W2[k * 64 + n] : finalW[k * 64 + (n - 64)];
    __nv_bfloat16 h = __float2bfloat16(v);
    Bh[i] = h;
    Bl[i] = __float2bfloat16(v - __bfloat162float(h));
}

// ====== fp16 single-pass HMMA GEMM: A[M,256] @ B[768,256]^T =================
__global__ __launch_bounds__(256, 2) void hmma_gemm_f16(
    const __half* __restrict__ A, const __half* __restrict__ B,
    __half* __restrict__ H0, __half* __restrict__ H1, float* __restrict__ C2, int M) {
    extern __shared__ char sm[];
    const int tid = threadIdx.x, lane = tid & 31, warp = tid >> 5;
    const int wm = warp & 1, wn = warp >> 1;
    const int m0 = blockIdx.y * 128, n0 = blockIdx.x * 128;
    uint32_t sbase = smem_u32(sm);

    float acc[4][4][4];
#pragma unroll
    for (int a = 0; a < 4; a++)
#pragma unroll
        for (int b = 0; b < 4; b++)
#pragma unroll
            for (int q = 0; q < 4; q++) acc[a][b][q] = 0.f;

#define LOADF(c, s)                                                               \
    do {                                                                          \
        uint32_t sb_ = sbase + (s) * 20480;                                       \
        _Pragma("unroll") for (int it = 0; it < 2; it++) {                        \
            int idx = tid + it * 256;                                             \
            int row = idx >> 2, kc = idx & 3;                                     \
            uint32_t so = row * 80 + kc * 16;                                     \
            bool va = (m0 + row) < M;                                             \
            long ga = (long)(m0 + row) * 256 + (c) * 32 + kc * 8;                 \
            if (!va) ga = 0;                                                      \
            cp16(sb_ + so, A + ga, va);                                           \
            long gb = (long)(n0 + row) * 256 + (c) * 32 + kc * 8;                 \
            cp16(sb_ + 10240 + so, B + gb, true);                                 \
        }                                                                         \
        asm volatile("cp.async.commit_group;\n" ::: "memory");                    \
    } while (0)

    LOADF(0, 0);
    LOADF(1, 1);
    for (int c = 0; c < 8; c++) {
        if (c + 2 < 8) LOADF(c + 2, (c + 2) % 3);
        if (c < 6) asm volatile("cp.async.wait_group 2;\n" ::: "memory");
        else if (c == 6) asm volatile("cp.async.wait_group 1;\n" ::: "memory");
        else asm volatile("cp.async.wait_group 0;\n" ::: "memory");
        __syncthreads();
        uint32_t sb = sbase + (c % 3) * 20480;
#pragma unroll
        for (int ks = 0; ks < 2; ks++) {
            uint32_t ah[4][4], bh[2][4];
            int acol = ks * 16 + 8 * (lane >> 4);
            int arowl = (lane & 15);
#pragma unroll
            for (int mf = 0; mf < 4; mf++) {
                int arow = wm * 64 + mf * 16 + arowl;
                ldsm4(ah[mf], sb + arow * 80 + acol * 2);
            }
            int bcol = ks * 16 + 8 * ((lane >> 3) & 1);
            int browl = (lane & 7) + 8 * (lane >> 4);
#pragma unroll
            for (int p = 0; p < 2; p++) {
                int brow = wn * 32 + p * 16 + browl;
                ldsm4(bh[p], sb + 10240 + brow * 80 + bcol * 2);
            }
#pragma unroll
            for (int mf = 0; mf < 4; mf++)
#pragma unroll
                for (int p = 0; p < 2; p++)
#pragma unroll
                    for (int sub = 0; sub < 2; sub++) {
                        int nf = p * 2 + sub;
                        mma_f16(acc[mf][nf], ah[mf], bh[p][sub * 2], bh[p][sub * 2 + 1]);
                    }
        }
        __syncthreads();
    }
#undef LOADF

    int bucket = n0 >> 8;
    int cb = n0 & 255;
    int group = lane >> 2, q = lane & 3;
    if (bucket < 2) {
        __half2* H = (__half2*)((bucket == 0) ? H0 : H1);
#pragma unroll
        for (int mf = 0; mf < 4; mf++) {
            int r0 = m0 + wm * 64 + mf * 16 + group;
#pragma unroll
            for (int nf = 0; nf < 4; nf++) {
                int col = cb + wn * 32 + nf * 8 + q * 2;
                if (r0 < M)
                    H[(long)r0 * 128 + col / 2] =
                        __floats2half2_rn(acc[mf][nf][0], acc[mf][nf][1]);
                if (r0 + 8 < M)
                    H[(long)(r0 + 8) * 128 + col / 2] =
                        __floats2half2_rn(acc[mf][nf][2], acc[mf][nf][3]);
            }
        }
    } else {
#pragma unroll
        for (int mf = 0; mf < 4; mf++) {
            int r0 = m0 + wm * 64 + mf * 16 + group;
#pragma unroll
            for (int nf = 0; nf < 4; nf++) {
                int col = cb + wn * 32 + nf * 8 + q * 2;
                if (r0 < M)
                    *(float2*)(C2 + (long)r0 * 256 + col) =
                        make_float2(acc[mf][nf][0], acc[mf][nf][1]);
                if (r0 + 8 < M)
                    *(float2*)(C2 + (long)(r0 + 8) * 256 + col) =
                        make_float2(acc[mf][nf][2], acc[mf][nf][3]);
            }
        }
    }
}

// ====== bf16-split HMMA GEMM (3 MMA) + fused fp16 mirror for cols<64 ========
__global__ __launch_bounds__(256, 2) void hmma_gemm(
    const __nv_bfloat16* __restrict__ Ah, const __nv_bfloat16* __restrict__ Al,
    const __nv_bfloat16* __restrict__ Bh, const __nv_bfloat16* __restrict__ Bl,
    float* __restrict__ C, __half* __restrict__ Hf, int M, int split) {
    extern __shared__ char sm[];
    const int tid = threadIdx.x, lane = tid & 31, warp = tid >> 5;
    const int wm = warp & 1, wn = warp >> 1;
    const int m0 = blockIdx.y * 128, n0 = blockIdx.x * 128;
    uint32_t sbase = smem_u32(sm);

    float acc[4][4][4];
#pragma unroll
    for (int a = 0; a < 4; a++)
#pragma unroll
        for (int b = 0; b < 4; b++)
#pragma unroll
            for (int q = 0; q < 4; q++) acc[a][b][q] = 0.f;

#define LOAD_STAGE(c, s)                                                          \
    do {                                                                          \
        uint32_t sb_ = sbase + (s) * 40960;                                       \
        _Pragma("unroll") for (int it = 0; it < 2; it++) {                        \
            int idx = tid + it * 256;                                             \
            int row = idx >> 2, kc = idx & 3;                                     \
            uint32_t so = row * 80 + kc * 16;                                     \
            bool va = (m0 + row) < M;                                             \
            long ga = (long)(m0 + row) * 256 + (c) * 32 + kc * 8;                 \
            if (!va) ga = 0;                                                      \
            cp16(sb_ + so, Ah + ga, va);                                          \
            cp16(sb_ + 10240 + so, Al + ga, va);                                  \
            long gb = (long)(n0 + row) * 256 + (c) * 32 + kc * 8;                 \
            cp16(sb_ + 20480 + so, Bh + gb, true);                                \
            cp16(sb_ + 30720 + so, Bl + gb, true);                                \
        }                                                                         \
        asm volatile("cp.async.commit_group;\n" ::: "memory");                    \
    } while (0)

    LOAD_STAGE(0, 0);
    for (int c = 0; c < 8; c++) {
        if (c < 7) {
            LOAD_STAGE(c + 1, (c + 1) & 1);
            asm volatile("cp.async.wait_group 1;\n" ::: "memory");
        } else {
            asm volatile("cp.async.wait_group 0;\n" ::: "memory");
        }
        __syncthreads();
        uint32_t sb = sbase + (c & 1) * 40960;
#pragma unroll
        for (int ks = 0; ks < 2; ks++) {
            uint32_t ah[4][4], al[4][4], bhf[2][4], blf[2][4];
            int acol = ks * 16 + 8 * (lane >> 4);
            int arowl = (lane & 15);
#pragma unroll
            for (int mf = 0; mf < 4; mf++) {
                int arow = wm * 64 + mf * 16 + arowl;
                uint32_t ad = sb + arow * 80 + acol * 2;
                ldsm4(ah[mf], ad);
                ldsm4(al[mf], ad + 10240);
            }
            int bcol = ks * 16 + 8 * ((lane >> 3) & 1);
            int browl = (lane & 7) + 8 * (lane >> 4);
#pragma unroll
            for (int p = 0; p < 2; p++) {
                int brow = wn * 32 + p * 16 + browl;
                uint32_t bd = sb + 20480 + brow * 80 + bcol * 2;
                ldsm4(bhf[p], bd);
                ldsm4(blf[p], bd + 10240);
            }
#pragma unroll
            for (int mf = 0; mf < 4; mf++)
#pragma unroll
                for (int p = 0; p < 2; p++)
#pragma unroll
                    for (int sub = 0; sub < 2; sub++) {
                        int nf = p * 2 + sub;
                        uint32_t h0 = bhf[p][sub * 2], h1 = bhf[p][sub * 2 + 1];
                        uint32_t l0 = blf[p][sub * 2], l1 = blf[p][sub * 2 + 1];
                        mma_bf16(acc[mf][nf], ah[mf], h0, h1);
                        mma_bf16(acc[mf][nf], ah[mf], l0, l1);
                        mma_bf16(acc[mf][nf], al[mf], h0, h1);
                    }
        }
        __syncthreads();
    }
#undef LOAD_STAGE

    int cb = n0 % split;
    int group = lane >> 2, q = lane & 3;
#pragma unroll
    for (int mf = 0; mf < 4; mf++) {
        int r0 = m0 + wm * 64 + mf * 16 + group;
#pragma unroll
        for (int nf = 0; nf < 4; nf++) {
            int col = cb + wn * 32 + nf * 8 + q * 2;
            if (r0 < M) {
                *(float2*)(C + (long)r0 * split + col) =
                    make_float2(acc[mf][nf][0], acc[mf][nf][1]);
                if (Hf && col < 64)
                    ((__half2*)Hf)[(long)r0 * 32 + col / 2] =
                        __floats2half2_rn(acc[mf][nf][0], acc[mf][nf][1]);
            }
            if (r0 + 8 < M) {
                *(float2*)(C + (long)(r0 + 8) * split + col) =
                    make_float2(acc[mf][nf][2], acc[mf][nf][3]);
                if (Hf && col < 64)
                    ((__half2*)Hf)[(long)(r0 + 8) * 32 + col / 2] =
                        __floats2half2_rn(acc[mf][nf][2], acc[mf][nf][3]);
            }
        }
    }
}

// ================= attention logits (both hops in one launch) ===============
__global__ void logits8_2(const __half2* __restrict__ h0, const __half2* __restrict__ h1,
                          const float* __restrict__ a_src, const float* __restrict__ a_dst,
                          float* __restrict__ as0, float* __restrict__ ad0,
                          float* __restrict__ as1, float* __restrict__ ad1) {
    int t = blockIdx.x * blockDim.x + threadIdx.x;
    if (t >= NN * 8) return;
    int hop = blockIdx.y;
    const __half2* h = hop ? h1 : h0;
    float* as = hop ? as1 : as0;
    float* ad = hop ? ad1 : ad0;
    int v = t >> 3, k = t & 7;
    const __half2* hr = h + (long)v * 128 + k * 16;
    const float* sv = a_src + hop * 256 + k * 32;
    const float* dv = a_dst + hop * 256 + k * 32;
    float s = 0.f, d = 0.f;
#pragma unroll
    for (int c = 0; c < 16; c++) {
        float2 hv = __half22float2(hr[c]);
        s += hv.x * sv[2 * c] + hv.y * sv[2 * c + 1];
        d += hv.x * dv[2 * c] + hv.y * dv[2 * c + 1];
    }
    as[t] = s;
    ad[t] = d;
}
__global__ void logits1(const __half2* __restrict__ h2, const float* __restrict__ a_src,
                        const float* __restrict__ a_dst, float* __restrict__ as,
                        float* __restrict__ ad) {
    int v = blockIdx.x * blockDim.x + threadIdx.x;
    if (v >= NN) return;
    const __half2* hr = h2 + (long)v * 32;
    float s = 0.f, d = 0.f;
#pragma unroll
    for (int c = 0; c < 32; c++) {
        float2 hv = __half22float2(hr[c]);
        s += hv.x * a_src[2 * c] + hv.y * a_src[2 * c + 1];
        d += hv.x * a_dst[2 * c] + hv.y * a_dst[2 * c + 1];
    }
    as[v] = s;
    ad[v] = d;
}

// ====== GAT aggregation: both hops, warp/dst, lane = 8 contiguous channels ==
__global__ __launch_bounds__(256) void gat_agg8_2(
    const __half* __restrict__ h0p, const __half* __restrict__ h1p,
    const float* __restrict__ as0, const float* __restrict__ ad0,
    const float* __restrict__ as1, const float* __restrict__ ad1,
    const int* __restrict__ off0, const int* __restrict__ csr0,
    const int* __restrict__ off1, const int* __restrict__ csr1,
    float* __restrict__ agg0, float* __restrict__ agg1) {
    __shared__ float sal[8][CAP * 9];
    int gwarp = (blockIdx.x * blockDim.x + threadIdx.x) >> 5;
    int lane = threadIdx.x & 31;
    if (gwarp >= NN) return;
    int hop = blockIdx.y;
    const __half* h = hop ? h1p : h0p;
    const float* as = hop ? as1 : as0;
    const float* ad = hop ? ad1 : ad0;
    const int* off = hop ? off1 : off0;
    const int* csr = hop ? csr1 : csr0;
    float* out = hop ? agg1 : agg0;

    int v = gwarp;
    float* sm = sal[threadIdx.x >> 5];
    int s0 = off[v], d = off[v + 1] - s0;
    int head = lane >> 2;

    float adv[8], asv[8];
    {
        float4 a0 = *(const float4*)(ad + v * 8);
        float4 a1 = *(const float4*)(ad + v * 8 + 4);
        adv[0] = a0.x; adv[1] = a0.y; adv[2] = a0.z; adv[3] = a0.w;
        adv[4] = a1.x; adv[5] = a1.y; adv[6] = a1.z; adv[7] = a1.w;
        float4 b0 = *(const float4*)(as + v * 8);
        float4 b1 = *(const float4*)(as + v * 8 + 4);
        asv[0] = b0.x; asv[1] = b0.y; asv[2] = b0.z; asv[3] = b0.w;
        asv[4] = b1.x; asv[5] = b1.y; asv[6] = b1.z; asv[7] = b1.w;
    }
    float m[8], den[8];
#pragma unroll
    for (int k = 0; k < 8; k++) m[k] = lrelu(asv[k] + adv[k]);

    bool fits = (d <= CAP);
    if (fits) {
        for (int j = lane; j < d; j += 32) {
            int s = csr[s0 + j];
            float4 a0 = *(const float4*)(as + s * 8);
            float4 a1 = *(const float4*)(as + s * 8 + 4);
            float ev[8] = {a0.x, a0.y, a0.z, a0.w, a1.x, a1.y, a1.z, a1.w};
#pragma unroll
            for (int k = 0; k < 8; k++) {
                float e = lrelu(ev[k] + adv[k]);
                sm[j * 9 + k] = e;
                m[k] = fmaxf(m[k], e);
            }
        }
#pragma unroll
        for (int k = 0; k < 8; k++) m[k] = wredmax(m[k]);
#pragma unroll
        for (int k = 0; k < 8; k++)
            den[k] = (lane == 0) ? __expf(lrelu(asv[k] + adv[k]) - m[k]) : 0.f;
        for (int j = lane; j < d; j += 32) {
#pragma unroll
            for (int k = 0; k < 8; k++) {
                float e = __expf(sm[j * 9 + k] - m[k]);
                sm[j * 9 + k] = e;
                den[k] += e;
            }
        }
#pragma unroll
        for (int k = 0; k < 8; k++) {
            den[k] = wredsum(den[k]);
            den[k] = 1.f / (den[k] + 1e-16f);
        }
        __syncwarp();
    } else {
        for (int j = lane; j < d; j += 32) {
            int s = csr[s0 + j];
#pragma unroll
            for (int k = 0; k < 8; k++) m[k] = fmaxf(m[k], lrelu(as[s * 8 + k] + adv[k]));
        }
#pragma unroll
        for (int k = 0; k < 8; k++) m[k] = wredmax(m[k]);
#pragma unroll
        for (int k = 0; k < 8; k++)
            den[k] = (lane == 0) ? __expf(lrelu(asv[k] + adv[k]) - m[k]) : 0.f;
        for (int j = lane; j < d; j += 32) {
            int s = csr[s0 + j];
#pragma unroll
            for (int k = 0; k < 8; k++)
                den[k] += __expf(lrelu(as[s * 8 + k] + adv[k]) - m[k]);
        }
#pragma unroll
        for (int k = 0; k < 8; k++) {
            den[k] = wredsum(den[k]);
            den[k] = 1.f / (den[k] + 1e-16f);
        }
    }

    float msel = m[0], dsel = den[0], advsel = adv[0], slsel = asv[0] + adv[0];
#pragma unroll
    for (int k = 1; k < 8; k++)
        if (head == k) { msel = m[k]; dsel = den[k]; advsel = adv[k]; slsel = asv[k] + adv[k]; }
    float esel = __expf(lrelu(slsel) - msel) * dsel;

    float2 acc[4];
    {
        uint4 r = *((const uint4*)(h + (long)v * 256) + lane);
        acc[0] = acc[1] = acc[2] = acc[3] = make_float2(0.f, 0.f);
        fma8(acc, r, esel);
    }
    if (fits) {
        int j = 0;
        for (; j + 4 <= d; j += 4) {
            int sA = csr[s0 + j], sB = csr[s0 + j + 1];
            int sC = csr[s0 + j + 2], sD = csr[s0 + j + 3];
            uint4 rA = *((const uint4*)(h + (long)sA * 256) + lane);
            uint4 rB = *((const uint4*)(h + (long)sB * 256) + lane);
            uint4 rC = *((const uint4*)(h + (long)sC * 256) + lane);
            uint4 rD = *((const uint4*)(h + (long)sD * 256) + lane);
            float aA = sm[j * 9 + head] * dsel;
            float aB = sm[(j + 1) * 9 + head] * dsel;
            float aC = sm[(j + 2) * 9 + head] * dsel;
            float aD = sm[(j + 3) * 9 + head] * dsel;
            fma8(acc, rA, aA);
            fma8(acc, rB, aB);
            fma8(acc, rC, aC);
            fma8(acc, rD, aD);
        }
        for (; j < d; j++) {
            int s = csr[s0 + j];
            uint4 r = *((const uint4*)(h + (long)s * 256) + lane);
            fma8(acc, r, sm[j * 9 + head] * dsel);
        }
    } else {
        for (int j = 0; j < d; j++) {
            int s = csr[s0 + j];
            uint4 r = *((const uint4*)(h + (long)s * 256) + lane);
            float a = __expf(lrelu(as[s * 8 + head] + advsel) - msel) * dsel;
            fma8(acc, r, a);
        }
    }
    float4* op = (float4*)(out + (long)v * 256 + lane * 8);
    op[0] = make_float4(acc[0].x, acc[0].y, acc[1].x, acc[1].y);
    op[1] = make_float4(acc[2].x, acc[2].y, acc[3].x, acc[3].y);
}

// ========== hop combine + skip + LN1 -> bf16 split for GEMM2 ================
__global__ __launch_bounds__(256) void combine_ln(const float* __restrict__ agg0,
                                                  const float* __restrict__ agg1,
                                                  const float* __restrict__ skb,
                                                  const float* __restrict__ b1,
                                                  const float* __restrict__ skip_b,
                                                  const float* __restrict__ ha,
                                                  const float* __restrict__ g,
                                                  const float* __restrict__ bt,
                                                  __nv_bfloat16* __restrict__ fxh,
                                                  __nv_bfloat16* __restrict__ fxl) {
    int warp = (blockIdx.x * blockDim.x + threadIdx.x) >> 5;
    int lane = threadIdx.x & 31;
    if (warp >= NN) return;
    int v = warp;
    float a0h = ha[0], a1h = ha[1];
    float mx = fmaxf(a0h, a1h);
    float e0 = __expf(a0h - mx), e1 = __expf(a1h - mx);
    float inv = 1.f / (e0 + e1);
    float w0 = e0 * inv, w1 = e1 * inv;

    float vals[8];
    float sum = 0.f;
#pragma unroll
    for (int k = 0; k < 8; k++) {
        int c = k * 32 + lane;
        float x0 = agg0[(long)v * 256 + c] + b1[c];
        x0 = (x0 > 0.f) ? x0 : (__expf(x0) - 1.f);
        float x1 = agg1[(long)v * 256 + c] + b1[256 + c];
        x1 = (x1 > 0.f) ? x1 : (__expf(x1) - 1.f);
        float val = w0 * x0 + w1 * x1 + skb[(long)v * 256 + c] + skip_b[c];
        vals[k] = val;
        sum += val;
    }
    sum = wredsum(sum);
    float mu = sum * (1.f / 256.f);
    float vs = 0.f;
#pragma unroll
    for (int k = 0; k < 8; k++) {
        float dd = vals[k] - mu;
        vs += dd * dd;
    }
    vs = wredsum(vs);
    float istd = rsqrtf(vs * (1.f / 256.f) + 1e-5f);
#pragma unroll
    for (int k = 0; k < 8; k++) {
        int c = k * 32 + lane;
        float y = (vals[k] - mu) * istd * g[c] + bt[c];
        __nv_bfloat16 hi = __float2bfloat16(y);
        fxh[(long)v * 256 + c] = hi;
        fxl[(long)v * 256 + c] = __float2bfloat16(y - __bfloat162float(hi));
    }
}

// ========== conv2 aggregate + residual + LN2 (4-edge groups) ================
__global__ __launch_bounds__(256) void conv2_ln(const __half* __restrict__ h2,
                                                const float* __restrict__ h2fw,
                                                const float* __restrict__ as2,
                                                const float* __restrict__ ad2,
                                                const int* __restrict__ off,
                                                const int* __restrict__ csr,
                                                const float* __restrict__ b2,
                                                const float* __restrict__ finalb,
                                                const float* __restrict__ g2,
                                                const float* __restrict__ bt2,
                                                float* __restrict__ out) {
    __shared__ float sal[8][CAP];
    int gwarp = (blockIdx.x * blockDim.x + threadIdx.x) >> 5;
    int lane = threadIdx.x & 31;
    if (gwarp >= NN) return;
    int v = gwarp;
    float* sm = sal[threadIdx.x >> 5];
    int s0 = off[v], d = off[v + 1] - s0;
    int grp = lane >> 3, ch8 = lane & 7;
    float adv = ad2[v], asv = as2[v];
    float eself = lrelu(asv + adv);
    float m = eself;
    float inv;
    bool fits = (d <= CAP);

    if (fits) {
        for (int j = lane; j < d; j += 32) {
            int s = csr[s0 + j];
            float e = lrelu(as2[s] + adv);
            sm[j] = e;
            m = fmaxf(m, e);
        }
        m = wredmax(m);
        float den = (lane == 0) ? __expf(eself - m) : 0.f;
        for (int j = lane; j < d; j += 32) {
            float e = __expf(sm[j] - m);
            sm[j] = e;
            den += e;
        }
        den = wredsum(den);
        inv = 1.f / (den + 1e-16f);
        __syncwarp();
    } else {
        for (int j = lane; j < d; j += 32) {
            int s = csr[s0 + j];
            m = fmaxf(m, lrelu(as2[s] + adv));
        }
        m = wredmax(m);
        float den = (lane == 0) ? __expf(eself - m) : 0.f;
        for (int j = lane; j < d; j += 32) {
            int s = csr[s0 + j];
            den += __expf(lrelu(as2[s] + adv) - m);
        }
        den = wredsum(den);
        inv = 1.f / (den + 1e-16f);
    }

    float2 acc[4];
    acc[0] = acc[1] = acc[2] = acc[3] = make_float2(0.f, 0.f);
    if (grp == 0) {
        uint4 r = ((const uint4*)(h2 + (long)v * 64))[ch8];
        fma8(acc, r, __expf(eself - m) * inv);
    }
    if (fits) {
        for (int j = grp; j < d; j += 4) {
            int s = csr[s0 + j];
            uint4 r = ((const uint4*)(h2 + (long)s * 64))[ch8];
            fma8(acc, r, sm[j] * inv);
        }
    } else {
        for (int j = grp; j < d; j += 4) {
            int s = csr[s0 + j];
            uint4 r = ((const uint4*)(h2 + (long)s * 64))[ch8];
            float a = __expf(lrelu(as2[s] + adv) - m) * inv;
            fma8(acc, r, a);
        }
    }
#pragma unroll
    for (int i = 0; i < 4; i++) {
        acc[i].x += __shfl_xor_sync(0xffffffffu, acc[i].x, 8);
        acc[i].x += __shfl_xor_sync(0xffffffffu, acc[i].x, 16);
        acc[i].y += __shfl_xor_sync(0xffffffffu, acc[i].y, 8);
        acc[i].y += __shfl_xor_sync(0xffffffffu, acc[i].y, 16);
    }
    float vals[8];
    float lsum = 0.f;
#pragma unroll
    for (int i = 0; i < 4; i++) {
        int c = ch8 * 8 + 2 * i;
        float r0 = acc[i].x + b2[c] + h2fw[(long)v * 128 + 64 + c] + finalb[c];
        float r1 = acc[i].y + b2[c + 1] + h2fw[(long)v * 128 + 64 + c + 1] + finalb[c + 1];
        vals[2 * i] = r0;
        vals[2 * i + 1] = r1;
        lsum += r0 + r1;
    }
    float sum = wredsum(lsum) * 0.25f;
    float mu = sum * (1.f / 64.f);
    float lvs = 0.f;
#pragma unroll
    for (int i = 0; i < 8; i++) {
        float dd = vals[i] - mu;
        lvs += dd * dd;
    }
    float vs = wredsum(lvs) * 0.25f;
    float istd = rsqrtf(vs * (1.f / 64.f) + 1e-5f);
    if (grp == 0) {
        float o[8];
#pragma unroll
        for (int i = 0; i < 8; i++) {
            int c = ch8 * 8 + i;
            o[i] = (vals[i] - mu) * istd * g2[c] + bt2[c];
        }
        float4* op = (float4*)(out + (long)v * 64 + ch8 * 8);
        op[0] = make_float4(o[0], o[1], o[2], o[3]);
        op[1] = make_float4(o[4], o[5], o[6], o[7]);
    }
}

__global__ void write_w(const float* __restrict__ ha, float* __restrict__ out) {
    if (threadIdx.x == 0) {
        float a0 = ha[0], a1 = ha[1];
        float mx = fmaxf(a0, a1);
        float e0 = __expf(a0 - mx), e1 = __expf(a1 - mx);
        float inv = 1.f / (e0 + e1);
        out[NN * 64 + 0] = e0 * inv;
        out[NN * 64 + 1] = e1 * inv;
    }
}

// ================= launch ===================================================
extern "C" void kernel_launch(void* const* d_in, const int* in_sizes, int n_in,
                              void* d_out, int out_size) {
    const float* x = (const float*)d_in[0];
    const int* ei = (const int*)d_in[1];
    const int* ei2 = (const int*)d_in[2];
    const float* W1 = (const float*)d_in[3];
    const float* att_src1 = (const float*)d_in[4];
    const float* att_dst1 = (const float*)d_in[5];
    const float* b1 = (const float*)d_in[6];
    const float* W2 = (const float*)d_in[7];
    const float* att_src2 = (const float*)d_in[8];
    const float* att_dst2 = (const float*)d_in[9];
    const float* b2 = (const float*)d_in[10];
    const float* ha = (const float*)d_in[11];
    const float* skipW = (const float*)d_in[12];
    const float* skipb = (const float*)d_in[13];
    const float* finalW = (const float*)d_in[14];
    const float* finalb = (const float*)d_in[15];
    const float* ln1g = (const float*)d_in[16];
    const float* ln1b = (const float*)d_in[17];
    const float* ln2g = (const float*)d_in[18];
    const float* ln2b = (const float*)d_in[19];
    float* out = (float*)d_out;

    GS* g = nullptr;
    cudaGetSymbolAddress((void**)&g, gs);

    static cudaStream_t sB = nullptr;
    static cudaEvent_t evFork = nullptr, evJoin = nullptr;
    if (!sB) {
        cudaStreamCreateWithFlags(&sB, cudaStreamNonBlocking);
        cudaEventCreateWithFlags(&evFork, cudaEventDisableTiming);
        cudaEventCreateWithFlags(&evJoin, cudaEventDisableTiming);
    }

    const int GSMEM = 2 * 40960;
    const int GSMEMF = 3 * 20480;
    cudaFuncSetAttribute(hmma_gemm, cudaFuncAttributeMaxDynamicSharedMemorySize, GSMEM);
    cudaFuncSetAttribute(hmma_gemm_f16, cudaFuncAttributeMaxDynamicSharedMemorySize, GSMEMF);

    const int TB = 256;
    int nb = (NN + TB - 1) / TB;
    int wb = (NN + 7) / 8;
    int eb2 = (2 * EE + TB - 1) / TB;

    // ---- fork: CSR build on stream B, concurrent with GEMM chain ----
    cudaEventRecord(evFork, 0);
    cudaStreamWaitEvent(sB, evFork, 0);
    zero_int<<<(2 * NN + TB - 1) / TB, TB, 0, sB>>>(g->deg0, 2 * NN);
    hist2<<<eb2, TB, 0, sB>>>(ei + EE, ei2 + EE, g->deg0, g->deg1);
    scan2<<<2, 1024, 0, sB>>>(g->deg0, g->off0, g->cur0, g->deg1, g->off1, g->cur1);
    scatter2<<<eb2, TB, 0, sB>>>(ei, ei2, g->cur0, g->cur1, g->csr0, g->csr1);
    cudaEventRecord(evJoin, sB);

    // ---- main stream: operand prep + GEMM1 + logits ----
    split_x<<<(NN * 256 + TB - 1) / TB, TB>>>(x, g->xf, NN * 256);
    pack_B1f<<<(768 * 256 + TB - 1) / TB, TB>>>(W1, skipW, g->B1f);
    pack_B2<<<(128 * 256 + TB - 1) / TB, TB>>>(W2, finalW, g->B2h, g->B2l);
    {
        dim3 grid(6, (NN + 127) / 128);
        hmma_gemm_f16<<<grid, 256, GSMEMF>>>(g->xf, g->B1f, g->h0f, g->h1f, g->skb, NN);
    }
    {
        dim3 grid((NN * 8 + TB - 1) / TB, 2);
        logits8_2<<<grid, TB>>>((const __half2*)g->h0f, (const __half2*)g->h1f,
                                att_src1, att_dst1, g->as0, g->ad0, g->as1, g->ad1);
    }

    // ---- join: aggregation needs CSR ----
    cudaStreamWaitEvent(0, evJoin, 0);
    {
        dim3 grid(wb, 2);
        gat_agg8_2<<<grid, TB>>>(g->h0f, g->h1f, g->as0, g->ad0, g->as1, g->ad1,
                                 g->off0, g->csr0, g->off1, g->csr1, g->agg0, g->agg1);
    }

    combine_ln<<<wb, TB>>>(g->agg0, g->agg1, g->skb, b1, skipb, ha, ln1g, ln1b, g->fxh, g->fxl);

    // GEMM2 (bf16 split): first @ [W2 | final_W] -> h2fw (fp32) + h2f (fp16 mirror)
    {
        dim3 grid(1, (NN + 127) / 128);
        hmma_gemm<<<grid, 256, GSMEM>>>(g->fxh, g->fxl, g->B2h, g->B2l, g->h2fw, g->h2f,
                                        NN, 128);
    }

    logits1<<<nb, TB>>>((const __half2*)g->h2f, att_src2, att_dst2, g->as2, g->ad2);
    conv2_ln<<<wb, TB>>>(g->h2f, g->h2fw, g->as2, g->ad2, g->off0, g->csr0,
                         b2, finalb, ln2g, ln2b, out);
    write_w<<<1, 32>>>(ha, out);
}

// round 10
// speedup vs baseline: 2.9515x; 1.0190x over previous
#include <cuda_runtime.h>
#include <cuda_bf16.h>
#include <cuda_fp16.h>
#include <math.h>
#include <stdint.h>

#define NN 50000
#define EE 800000
#define CAP 64

// ================= scratch ==================================================
struct GS {
    float skb[(size_t)NN * 256];
    float agg0[(size_t)NN * 256];
    float agg1[(size_t)NN * 256];
    float h2fw[(size_t)NN * 128];
    __half h0f[(size_t)NN * 256];
    __half h1f[(size_t)NN * 256];
    __half h2f[(size_t)NN * 64];
    float as0[NN * 8], ad0[NN * 8], as1[NN * 8], ad1[NN * 8];
    float as2[NN], ad2[NN];
    __half xf[(size_t)NN * 256];
    __nv_bfloat16 fxh[(size_t)NN * 256], fxl[(size_t)NN * 256];
    __half B1f[768 * 256];
    __nv_bfloat16 B2h[128 * 256], B2l[128 * 256];
    int deg0[NN], deg1[NN];
    int off0[NN + 1], off1[NN + 1];
    int cur0[NN], cur1[NN];
    int csr0[EE], csr1[EE];
};
__device__ GS gs;

// ================= helpers ==================================================
__device__ __forceinline__ float wredsum(float v) {
#pragma unroll
    for (int o = 16; o; o >>= 1) v += __shfl_xor_sync(0xffffffffu, v, o);
    return v;
}
__device__ __forceinline__ float wredmax(float v) {
#pragma unroll
    for (int o = 16; o; o >>= 1) v = fmaxf(v, __shfl_xor_sync(0xffffffffu, v, o));
    return v;
}
__device__ __forceinline__ float lrelu(float x) { return fmaxf(x, 0.2f * x); }
__device__ __forceinline__ uint32_t smem_u32(const void* p) {
    uint32_t a;
    asm("{ .reg .u64 t; cvta.to.shared.u64 t, %1; cvt.u32.u64 %0, t; }" : "=r"(a) : "l"(p));
    return a;
}
__device__ __forceinline__ void cp16(uint32_t dst, const void* src, bool v) {
    int bytes = v ? 16 : 0;
    asm volatile("cp.async.cg.shared.global [%0], [%1], 16, %2;\n"
                 :: "r"(dst), "l"(src), "r"(bytes));
}
__device__ __forceinline__ void ldsm4(uint32_t* r, uint32_t addr) {
    asm volatile("ldmatrix.sync.aligned.m8n8.x4.shared.b16 {%0,%1,%2,%3}, [%4];\n"
                 : "=r"(r[0]), "=r"(r[1]), "=r"(r[2]), "=r"(r[3]) : "r"(addr));
}
__device__ __forceinline__ void mma_bf16(float* d, const uint32_t* a, uint32_t b0, uint32_t b1) {
    asm volatile(
        "mma.sync.aligned.m16n8k16.row.col.f32.bf16.bf16.f32 "
        "{%0,%1,%2,%3}, {%4,%5,%6,%7}, {%8,%9}, {%0,%1,%2,%3};\n"
        : "+f"(d[0]), "+f"(d[1]), "+f"(d[2]), "+f"(d[3])
        : "r"(a[0]), "r"(a[1]), "r"(a[2]), "r"(a[3]), "r"(b0), "r"(b1));
}
__device__ __forceinline__ void mma_f16(float* d, const uint32_t* a, uint32_t b0, uint32_t b1) {
    asm volatile(
        "mma.sync.aligned.m16n8k16.row.col.f32.f16.f16.f32 "
        "{%0,%1,%2,%3}, {%4,%5,%6,%7}, {%8,%9}, {%0,%1,%2,%3};\n"
        : "+f"(d[0]), "+f"(d[1]), "+f"(d[2]), "+f"(d[3])
        : "r"(a[0]), "r"(a[1]), "r"(a[2]), "r"(a[3]), "r"(b0), "r"(b1));
}
__device__ __forceinline__ void fma8(float2* acc, uint4 r, float a) {
    float2 x0 = __half22float2(*(__half2*)&r.x);
    float2 x1 = __half22float2(*(__half2*)&r.y);
    float2 x2 = __half22float2(*(__half2*)&r.z);
    float2 x3 = __half22float2(*(__half2*)&r.w);
    acc[0].x += a * x0.x; acc[0].y += a * x0.y;
    acc[1].x += a * x1.x; acc[1].y += a * x1.y;
    acc[2].x += a * x2.x; acc[2].y += a * x2.y;
    acc[3].x += a * x3.x; acc[3].y += a * x3.y;
}

// ================= CSR build (merged launches) ==============================
__global__ void zero_int(int* p, int n) {
    int i = blockIdx.x * blockDim.x + threadIdx.x;
    if (i < n) p[i] = 0;
}
__global__ void hist2(const int* __restrict__ d0, const int* __restrict__ d1,
                      int* __restrict__ deg0, int* __restrict__ deg1) {
    int i = blockIdx.x * blockDim.x + threadIdx.x;
    if (i < EE) atomicAdd(&deg0[d0[i]], 1);
    else if (i < 2 * EE) atomicAdd(&deg1[d1[i - EE]], 1);
}
__global__ void scan2(const int* __restrict__ deg0, int* __restrict__ off0, int* __restrict__ cur0,
                      const int* __restrict__ deg1, int* __restrict__ off1, int* __restrict__ cur1) {
    __shared__ int sh[1024];
    const int* deg = blockIdx.x ? deg1 : deg0;
    int* off = blockIdx.x ? off1 : off0;
    int* cur = blockIdx.x ? cur1 : cur0;
    const int n = NN;
    int t = threadIdx.x;
    int chunk = (n + 1023) >> 10;
    int s = t * chunk;
    int e = min(s + chunk, n);
    int sum = 0;
    for (int i = s; i < e; i++) sum += deg[i];
    sh[t] = sum;
    __syncthreads();
#pragma unroll
    for (int o = 1; o < 1024; o <<= 1) {
        int val = (t >= o) ? sh[t - o] : 0;
        __syncthreads();
        sh[t] += val;
        __syncthreads();
    }
    int run = sh[t] - sum;
    for (int i = s; i < e; i++) {
        off[i] = run;
        cur[i] = run;
        run += deg[i];
    }
    if (t == 1023) off[n] = sh[1023];
}
__global__ void scatter2(const int* __restrict__ e0, const int* __restrict__ e1,
                         int* __restrict__ cur0, int* __restrict__ cur1,
                         int* __restrict__ csr0, int* __restrict__ csr1) {
    int i = blockIdx.x * blockDim.x + threadIdx.x;
    if (i < EE) {
        int d = e0[EE + i];
        int p = atomicAdd(&cur0[d], 1);
        csr0[p] = e0[i];
    } else if (i < 2 * EE) {
        int j = i - EE;
        int d = e1[EE + j];
        int p = atomicAdd(&cur1[d], 1);
        csr1[p] = e1[j];
    }
}

// ================= operand packing ==========================================
__global__ void split_x(const float* __restrict__ x, __half* __restrict__ xf, int n) {
    int i = blockIdx.x * blockDim.x + threadIdx.x;
    if (i < n) xf[i] = __float2half_rn(x[i]);
}
__global__ void pack_B1f(const float* __restrict__ W1, const float* __restrict__ skipW,
                         __half* __restrict__ Bf) {
    int i = blockIdx.x * blockDim.x + threadIdx.x;
    if (i >= 768 * 256) return;
    int n = i / 256, k = i % 256;
    float v;
    if (n < 256) v = W1[k * 256 + n];
    else if (n < 512) v = W1[65536 + k * 256 + (n - 256)];
    else v = skipW[k * 256 + (n - 512)];
    Bf[i] = __float2half_rn(v);
}
__global__ void pack_B2(const float* __restrict__ W2, const float* __restrict__ finalW,
                        __nv_bfloat16* __restrict__ Bh, __nv_bfloat16* __restrict__ Bl) {
    int i = blockIdx.x * blockDim.x + threadIdx.x;
    if (i >= 128 * 256) return;
    int n = i / 256, k = i % 256;
    float v = (n < 64) ? W2[k * 64 + n] : finalW[k * 64 + (n - 64)];
    __nv_bfloat16 h = __float2bfloat16(v);
    Bh[i] = h;
    Bl[i] = __float2bfloat16(v - __bfloat162float(h));
}

// ====== fp16 single-pass HMMA GEMM: A[M,256] @ B[768,256]^T =================
__global__ __launch_bounds__(256, 2) void hmma_gemm_f16(
    const __half* __restrict__ A, const __half* __restrict__ B,
    __half* __restrict__ H0, __half* __restrict__ H1, float* __restrict__ C2, int M) {
    extern __shared__ char sm[];
    const int tid = threadIdx.x, lane = tid & 31, warp = tid >> 5;
    const int wm = warp & 1, wn = warp >> 1;
    const int m0 = blockIdx.y * 128, n0 = blockIdx.x * 128;
    uint32_t sbase = smem_u32(sm);

    float acc[4][4][4];
#pragma unroll
    for (int a = 0; a < 4; a++)
#pragma unroll
        for (int b = 0; b < 4; b++)
#pragma unroll
            for (int q = 0; q < 4; q++) acc[a][b][q] = 0.f;

#define LOADF(c, s)                                                               \
    do {                                                                          \
        uint32_t sb_ = sbase + (s) * 20480;                                       \
        _Pragma("unroll") for (int it = 0; it < 2; it++) {                        \
            int idx = tid + it * 256;                                             \
            int row = idx >> 2, kc = idx & 3;                                     \
            uint32_t so = row * 80 + kc * 16;                                     \
            bool va = (m0 + row) < M;                                             \
            long ga = (long)(m0 + row) * 256 + (c) * 32 + kc * 8;                 \
            if (!va) ga = 0;                                                      \
            cp16(sb_ + so, A + ga, va);                                           \
            long gb = (long)(n0 + row) * 256 + (c) * 32 + kc * 8;                 \
            cp16(sb_ + 10240 + so, B + gb, true);                                 \
        }                                                                         \
        asm volatile("cp.async.commit_group;\n" ::: "memory");                    \
    } while (0)

    LOADF(0, 0);
    LOADF(1, 1);
    for (int c = 0; c < 8; c++) {
        if (c + 2 < 8) LOADF(c + 2, (c + 2) % 3);
        if (c < 6) asm volatile("cp.async.wait_group 2;\n" ::: "memory");
        else if (c == 6) asm volatile("cp.async.wait_group 1;\n" ::: "memory");
        else asm volatile("cp.async.wait_group 0;\n" ::: "memory");
        __syncthreads();
        uint32_t sb = sbase + (c % 3) * 20480;
#pragma unroll
        for (int ks = 0; ks < 2; ks++) {
            uint32_t ah[4][4], bh[2][4];
            int acol = ks * 16 + 8 * (lane >> 4);
            int arowl = (lane & 15);
#pragma unroll
            for (int mf = 0; mf < 4; mf++) {
                int arow = wm * 64 + mf * 16 + arowl;
                ldsm4(ah[mf], sb + arow * 80 + acol * 2);
            }
            int bcol = ks * 16 + 8 * ((lane >> 3) & 1);
            int browl = (lane & 7) + 8 * (lane >> 4);
#pragma unroll
            for (int p = 0; p < 2; p++) {
                int brow = wn * 32 + p * 16 + browl;
                ldsm4(bh[p], sb + 10240 + brow * 80 + bcol * 2);
            }
#pragma unroll
            for (int mf = 0; mf < 4; mf++)
#pragma unroll
                for (int p = 0; p < 2; p++)
#pragma unroll
                    for (int sub = 0; sub < 2; sub++) {
                        int nf = p * 2 + sub;
                        mma_f16(acc[mf][nf], ah[mf], bh[p][sub * 2], bh[p][sub * 2 + 1]);
                    }
        }
        __syncthreads();
    }
#undef LOADF

    int bucket = n0 >> 8;
    int cb = n0 & 255;
    int group = lane >> 2, q = lane & 3;
    if (bucket < 2) {
        __half2* H = (__half2*)((bucket == 0) ? H0 : H1);
#pragma unroll
        for (int mf = 0; mf < 4; mf++) {
            int r0 = m0 + wm * 64 + mf * 16 + group;
#pragma unroll
            for (int nf = 0; nf < 4; nf++) {
                int col = cb + wn * 32 + nf * 8 + q * 2;
                if (r0 < M)
                    H[(long)r0 * 128 + col / 2] =
                        __floats2half2_rn(acc[mf][nf][0], acc[mf][nf][1]);
                if (r0 + 8 < M)
                    H[(long)(r0 + 8) * 128 + col / 2] =
                        __floats2half2_rn(acc[mf][nf][2], acc[mf][nf][3]);
            }
        }
    } else {
#pragma unroll
        for (int mf = 0; mf < 4; mf++) {
            int r0 = m0 + wm * 64 + mf * 16 + group;
#pragma unroll
            for (int nf = 0; nf < 4; nf++) {
                int col = cb + wn * 32 + nf * 8 + q * 2;
                if (r0 < M)
                    *(float2*)(C2 + (long)r0 * 256 + col) =
                        make_float2(acc[mf][nf][0], acc[mf][nf][1]);
                if (r0 + 8 < M)
                    *(float2*)(C2 + (long)(r0 + 8) * 256 + col) =
                        make_float2(acc[mf][nf][2], acc[mf][nf][3]);
            }
        }
    }
}

// ====== bf16-split HMMA GEMM (3 MMA) + fused fp16 mirror for cols<64 ========
__global__ __launch_bounds__(256, 2) void hmma_gemm(
    const __nv_bfloat16* __restrict__ Ah, const __nv_bfloat16* __restrict__ Al,
    const __nv_bfloat16* __restrict__ Bh, const __nv_bfloat16* __restrict__ Bl,
    float* __restrict__ C, __half* __restrict__ Hf, int M, int split) {
    extern __shared__ char sm[];
    const int tid = threadIdx.x, lane = tid & 31, warp = tid >> 5;
    const int wm = warp & 1, wn = warp >> 1;
    const int m0 = blockIdx.y * 128, n0 = blockIdx.x * 128;
    uint32_t sbase = smem_u32(sm);

    float acc[4][4][4];
#pragma unroll
    for (int a = 0; a < 4; a++)
#pragma unroll
        for (int b = 0; b < 4; b++)
#pragma unroll
            for (int q = 0; q < 4; q++) acc[a][b][q] = 0.f;

#define LOAD_STAGE(c, s)                                                          \
    do {                                                                          \
        uint32_t sb_ = sbase + (s) * 40960;                                       \
        _Pragma("unroll") for (int it = 0; it < 2; it++) {                        \
            int idx = tid + it * 256;                                             \
            int row = idx >> 2, kc = idx & 3;                                     \
            uint32_t so = row * 80 + kc * 16;                                     \
            bool va = (m0 + row) < M;                                             \
            long ga = (long)(m0 + row) * 256 + (c) * 32 + kc * 8;                 \
            if (!va) ga = 0;                                                      \
            cp16(sb_ + so, Ah + ga, va);                                          \
            cp16(sb_ + 10240 + so, Al + ga, va);                                  \
            long gb = (long)(n0 + row) * 256 + (c) * 32 + kc * 8;                 \
            cp16(sb_ + 20480 + so, Bh + gb, true);                                \
            cp16(sb_ + 30720 + so, Bl + gb, true);                                \
        }                                                                         \
        asm volatile("cp.async.commit_group;\n" ::: "memory");                    \
    } while (0)

    LOAD_STAGE(0, 0);
    for (int c = 0; c < 8; c++) {
        if (c < 7) {
            LOAD_STAGE(c + 1, (c + 1) & 1);
            asm volatile("cp.async.wait_group 1;\n" ::: "memory");
        } else {
            asm volatile("cp.async.wait_group 0;\n" ::: "memory");
        }
        __syncthreads();
        uint32_t sb = sbase + (c & 1) * 40960;
#pragma unroll
        for (int ks = 0; ks < 2; ks++) {
            uint32_t ah[4][4], al[4][4], bhf[2][4], blf[2][4];
            int acol = ks * 16 + 8 * (lane >> 4);
            int arowl = (lane & 15);
#pragma unroll
            for (int mf = 0; mf < 4; mf++) {
                int arow = wm * 64 + mf * 16 + arowl;
                uint32_t ad = sb + arow * 80 + acol * 2;
                ldsm4(ah[mf], ad);
                ldsm4(al[mf], ad + 10240);
            }
            int bcol = ks * 16 + 8 * ((lane >> 3) & 1);
            int browl = (lane & 7) + 8 * (lane >> 4);
#pragma unroll
            for (int p = 0; p < 2; p++) {
                int brow = wn * 32 + p * 16 + browl;
                uint32_t bd = sb + 20480 + brow * 80 + bcol * 2;
                ldsm4(bhf[p], bd);
                ldsm4(blf[p], bd + 10240);
            }
#pragma unroll
            for (int mf = 0; mf < 4; mf++)
#pragma unroll
                for (int p = 0; p < 2; p++)
#pragma unroll
                    for (int sub = 0; sub < 2; sub++) {
                        int nf = p * 2 + sub;
                        uint32_t h0 = bhf[p][sub * 2], h1 = bhf[p][sub * 2 + 1];
                        uint32_t l0 = blf[p][sub * 2], l1 = blf[p][sub * 2 + 1];
                        mma_bf16(acc[mf][nf], ah[mf], h0, h1);
                        mma_bf16(acc[mf][nf], ah[mf], l0, l1);
                        mma_bf16(acc[mf][nf], al[mf], h0, h1);
                    }
        }
        __syncthreads();
    }
#undef LOAD_STAGE

    int cb = n0 % split;
    int group = lane >> 2, q = lane & 3;
#pragma unroll
    for (int mf = 0; mf < 4; mf++) {
        int r0 = m0 + wm * 64 + mf * 16 + group;
#pragma unroll
        for (int nf = 0; nf < 4; nf++) {
            int col = cb + wn * 32 + nf * 8 + q * 2;
            if (r0 < M) {
                *(float2*)(C + (long)r0 * split + col) =
                    make_float2(acc[mf][nf][0], acc[mf][nf][1]);
                if (Hf && col < 64)
                    ((__half2*)Hf)[(long)r0 * 32 + col / 2] =
                        __floats2half2_rn(acc[mf][nf][0], acc[mf][nf][1]);
            }
            if (r0 + 8 < M) {
                *(float2*)(C + (long)(r0 + 8) * split + col) =
                    make_float2(acc[mf][nf][2], acc[mf][nf][3]);
                if (Hf && col < 64)
                    ((__half2*)Hf)[(long)(r0 + 8) * 32 + col / 2] =
                        __floats2half2_rn(acc[mf][nf][2], acc[mf][nf][3]);
            }
        }
    }
}

// ================= attention logits (both hops in one launch) ===============
__global__ void logits8_2(const __half2* __restrict__ h0, const __half2* __restrict__ h1,
                          const float* __restrict__ a_src, const float* __restrict__ a_dst,
                          float* __restrict__ as0, float* __restrict__ ad0,
                          float* __restrict__ as1, float* __restrict__ ad1) {
    int t = blockIdx.x * blockDim.x + threadIdx.x;
    if (t >= NN * 8) return;
    int hop = blockIdx.y;
    const __half2* h = hop ? h1 : h0;
    float* as = hop ? as1 : as0;
    float* ad = hop ? ad1 : ad0;
    int v = t >> 3, k = t & 7;
    const __half2* hr = h + (long)v * 128 + k * 16;
    const float* sv = a_src + hop * 256 + k * 32;
    const float* dv = a_dst + hop * 256 + k * 32;
    float s = 0.f, d = 0.f;
#pragma unroll
    for (int c = 0; c < 16; c++) {
        float2 hv = __half22float2(hr[c]);
        s += hv.x * sv[2 * c] + hv.y * sv[2 * c + 1];
        d += hv.x * dv[2 * c] + hv.y * dv[2 * c + 1];
    }
    as[t] = s;
    ad[t] = d;
}
__global__ void logits1(const __half2* __restrict__ h2, const float* __restrict__ a_src,
                        const float* __restrict__ a_dst, float* __restrict__ as,
                        float* __restrict__ ad) {
    int v = blockIdx.x * blockDim.x + threadIdx.x;
    if (v >= NN) return;
    const __half2* hr = h2 + (long)v * 32;
    float s = 0.f, d = 0.f;
#pragma unroll
    for (int c = 0; c < 32; c++) {
        float2 hv = __half22float2(hr[c]);
        s += hv.x * a_src[2 * c] + hv.y * a_src[2 * c + 1];
        d += hv.x * a_dst[2 * c] + hv.y * a_dst[2 * c + 1];
    }
    as[v] = s;
    ad[v] = d;
}

// ====== GAT aggregation: both hops, warp/dst, lane = 8 contiguous channels ==
__global__ __launch_bounds__(256) void gat_agg8_2(
    const __half* __restrict__ h0p, const __half* __restrict__ h1p,
    const float* __restrict__ as0, const float* __restrict__ ad0,
    const float* __restrict__ as1, const float* __restrict__ ad1,
    const int* __restrict__ off0, const int* __restrict__ csr0,
    const int* __restrict__ off1, const int* __restrict__ csr1,
    float* __restrict__ agg0, float* __restrict__ agg1) {
    __shared__ float sal[8][CAP * 9];
    int gwarp = (blockIdx.x * blockDim.x + threadIdx.x) >> 5;
    int lane = threadIdx.x & 31;
    if (gwarp >= NN) return;
    int hop = blockIdx.y;
    const __half* h = hop ? h1p : h0p;
    const float* as = hop ? as1 : as0;
    const float* ad = hop ? ad1 : ad0;
    const int* off = hop ? off1 : off0;
    const int* csr = hop ? csr1 : csr0;
    float* out = hop ? agg1 : agg0;

    int v = gwarp;
    float* sm = sal[threadIdx.x >> 5];
    int s0 = off[v], d = off[v + 1] - s0;
    int head = lane >> 2;

    float adv[8], asv[8];
    {
        float4 a0 = *(const float4*)(ad + v * 8);
        float4 a1 = *(const float4*)(ad + v * 8 + 4);
        adv[0] = a0.x; adv[1] = a0.y; adv[2] = a0.z; adv[3] = a0.w;
        adv[4] = a1.x; adv[5] = a1.y; adv[6] = a1.z; adv[7] = a1.w;
        float4 b0 = *(const float4*)(as + v * 8);
        float4 b1 = *(const float4*)(as + v * 8 + 4);
        asv[0] = b0.x; asv[1] = b0.y; asv[2] = b0.z; asv[3] = b0.w;
        asv[4] = b1.x; asv[5] = b1.y; asv[6] = b1.z; asv[7] = b1.w;
    }
    float m[8], den[8];
#pragma unroll
    for (int k = 0; k < 8; k++) m[k] = lrelu(asv[k] + adv[k]);

    bool fits = (d <= CAP);
    if (fits) {
        for (int j = lane; j < d; j += 32) {
            int s = csr[s0 + j];
            float4 a0 = *(const float4*)(as + s * 8);
            float4 a1 = *(const float4*)(as + s * 8 + 4);
            float ev[8] = {a0.x, a0.y, a0.z, a0.w, a1.x, a1.y, a1.z, a1.w};
#pragma unroll
            for (int k = 0; k < 8; k++) {
                float e = lrelu(ev[k] + adv[k]);
                sm[j * 9 + k] = e;
                m[k] = fmaxf(m[k], e);
            }
        }
#pragma unroll
        for (int k = 0; k < 8; k++) m[k] = wredmax(m[k]);
#pragma unroll
        for (int k = 0; k < 8; k++)
            den[k] = (lane == 0) ? __expf(lrelu(asv[k] + adv[k]) - m[k]) : 0.f;
        for (int j = lane; j < d; j += 32) {
#pragma unroll
            for (int k = 0; k < 8; k++) {
                float e = __expf(sm[j * 9 + k] - m[k]);
                sm[j * 9 + k] = e;
                den[k] += e;
            }
        }
#pragma unroll
        for (int k = 0; k < 8; k++) {
            den[k] = wredsum(den[k]);
            den[k] = 1.f / (den[k] + 1e-16f);
        }
        __syncwarp();
    } else {
        for (int j = lane; j < d; j += 32) {
            int s = csr[s0 + j];
#pragma unroll
            for (int k = 0; k < 8; k++) m[k] = fmaxf(m[k], lrelu(as[s * 8 + k] + adv[k]));
        }
#pragma unroll
        for (int k = 0; k < 8; k++) m[k] = wredmax(m[k]);
#pragma unroll
        for (int k = 0; k < 8; k++)
            den[k] = (lane == 0) ? __expf(lrelu(asv[k] + adv[k]) - m[k]) : 0.f;
        for (int j = lane; j < d; j += 32) {
            int s = csr[s0 + j];
#pragma unroll
            for (int k = 0; k < 8; k++)
                den[k] += __expf(lrelu(as[s * 8 + k] + adv[k]) - m[k]);
        }
#pragma unroll
        for (int k = 0; k < 8; k++) {
            den[k] = wredsum(den[k]);
            den[k] = 1.f / (den[k] + 1e-16f);
        }
    }

    float msel = m[0], dsel = den[0], advsel = adv[0], slsel = asv[0] + adv[0];
#pragma unroll
    for (int k = 1; k < 8; k++)
        if (head == k) { msel = m[k]; dsel = den[k]; advsel = adv[k]; slsel = asv[k] + adv[k]; }
    float esel = __expf(lrelu(slsel) - msel) * dsel;

    float2 acc[4];
    {
        uint4 r = *((const uint4*)(h + (long)v * 256) + lane);
        acc[0] = acc[1] = acc[2] = acc[3] = make_float2(0.f, 0.f);
        fma8(acc, r, esel);
    }
    if (fits) {
        int j = 0;
        for (; j + 8 <= d; j += 8) {
            int sx[8];
#pragma unroll
            for (int u = 0; u < 8; u++) sx[u] = csr[s0 + j + u];
            uint4 r[8];
#pragma unroll
            for (int u = 0; u < 8; u++)
                r[u] = *((const uint4*)(h + (long)sx[u] * 256) + lane);
#pragma unroll
            for (int u = 0; u < 8; u++) fma8(acc, r[u], sm[(j + u) * 9 + head] * dsel);
        }
        for (; j + 4 <= d; j += 4) {
            int sx[4];
#pragma unroll
            for (int u = 0; u < 4; u++) sx[u] = csr[s0 + j + u];
            uint4 r[4];
#pragma unroll
            for (int u = 0; u < 4; u++)
                r[u] = *((const uint4*)(h + (long)sx[u] * 256) + lane);
#pragma unroll
            for (int u = 0; u < 4; u++) fma8(acc, r[u], sm[(j + u) * 9 + head] * dsel);
        }
        for (; j < d; j++) {
            int s = csr[s0 + j];
            uint4 r = *((const uint4*)(h + (long)s * 256) + lane);
            fma8(acc, r, sm[j * 9 + head] * dsel);
        }
    } else {
        for (int j = 0; j < d; j++) {
            int s = csr[s0 + j];
            uint4 r = *((const uint4*)(h + (long)s * 256) + lane);
            float a = __expf(lrelu(as[s * 8 + head] + advsel) - msel) * dsel;
            fma8(acc, r, a);
        }
    }
    float4* op = (float4*)(out + (long)v * 256 + lane * 8);
    op[0] = make_float4(acc[0].x, acc[0].y, acc[1].x, acc[1].y);
    op[1] = make_float4(acc[2].x, acc[2].y, acc[3].x, acc[3].y);
}

// ========== hop combine + skip + LN1 -> bf16 split for GEMM2 ================
__global__ __launch_bounds__(256) void combine_ln(const float* __restrict__ agg0,
                                                  const float* __restrict__ agg1,
                                                  const float* __restrict__ skb,
                                                  const float* __restrict__ b1,
                                                  const float* __restrict__ skip_b,
                                                  const float* __restrict__ ha,
                                                  const float* __restrict__ g,
                                                  const float* __restrict__ bt,
                                                  __nv_bfloat16* __restrict__ fxh,
                                                  __nv_bfloat16* __restrict__ fxl) {
    int warp = (blockIdx.x * blockDim.x + threadIdx.x) >> 5;
    int lane = threadIdx.x & 31;
    if (warp >= NN) return;
    int v = warp;
    float a0h = ha[0], a1h = ha[1];
    float mx = fmaxf(a0h, a1h);
    float e0 = __expf(a0h - mx), e1 = __expf(a1h - mx);
    float inv = 1.f / (e0 + e1);
    float w0 = e0 * inv, w1 = e1 * inv;

    float vals[8];
    float sum = 0.f;
#pragma unroll
    for (int k = 0; k < 8; k++) {
        int c = k * 32 + lane;
        float x0 = agg0[(long)v * 256 + c] + b1[c];
        x0 = (x0 > 0.f) ? x0 : (__expf(x0) - 1.f);
        float x1 = agg1[(long)v * 256 + c] + b1[256 + c];
        x1 = (x1 > 0.f) ? x1 : (__expf(x1) - 1.f);
        float val = w0 * x0 + w1 * x1 + skb[(long)v * 256 + c] + skip_b[c];
        vals[k] = val;
        sum += val;
    }
    sum = wredsum(sum);
    float mu = sum * (1.f / 256.f);
    float vs = 0.f;
#pragma unroll
    for (int k = 0; k < 8; k++) {
        float dd = vals[k] - mu;
        vs += dd * dd;
    }
    vs = wredsum(vs);
    float istd = rsqrtf(vs * (1.f / 256.f) + 1e-5f);
#pragma unroll
    for (int k = 0; k < 8; k++) {
        int c = k * 32 + lane;
        float y = (vals[k] - mu) * istd * g[c] + bt[c];
        __nv_bfloat16 hi = __float2bfloat16(y);
        fxh[(long)v * 256 + c] = hi;
        fxl[(long)v * 256 + c] = __float2bfloat16(y - __bfloat162float(hi));
    }
}

// ========== conv2 aggregate + residual + LN2 (4-edge groups, unroll 2) ======
__global__ __launch_bounds__(256) void conv2_ln(const __half* __restrict__ h2,
                                                const float* __restrict__ h2fw,
                                                const float* __restrict__ as2,
                                                const float* __restrict__ ad2,
                                                const int* __restrict__ off,
                                                const int* __restrict__ csr,
                                                const float* __restrict__ b2,
                                                const float* __restrict__ finalb,
                                                const float* __restrict__ g2,
                                                const float* __restrict__ bt2,
                                                float* __restrict__ out) {
    __shared__ float sal[8][CAP];
    int gwarp = (blockIdx.x * blockDim.x + threadIdx.x) >> 5;
    int lane = threadIdx.x & 31;
    if (gwarp >= NN) return;
    int v = gwarp;
    float* sm = sal[threadIdx.x >> 5];
    int s0 = off[v], d = off[v + 1] - s0;
    int grp = lane >> 3, ch8 = lane & 7;
    float adv = ad2[v], asv = as2[v];
    float eself = lrelu(asv + adv);
    float m = eself;
    float inv;
    bool fits = (d <= CAP);

    if (fits) {
        for (int j = lane; j < d; j += 32) {
            int s = csr[s0 + j];
            float e = lrelu(as2[s] + adv);
            sm[j] = e;
            m = fmaxf(m, e);
        }
        m = wredmax(m);
        float den = (lane == 0) ? __expf(eself - m) : 0.f;
        for (int j = lane; j < d; j += 32) {
            float e = __expf(sm[j] - m);
            sm[j] = e;
            den += e;
        }
        den = wredsum(den);
        inv = 1.f / (den + 1e-16f);
        __syncwarp();
    } else {
        for (int j = lane; j < d; j += 32) {
            int s = csr[s0 + j];
            m = fmaxf(m, lrelu(as2[s] + adv));
        }
        m = wredmax(m);
        float den = (lane == 0) ? __expf(eself - m) : 0.f;
        for (int j = lane; j < d; j += 32) {
            int s = csr[s0 + j];
            den += __expf(lrelu(as2[s] + adv) - m);
        }
        den = wredsum(den);
        inv = 1.f / (den + 1e-16f);
    }

    float2 acc[4];
    acc[0] = acc[1] = acc[2] = acc[3] = make_float2(0.f, 0.f);
    if (grp == 0) {
        uint4 r = ((const uint4*)(h2 + (long)v * 64))[ch8];
        fma8(acc, r, __expf(eself - m) * inv);
    }
    if (fits) {
        int j = grp;
        for (; j + 4 < d; j += 8) {
            int sA = csr[s0 + j], sB = csr[s0 + j + 4];
            uint4 rA = ((const uint4*)(h2 + (long)sA * 64))[ch8];
            uint4 rB = ((const uint4*)(h2 + (long)sB * 64))[ch8];
            fma8(acc, rA, sm[j] * inv);
            fma8(acc, rB, sm[j + 4] * inv);
        }
        for (; j < d; j += 4) {
            int s = csr[s0 + j];
            uint4 r = ((const uint4*)(h2 + (long)s * 64))[ch8];
            fma8(acc, r, sm[j] * inv);
        }
    } else {
        for (int j = grp; j < d; j += 4) {
            int s = csr[s0 + j];
            uint4 r = ((const uint4*)(h2 + (long)s * 64))[ch8];
            float a = __expf(lrelu(as2[s] + adv) - m) * inv;
            fma8(acc, r, a);
        }
    }
#pragma unroll
    for (int i = 0; i < 4; i++) {
        acc[i].x += __shfl_xor_sync(0xffffffffu, acc[i].x, 8);
        acc[i].x += __shfl_xor_sync(0xffffffffu, acc[i].x, 16);
        acc[i].y += __shfl_xor_sync(0xffffffffu, acc[i].y, 8);
        acc[i].y += __shfl_xor_sync(0xffffffffu, acc[i].y, 16);
    }
    float vals[8];
    float lsum = 0.f;
#pragma unroll
    for (int i = 0; i < 4; i++) {
        int c = ch8 * 8 + 2 * i;
        float r0 = acc[i].x + b2[c] + h2fw[(long)v * 128 + 64 + c] + finalb[c];
        float r1 = acc[i].y + b2[c + 1] + h2fw[(long)v * 128 + 64 + c + 1] + finalb[c + 1];
        vals[2 * i] = r0;
        vals[2 * i + 1] = r1;
        lsum += r0 + r1;
    }
    float sum = wredsum(lsum) * 0.25f;
    float mu = sum * (1.f / 64.f);
    float lvs = 0.f;
#pragma unroll
    for (int i = 0; i < 8; i++) {
        float dd = vals[i] - mu;
        lvs += dd * dd;
    }
    float vs = wredsum(lvs) * 0.25f;
    float istd = rsqrtf(vs * (1.f / 64.f) + 1e-5f);
    if (grp == 0) {
        float o[8];
#pragma unroll
        for (int i = 0; i < 8; i++) {
            int c = ch8 * 8 + i;
            o[i] = (vals[i] - mu) * istd * g2[c] + bt2[c];
        }
        float4* op = (float4*)(out + (long)v * 64 + ch8 * 8);
        op[0] = make_float4(o[0], o[1], o[2], o[3]);
        op[1] = make_float4(o[4], o[5], o[6], o[7]);
    }
}

__global__ void write_w(const float* __restrict__ ha, float* __restrict__ out) {
    if (threadIdx.x == 0) {
        float a0 = ha[0], a1 = ha[1];
        float mx = fmaxf(a0, a1);
        float e0 = __expf(a0 - mx), e1 = __expf(a1 - mx);
        float inv = 1.f / (e0 + e1);
        out[NN * 64 + 0] = e0 * inv;
        out[NN * 64 + 1] = e1 * inv;
    }
}

// ================= launch ===================================================
extern "C" void kernel_launch(void* const* d_in, const int* in_sizes, int n_in,
                              void* d_out, int out_size) {
    const float* x = (const float*)d_in[0];
    const int* ei = (const int*)d_in[1];
    const int* ei2 = (const int*)d_in[2];
    const float* W1 = (const float*)d_in[3];
    const float* att_src1 = (const float*)d_in[4];
    const float* att_dst1 = (const float*)d_in[5];
    const float* b1 = (const float*)d_in[6];
    const float* W2 = (const float*)d_in[7];
    const float* att_src2 = (const float*)d_in[8];
    const float* att_dst2 = (const float*)d_in[9];
    const float* b2 = (const float*)d_in[10];
    const float* ha = (const float*)d_in[11];
    const float* skipW = (const float*)d_in[12];
    const float* skipb = (const float*)d_in[13];
    const float* finalW = (const float*)d_in[14];
    const float* finalb = (const float*)d_in[15];
    const float* ln1g = (const float*)d_in[16];
    const float* ln1b = (const float*)d_in[17];
    const float* ln2g = (const float*)d_in[18];
    const float* ln2b = (const float*)d_in[19];
    float* out = (float*)d_out;

    GS* g = nullptr;
    cudaGetSymbolAddress((void**)&g, gs);

    static cudaStream_t sB = nullptr;
    static cudaEvent_t evFork = nullptr, evJoin = nullptr;
    if (!sB) {
        cudaStreamCreateWithFlags(&sB, cudaStreamNonBlocking);
        cudaEventCreateWithFlags(&evFork, cudaEventDisableTiming);
        cudaEventCreateWithFlags(&evJoin, cudaEventDisableTiming);
    }

    const int GSMEM = 2 * 40960;
    const int GSMEMF = 3 * 20480;
    cudaFuncSetAttribute(hmma_gemm, cudaFuncAttributeMaxDynamicSharedMemorySize, GSMEM);
    cudaFuncSetAttribute(hmma_gemm_f16, cudaFuncAttributeMaxDynamicSharedMemorySize, GSMEMF);

    const int TB = 256;
    int nb = (NN + TB - 1) / TB;
    int wb = (NN + 7) / 8;
    int eb2 = (2 * EE + TB - 1) / TB;

    // ---- fork: CSR build on stream B, concurrent with GEMM chain ----
    cudaEventRecord(evFork, 0);
    cudaStreamWaitEvent(sB, evFork, 0);
    zero_int<<<(2 * NN + TB - 1) / TB, TB, 0, sB>>>(g->deg0, 2 * NN);
    hist2<<<eb2, TB, 0, sB>>>(ei + EE, ei2 + EE, g->deg0, g->deg1);
    scan2<<<2, 1024, 0, sB>>>(g->deg0, g->off0, g->cur0, g->deg1, g->off1, g->cur1);
    scatter2<<<eb2, TB, 0, sB>>>(ei, ei2, g->cur0, g->cur1, g->csr0, g->csr1);
    cudaEventRecord(evJoin, sB);

    // ---- main stream: operand prep + GEMM1 + logits ----
    split_x<<<(NN * 256 + TB - 1) / TB, TB>>>(x, g->xf, NN * 256);
    pack_B1f<<<(768 * 256 + TB - 1) / TB, TB>>>(W1, skipW, g->B1f);
    pack_B2<<<(128 * 256 + TB - 1) / TB, TB>>>(W2, finalW, g->B2h, g->B2l);
    {
        dim3 grid(6, (NN + 127) / 128);
        hmma_gemm_f16<<<grid, 256, GSMEMF>>>(g->xf, g->B1f, g->h0f, g->h1f, g->skb, NN);
    }
    {
        dim3 grid((NN * 8 + TB - 1) / TB, 2);
        logits8_2<<<grid, TB>>>((const __half2*)g->h0f, (const __half2*)g->h1f,
                                att_src1, att_dst1, g->as0, g->ad0, g->as1, g->ad1);
    }

    // ---- join: aggregation needs CSR ----
    cudaStreamWaitEvent(0, evJoin, 0);
    {
        dim3 grid(wb, 2);
        gat_agg8_2<<<grid, TB>>>(g->h0f, g->h1f, g->as0, g->ad0, g->as1, g->ad1,
                                 g->off0, g->csr0, g->off1, g->csr1, g->agg0, g->agg1);
    }

    combine_ln<<<wb, TB>>>(g->agg0, g->agg1, g->skb, b1, skipb, ha, ln1g, ln1b, g->fxh, g->fxl);

    // GEMM2 (bf16 split): first @ [W2 | final_W] -> h2fw (fp32) + h2f (fp16 mirror)
    {
        dim3 grid(1, (NN + 127) / 128);
        hmma_gemm<<<grid, 256, GSMEM>>>(g->fxh, g->fxl, g->B2h, g->B2l, g->h2fw, g->h2f,
                                        NN, 128);
    }

    logits1<<<nb, TB>>>((const __half2*)g->h2f, att_src2, att_dst2, g->as2, g->ad2);
    conv2_ln<<<wb, TB>>>(g->h2f, g->h2fw, g->as2, g->ad2, g->off0, g->csr0,
                         b2, finalb, ln2g, ln2b, out);
    write_w<<<1, 32>>>(ha, out);
}